// round 3
// baseline (speedup 1.0000x reference)
#include <cuda_runtime.h>
#include <cstdint>

// ---------------- problem constants ----------------
namespace {
constexpr int B   = 2048;
constexpr int NN  = 24;
constexpr int NC  = 8;
constexpr int D   = 512;
constexpr int NH  = 8;     // heads
constexpr int L   = 3;
constexpr int FH  = 1024;
constexpr int S   = 33;    // NN + NC + 1
constexpr int DH  = 64;    // D / NH
constexpr int M   = B * S; // 67584 rows; divisible by 128

constexpr int AS_STRIDE = 36;
constexpr int BS_STRIDE = 136;
constexpr int AS_ELEMS  = 128 * AS_STRIDE;
constexpr int BS_ELEMS  = 32 * BS_STRIDE;
constexpr size_t GEMM_SMEM = (size_t)(2 * AS_ELEMS + 2 * BS_ELEMS) * sizeof(float);
}

// ---------------- scratch (device globals; allocation-free) ----------------
__device__ float g_X[(size_t)M * D];        // residual stream
__device__ float g_Hn[(size_t)M * D];       // LN output
__device__ float g_Q[(size_t)M * D];
__device__ float g_K[(size_t)M * D];
__device__ float g_V[(size_t)M * D];
__device__ float g_O[(size_t)M * D];
__device__ float g_F[(size_t)M * 2 * FH];   // FFN pre-activation
__device__ float g_U[(size_t)M * FH];       // ReGLU output
__device__ unsigned char g_mask[L * S * S]; // canonical uint8 mask

// ---------------- mask canonicalization ----------------
// The reference mask is boolean; the harness may serialize it as uint8,
// int32, or float32. Detect layout from invariants (m[l=0][1][1] is True:
// as uint8 byte 34 == 1; as int32/float32 byte 34 is byte-2 of element 8,
// which is 0 or 0x80, never 1. float32 detected by exponent byte of
// element 0 == 0x3f).
__global__ void mask_convert_kernel(const unsigned char* __restrict__ raw)
{
    int i = blockIdx.x * blockDim.x + threadIdx.x;
    if (i >= L * S * S) return;
    bool v;
    if (raw[34] == 1) {
        v = raw[i] != 0;                                // uint8 / bool
    } else if (raw[3] == 0x3f) {
        v = ((const float*)raw)[i] != 0.0f;             // float32
    } else {
        v = ((const int*)raw)[i] != 0;                  // int32
    }
    g_mask[i] = v ? 1 : 0;
}

// ---------------- helpers ----------------
__device__ __forceinline__ float tf32rn(float x) {
    // round-to-nearest into tf32's 10-bit mantissa
    unsigned u = __float_as_uint(x);
    u = (u + 0x1000u) & 0xffffe000u;
    return __uint_as_float(u);
}

__device__ __forceinline__ void mma8(float* c, const unsigned* a, const unsigned* b) {
    asm volatile(
        "mma.sync.aligned.m16n8k8.row.col.f32.tf32.tf32.f32 "
        "{%0,%1,%2,%3}, {%4,%5,%6,%7}, {%8,%9}, {%0,%1,%2,%3};\n"
        : "+f"(c[0]), "+f"(c[1]), "+f"(c[2]), "+f"(c[3])
        : "r"(a[0]), "r"(a[1]), "r"(a[2]), "r"(a[3]),
          "r"(b[0]), "r"(b[1]));
}

// ---------------- tokenizer ----------------
__global__ void tokenize_kernel(const float* __restrict__ x_num,
                                const int* __restrict__ x_cat,
                                const float* __restrict__ w_num,
                                const float* __restrict__ b_num,
                                const float* __restrict__ emb_cat,
                                const float* __restrict__ b_cat,
                                const float* __restrict__ cls,
                                const int* __restrict__ cat_offsets)
{
    int idx = blockIdx.x * blockDim.x + threadIdx.x;
    const int total = M * (D / 4);
    if (idx >= total) return;
    int d4 = idx & (D / 4 - 1);   // D/4 = 128
    int ms = idx >> 7;
    int s  = ms % S;
    int b  = ms / S;
    int d  = d4 * 4;
    float4 o;
    if (s < NN) {
        float xv  = x_num[b * NN + s];
        float4 w  = *(const float4*)(w_num + (size_t)s * D + d);
        float4 bb = *(const float4*)(b_num + (size_t)s * D + d);
        o.x = xv * w.x + bb.x;
        o.y = xv * w.y + bb.y;
        o.z = xv * w.z + bb.z;
        o.w = xv * w.w + bb.w;
    } else if (s < NN + NC) {
        int c   = s - NN;
        int row = x_cat[b * NC + c] + cat_offsets[c];
        float4 e  = *(const float4*)(emb_cat + (size_t)row * D + d);
        float4 bb = *(const float4*)(b_cat + (size_t)c * D + d);
        o.x = e.x + bb.x; o.y = e.y + bb.y; o.z = e.z + bb.z; o.w = e.w + bb.w;
    } else {
        o = *(const float4*)(cls + d);
    }
    *(float4*)(g_X + (size_t)ms * D + d) = o;
}

// ---------------- LayerNorm (one block / row) ----------------
__global__ void ln_kernel(const float* __restrict__ X, float* __restrict__ Y,
                          const float* __restrict__ w, const float* __restrict__ bb)
{
    int row = blockIdx.x;
    int t   = threadIdx.x;     // 128 threads; 4 floats each
    const float* xr = X + (size_t)row * D;
    float4 v = *(const float4*)(xr + t * 4);
    float s  = v.x + v.y + v.z + v.w;
    float sq = v.x * v.x + v.y * v.y + v.z * v.z + v.w * v.w;
#pragma unroll
    for (int o = 16; o > 0; o >>= 1) {
        s  += __shfl_xor_sync(0xffffffffu, s, o);
        sq += __shfl_xor_sync(0xffffffffu, sq, o);
    }
    __shared__ float ss[4], sqs[4];
    if ((t & 31) == 0) { ss[t >> 5] = s; sqs[t >> 5] = sq; }
    __syncthreads();
    s  = ss[0] + ss[1] + ss[2] + ss[3];
    sq = sqs[0] + sqs[1] + sqs[2] + sqs[3];
    float mean = s * (1.0f / D);
    float var  = sq * (1.0f / D) - mean * mean;
    float r = rsqrtf(var + 1e-5f);
    float4 wv = *(const float4*)(w + t * 4);
    float4 bv = *(const float4*)(bb + t * 4);
    float4 o;
    o.x = (v.x - mean) * r * wv.x + bv.x;
    o.y = (v.y - mean) * r * wv.y + bv.y;
    o.z = (v.z - mean) * r * wv.z + bv.z;
    o.w = (v.w - mean) * r * wv.w + bv.w;
    *(float4*)(Y + (size_t)row * D + t * 4) = o;
}

// ---------------- 3xTF32 tensor-core GEMM (fp32-accurate) ----------------
// C[M,N] = A[M,K] @ W[K,N] + bias[N] (+ Rsd[M,N] if RES)
// Each input split a = a_hi + a_lo (both tf32); accumulate
// a_hi*b_hi + a_hi*b_lo + a_lo*b_hi -> ~fp32 precision.
// BM=128 BN=128 BK=32, 256 threads, warp tile 64x32.
template <bool RES>
__global__ void __launch_bounds__(256)
gemm_kernel(const float* __restrict__ A, const float* __restrict__ W,
            const float* __restrict__ bias, const float* __restrict__ Rsd,
            float* __restrict__ C, int K, int N)
{
    extern __shared__ float smem[];
    float* As_hi = smem;                    // 128 x 36
    float* As_lo = As_hi + AS_ELEMS;
    float* Bs_hi = As_lo + AS_ELEMS;        // 32 x 136
    float* Bs_lo = Bs_hi + BS_ELEMS;

    const int tid  = threadIdx.x;
    const int lane = tid & 31;
    const int warp = tid >> 5;
    const int wm   = (warp & 1) * 64;
    const int wn   = (warp >> 1) * 32;
    const int grp  = lane >> 2;
    const int t4   = lane & 3;

    const int bm = blockIdx.x;
    const int bn = blockIdx.y;

    float acc[4][4][4];
#pragma unroll
    for (int i = 0; i < 4; ++i)
#pragma unroll
        for (int j = 0; j < 4; ++j)
#pragma unroll
            for (int r = 0; r < 4; ++r) acc[i][j][r] = 0.0f;

    const int ar  = tid >> 3;          // A tile row (0..31), +p*32
    const int ac  = (tid & 7) * 4;     // A tile col
    const int brr = tid >> 5;          // B tile row (0..7), +p*8
    const int bcc = (tid & 31) * 4;    // B tile col

    const float* Ag = A + (size_t)(bm * 128 + ar) * K + ac;
    const float* Wg = W + (size_t)brr * N + (size_t)bn * 128 + bcc;

    float4 ra[4], rb[4];
    const int KT = K >> 5;

#define GLOAD(kt)                                                              \
    do {                                                                       \
        _Pragma("unroll")                                                      \
        for (int p = 0; p < 4; ++p)                                            \
            ra[p] = *(const float4*)(Ag + (size_t)(p * 32) * K + (kt) * 32);   \
        _Pragma("unroll")                                                      \
        for (int p = 0; p < 4; ++p)                                            \
            rb[p] = *(const float4*)(Wg + (size_t)((kt) * 32 + p * 8) * N);    \
    } while (0)

#define SPLIT4(v, hi, lo)                                                      \
    do {                                                                       \
        hi = make_float4(tf32rn(v.x), tf32rn(v.y), tf32rn(v.z), tf32rn(v.w));  \
        lo = make_float4(tf32rn(v.x - hi.x), tf32rn(v.y - hi.y),               \
                         tf32rn(v.z - hi.z), tf32rn(v.w - hi.w));              \
    } while (0)

#define SSTORE()                                                               \
    do {                                                                       \
        _Pragma("unroll")                                                      \
        for (int p = 0; p < 4; ++p) {                                          \
            float4 hi, lo;                                                     \
            SPLIT4(ra[p], hi, lo);                                             \
            *(float4*)(As_hi + (ar + p * 32) * AS_STRIDE + ac) = hi;           \
            *(float4*)(As_lo + (ar + p * 32) * AS_STRIDE + ac) = lo;           \
        }                                                                      \
        _Pragma("unroll")                                                      \
        for (int p = 0; p < 4; ++p) {                                          \
            float4 hi, lo;                                                     \
            SPLIT4(rb[p], hi, lo);                                             \
            *(float4*)(Bs_hi + (brr + p * 8) * BS_STRIDE + bcc) = hi;          \
            *(float4*)(Bs_lo + (brr + p * 8) * BS_STRIDE + bcc) = lo;          \
        }                                                                      \
    } while (0)

    GLOAD(0);
    SSTORE();
    __syncthreads();

    for (int kt = 0; kt < KT; ++kt) {
        if (kt + 1 < KT) GLOAD(kt + 1);
#pragma unroll
        for (int ks = 0; ks < 4; ++ks) {
            unsigned ah[4][4], al[4][4], bh[4][2], bl[4][2];
#pragma unroll
            for (int mi = 0; mi < 4; ++mi) {
                int off = (wm + mi * 16 + grp) * AS_STRIDE + ks * 8 + t4;
                const float* ph = As_hi + off;
                const float* pl = As_lo + off;
                ah[mi][0] = __float_as_uint(ph[0]);
                ah[mi][1] = __float_as_uint(ph[8 * AS_STRIDE]);
                ah[mi][2] = __float_as_uint(ph[4]);
                ah[mi][3] = __float_as_uint(ph[8 * AS_STRIDE + 4]);
                al[mi][0] = __float_as_uint(pl[0]);
                al[mi][1] = __float_as_uint(pl[8 * AS_STRIDE]);
                al[mi][2] = __float_as_uint(pl[4]);
                al[mi][3] = __float_as_uint(pl[8 * AS_STRIDE + 4]);
            }
#pragma unroll
            for (int ni = 0; ni < 4; ++ni) {
                int off = (ks * 8 + t4) * BS_STRIDE + wn + ni * 8 + grp;
                const float* ph = Bs_hi + off;
                const float* pl = Bs_lo + off;
                bh[ni][0] = __float_as_uint(ph[0]);
                bh[ni][1] = __float_as_uint(ph[4 * BS_STRIDE]);
                bl[ni][0] = __float_as_uint(pl[0]);
                bl[ni][1] = __float_as_uint(pl[4 * BS_STRIDE]);
            }
#pragma unroll
            for (int mi = 0; mi < 4; ++mi)
#pragma unroll
                for (int ni = 0; ni < 4; ++ni) {
                    mma8(acc[mi][ni], al[mi], bh[ni]);  // cross terms first
                    mma8(acc[mi][ni], ah[mi], bl[ni]);
                    mma8(acc[mi][ni], ah[mi], bh[ni]);  // main term
                }
        }
        if (kt + 1 < KT) {
            __syncthreads();
            SSTORE();
            __syncthreads();
        }
    }
#undef GLOAD
#undef SPLIT4
#undef SSTORE

    // epilogue
#pragma unroll
    for (int mi = 0; mi < 4; ++mi) {
        int r0 = bm * 128 + wm + mi * 16 + grp;
#pragma unroll
        for (int ni = 0; ni < 4; ++ni) {
            int c0 = bn * 128 + wn + ni * 8 + 2 * t4;
            float b0 = bias[c0], b1 = bias[c0 + 1];
            float2 o0 = make_float2(acc[mi][ni][0] + b0, acc[mi][ni][1] + b1);
            float2 o1 = make_float2(acc[mi][ni][2] + b0, acc[mi][ni][3] + b1);
            if (RES) {
                float2 rv0 = *(const float2*)(Rsd + (size_t)r0 * N + c0);
                float2 rv1 = *(const float2*)(Rsd + (size_t)(r0 + 8) * N + c0);
                o0.x += rv0.x; o0.y += rv0.y;
                o1.x += rv1.x; o1.y += rv1.y;
            }
            *(float2*)(C + (size_t)r0 * N + c0)       = o0;
            *(float2*)(C + (size_t)(r0 + 8) * N + c0) = o1;
        }
    }
}

// ---------------- attention (one block per (batch, head)) ----------------
__global__ void attn_kernel(const float* __restrict__ Q, const float* __restrict__ Kk,
                            const float* __restrict__ V,
                            const unsigned char* __restrict__ mask,
                            float* __restrict__ O)
{
    int bh = blockIdx.x;
    int h  = bh % NH;
    int b  = bh / NH;
    int t  = threadIdx.x;   // 256

    __shared__ float qs[S][DH];
    __shared__ float ks[S][DH];
    __shared__ float vs[S][DH];
    __shared__ float sc[S][S + 3];

    const size_t base = (size_t)(b * S) * D + h * DH;
    for (int i = t; i < S * DH; i += 256) {
        int s = i / DH, d = i % DH;
        qs[s][d] = Q[base + (size_t)s * D + d];
        ks[s][d] = Kk[base + (size_t)s * D + d];
        vs[s][d] = V[base + (size_t)s * D + d];
    }
    __syncthreads();

    const float scale = 0.125f;  // 1/sqrt(64)
    for (int p = t; p < S * S; p += 256) {
        int i = p / S, j = p % S;
        float s = 0.0f;
#pragma unroll 16
        for (int d = 0; d < DH; ++d) s += qs[i][d] * ks[j][d];
        s *= scale;
        if (!mask[i * S + j]) s = -1e9f;
        sc[i][j] = s;
    }
    __syncthreads();

    if (t < S) {
        float mx = -1e30f;
        for (int j = 0; j < S; ++j) mx = fmaxf(mx, sc[t][j]);
        float sum = 0.0f;
        for (int j = 0; j < S; ++j) { float e = __expf(sc[t][j] - mx); sc[t][j] = e; sum += e; }
        float inv = 1.0f / sum;
        for (int j = 0; j < S; ++j) sc[t][j] *= inv;
    }
    __syncthreads();

    for (int p = t; p < S * DH; p += 256) {
        int i = p / DH, d = p % DH;
        float o = 0.0f;
#pragma unroll
        for (int j = 0; j < S; ++j) o += sc[i][j] * vs[j][d];
        O[base + (size_t)i * D + d] = o;
    }
}

// ---------------- ReGLU: u = a * relu(g) ----------------
__global__ void reglu_kernel(const float* __restrict__ F, float* __restrict__ U)
{
    int idx = blockIdx.x * blockDim.x + threadIdx.x;   // over M*FH/4
    const int total = M * (FH / 4);
    if (idx >= total) return;
    int m  = idx / (FH / 4);
    int j4 = (idx % (FH / 4)) * 4;
    float4 a = *(const float4*)(F + (size_t)m * 2 * FH + j4);
    float4 g = *(const float4*)(F + (size_t)m * 2 * FH + FH + j4);
    float4 o;
    o.x = a.x * fmaxf(g.x, 0.0f);
    o.y = a.y * fmaxf(g.y, 0.0f);
    o.z = a.z * fmaxf(g.z, 0.0f);
    o.w = a.w * fmaxf(g.w, 0.0f);
    *(float4*)(U + (size_t)m * FH + j4) = o;
}

// ---------------- head: LN(cls) -> relu -> dot Wh + bh ----------------
__global__ void head_kernel(const float* __restrict__ X,
                            const float* __restrict__ hw, const float* __restrict__ hb,
                            const float* __restrict__ Wh, const float* __restrict__ bh,
                            float* __restrict__ out)
{
    int b = blockIdx.x;
    int t = threadIdx.x;   // 128
    const float* xr = X + ((size_t)b * S + (S - 1)) * D;
    float4 v = *(const float4*)(xr + t * 4);
    float s  = v.x + v.y + v.z + v.w;
    float sq = v.x * v.x + v.y * v.y + v.z * v.z + v.w * v.w;
#pragma unroll
    for (int o = 16; o > 0; o >>= 1) {
        s  += __shfl_xor_sync(0xffffffffu, s, o);
        sq += __shfl_xor_sync(0xffffffffu, sq, o);
    }
    __shared__ float ss[4], sqs[4], ds[4];
    if ((t & 31) == 0) { ss[t >> 5] = s; sqs[t >> 5] = sq; }
    __syncthreads();
    s  = ss[0] + ss[1] + ss[2] + ss[3];
    sq = sqs[0] + sqs[1] + sqs[2] + sqs[3];
    float mean = s * (1.0f / D);
    float var  = sq * (1.0f / D) - mean * mean;
    float r = rsqrtf(var + 1e-5f);
    float4 wv = *(const float4*)(hw + t * 4);
    float4 bv = *(const float4*)(hb + t * 4);
    float4 wh = *(const float4*)(Wh + t * 4);   // DOUT == 1
    float dot = 0.0f;
    dot += fmaxf((v.x - mean) * r * wv.x + bv.x, 0.0f) * wh.x;
    dot += fmaxf((v.y - mean) * r * wv.y + bv.y, 0.0f) * wh.y;
    dot += fmaxf((v.z - mean) * r * wv.z + bv.z, 0.0f) * wh.z;
    dot += fmaxf((v.w - mean) * r * wv.w + bv.w, 0.0f) * wh.w;
#pragma unroll
    for (int o = 16; o > 0; o >>= 1) dot += __shfl_xor_sync(0xffffffffu, dot, o);
    if ((t & 31) == 0) ds[t >> 5] = dot;
    __syncthreads();
    if (t == 0) out[b] = ds[0] + ds[1] + ds[2] + ds[3] + bh[0];
}

// ---------------- launcher ----------------
extern "C" void kernel_launch(void* const* d_in, const int* in_sizes, int n_in,
                              void* d_out, int out_size)
{
    (void)in_sizes; (void)n_in; (void)out_size;
    const float* x_num    = (const float*)d_in[0];
    const int*   x_cat    = (const int*)d_in[1];
    const float* w_num    = (const float*)d_in[2];
    const float* b_num    = (const float*)d_in[3];
    const float* emb_cat  = (const float*)d_in[4];
    const float* b_cat    = (const float*)d_in[5];
    const float* cls      = (const float*)d_in[6];
    const float* ln1_w    = (const float*)d_in[7];
    const float* ln1_b    = (const float*)d_in[8];
    const float* Wq       = (const float*)d_in[9];
    const float* bq       = (const float*)d_in[10];
    const float* Wk       = (const float*)d_in[11];
    const float* bk       = (const float*)d_in[12];
    const float* Wv       = (const float*)d_in[13];
    const float* bv       = (const float*)d_in[14];
    const float* Wo       = (const float*)d_in[15];
    const float* bo       = (const float*)d_in[16];
    const float* ln2_w    = (const float*)d_in[17];
    const float* ln2_b    = (const float*)d_in[18];
    const float* Wf1      = (const float*)d_in[19];
    const float* bf1      = (const float*)d_in[20];
    const float* Wf2      = (const float*)d_in[21];
    const float* bf2      = (const float*)d_in[22];
    const unsigned char* mask_raw = (const unsigned char*)d_in[23];
    const int*   cat_offsets  = (const int*)d_in[24];
    const float* hln_w    = (const float*)d_in[25];
    const float* hln_b    = (const float*)d_in[26];
    const float* Wh       = (const float*)d_in[27];
    const float* bh       = (const float*)d_in[28];
    float* out = (float*)d_out;

    float *X, *Hn, *Q, *Kb, *Vb, *O, *F, *U;
    unsigned char* Mk;
    cudaGetSymbolAddress((void**)&X,  g_X);
    cudaGetSymbolAddress((void**)&Hn, g_Hn);
    cudaGetSymbolAddress((void**)&Q,  g_Q);
    cudaGetSymbolAddress((void**)&Kb, g_K);
    cudaGetSymbolAddress((void**)&Vb, g_V);
    cudaGetSymbolAddress((void**)&O,  g_O);
    cudaGetSymbolAddress((void**)&F,  g_F);
    cudaGetSymbolAddress((void**)&U,  g_U);
    cudaGetSymbolAddress((void**)&Mk, g_mask);

    cudaFuncSetAttribute(gemm_kernel<false>,
                         cudaFuncAttributeMaxDynamicSharedMemorySize, (int)GEMM_SMEM);
    cudaFuncSetAttribute(gemm_kernel<true>,
                         cudaFuncAttributeMaxDynamicSharedMemorySize, (int)GEMM_SMEM);

    mask_convert_kernel<<<(L * S * S + 255) / 256, 256>>>(mask_raw);

    tokenize_kernel<<<(M * (D / 4) + 255) / 256, 256>>>(
        x_num, x_cat, w_num, b_num, emb_cat, b_cat, cls, cat_offsets);

    const dim3 g512(M / 128, D / 128);        // N = 512
    const dim3 g2048(M / 128, (2 * FH) / 128);// N = 2048

    for (int l = 0; l < L; ++l) {
        ln_kernel<<<M, 128>>>(X, Hn, ln1_w + (size_t)l * D, ln1_b + (size_t)l * D);

        gemm_kernel<false><<<g512, 256, GEMM_SMEM>>>(Hn, Wq + (size_t)l * D * D, bq + (size_t)l * D, nullptr, Q,  D, D);
        gemm_kernel<false><<<g512, 256, GEMM_SMEM>>>(Hn, Wk + (size_t)l * D * D, bk + (size_t)l * D, nullptr, Kb, D, D);
        gemm_kernel<false><<<g512, 256, GEMM_SMEM>>>(Hn, Wv + (size_t)l * D * D, bv + (size_t)l * D, nullptr, Vb, D, D);

        attn_kernel<<<B * NH, 256>>>(Q, Kb, Vb, Mk + (size_t)l * S * S, O);

        gemm_kernel<true><<<g512, 256, GEMM_SMEM>>>(O, Wo + (size_t)l * D * D, bo + (size_t)l * D, X, X, D, D);

        ln_kernel<<<M, 128>>>(X, Hn, ln2_w + (size_t)l * D, ln2_b + (size_t)l * D);

        gemm_kernel<false><<<g2048, 256, GEMM_SMEM>>>(Hn, Wf1 + (size_t)l * D * 2 * FH, bf1 + (size_t)l * 2 * FH, nullptr, F, D, 2 * FH);

        reglu_kernel<<<(M * (FH / 4) + 255) / 256, 256>>>(F, U);

        gemm_kernel<true><<<g512, 256, GEMM_SMEM>>>(U, Wf2 + (size_t)l * FH * D, bf2 + (size_t)l * D, X, X, FH, D);
    }

    head_kernel<<<B, 128>>>(X, hln_w, hln_b, Wh, bh, out);
}

// round 4
// speedup vs baseline: 1.4862x; 1.4862x over previous
#include <cuda_runtime.h>
#include <cuda_bf16.h>
#include <cstdint>

// ---------------- problem constants ----------------
namespace {
constexpr int B   = 2048;
constexpr int NN  = 24;
constexpr int NC  = 8;
constexpr int D   = 512;
constexpr int NH  = 8;     // heads
constexpr int L   = 3;
constexpr int FH  = 1024;
constexpr int S   = 33;    // NN + NC + 1
constexpr int DH  = 64;    // D / NH
constexpr int M   = B * S; // 67584 rows; divisible by 128

// GEMM smem geometry (bf16 elements)
constexpr int A_STRIDE = 40;               // 128 rows x 40 (pad: 80B rows, conflict-free ldmatrix)
constexpr int B_STRIDE = 136;              // 32 k-rows... stored [k? no: see kernel] 
constexpr int A_PLANE  = 128 * A_STRIDE;   // 5120 elems per buffer per plane
constexpr int B_PLANE  = 32 * B_STRIDE;    // 4352 elems per buffer per plane (B stored [k][n], n padded 128->136? no: [k rows=32][n=136])
constexpr size_t GEMM_SMEM = (size_t)(2 * 2 * A_PLANE + 2 * 2 * B_PLANE) * 2; // 75776 bytes
}

// ---------------- scratch (device globals; allocation-free) ----------------
__device__ float g_X[(size_t)M * D];        // residual stream
__device__ float g_Hn[(size_t)M * D];       // LN output
__device__ float g_Q[(size_t)M * D];
__device__ float g_K[(size_t)M * D];
__device__ float g_V[(size_t)M * D];
__device__ float g_O[(size_t)M * D];
__device__ float g_F[(size_t)M * 2 * FH];   // FFN pre-activation
__device__ float g_U[(size_t)M * FH];       // ReGLU output
__device__ unsigned char g_mask[L * S * S]; // canonical uint8 mask

// ---------------- mask canonicalization ----------------
__global__ void mask_convert_kernel(const unsigned char* __restrict__ raw)
{
    int i = blockIdx.x * blockDim.x + threadIdx.x;
    if (i >= L * S * S) return;
    bool v;
    if (raw[34] == 1) {
        v = raw[i] != 0;                                // uint8 / bool
    } else if (raw[3] == 0x3f) {
        v = ((const float*)raw)[i] != 0.0f;             // float32
    } else {
        v = ((const int*)raw)[i] != 0;                  // int32
    }
    g_mask[i] = v ? 1 : 0;
}

// ---------------- helpers ----------------
__device__ __forceinline__ void split2(float x, float y, uint32_t& hi, uint32_t& lo)
{
    __nv_bfloat162 h = __floats2bfloat162_rn(x, y);
    float hx = __bfloat162float(h.x), hy = __bfloat162float(h.y);
    __nv_bfloat162 l = __floats2bfloat162_rn(x - hx, y - hy);
    hi = *reinterpret_cast<uint32_t*>(&h);
    lo = *reinterpret_cast<uint32_t*>(&l);
}

__device__ __forceinline__ void ldmx4(uint32_t addr, uint32_t& r0, uint32_t& r1,
                                      uint32_t& r2, uint32_t& r3)
{
    asm volatile("ldmatrix.sync.aligned.m8n8.x4.shared.b16 {%0,%1,%2,%3},[%4];"
                 : "=r"(r0), "=r"(r1), "=r"(r2), "=r"(r3) : "r"(addr));
}

__device__ __forceinline__ void ldmx4t(uint32_t addr, uint32_t& r0, uint32_t& r1,
                                       uint32_t& r2, uint32_t& r3)
{
    asm volatile("ldmatrix.sync.aligned.m8n8.x4.trans.shared.b16 {%0,%1,%2,%3},[%4];"
                 : "=r"(r0), "=r"(r1), "=r"(r2), "=r"(r3) : "r"(addr));
}

__device__ __forceinline__ void mma16(float* c, const uint32_t* a, const uint32_t* b)
{
    asm volatile(
        "mma.sync.aligned.m16n8k16.row.col.f32.bf16.bf16.f32 "
        "{%0,%1,%2,%3},{%4,%5,%6,%7},{%8,%9},{%0,%1,%2,%3};\n"
        : "+f"(c[0]), "+f"(c[1]), "+f"(c[2]), "+f"(c[3])
        : "r"(a[0]), "r"(a[1]), "r"(a[2]), "r"(a[3]),
          "r"(b[0]), "r"(b[1]));
}

// ---------------- tokenizer ----------------
__global__ void tokenize_kernel(const float* __restrict__ x_num,
                                const int* __restrict__ x_cat,
                                const float* __restrict__ w_num,
                                const float* __restrict__ b_num,
                                const float* __restrict__ emb_cat,
                                const float* __restrict__ b_cat,
                                const float* __restrict__ cls,
                                const int* __restrict__ cat_offsets)
{
    int idx = blockIdx.x * blockDim.x + threadIdx.x;
    const int total = M * (D / 4);
    if (idx >= total) return;
    int d4 = idx & (D / 4 - 1);   // D/4 = 128
    int ms = idx >> 7;
    int s  = ms % S;
    int b  = ms / S;
    int d  = d4 * 4;
    float4 o;
    if (s < NN) {
        float xv  = x_num[b * NN + s];
        float4 w  = *(const float4*)(w_num + (size_t)s * D + d);
        float4 bb = *(const float4*)(b_num + (size_t)s * D + d);
        o.x = xv * w.x + bb.x;
        o.y = xv * w.y + bb.y;
        o.z = xv * w.z + bb.z;
        o.w = xv * w.w + bb.w;
    } else if (s < NN + NC) {
        int c   = s - NN;
        int row = x_cat[b * NC + c] + cat_offsets[c];
        float4 e  = *(const float4*)(emb_cat + (size_t)row * D + d);
        float4 bb = *(const float4*)(b_cat + (size_t)c * D + d);
        o.x = e.x + bb.x; o.y = e.y + bb.y; o.z = e.z + bb.z; o.w = e.w + bb.w;
    } else {
        o = *(const float4*)(cls + d);
    }
    *(float4*)(g_X + (size_t)ms * D + d) = o;
}

// ---------------- LayerNorm (one block / row) ----------------
__global__ void ln_kernel(const float* __restrict__ X, float* __restrict__ Y,
                          const float* __restrict__ w, const float* __restrict__ bb)
{
    int row = blockIdx.x;
    int t   = threadIdx.x;     // 128 threads; 4 floats each
    const float* xr = X + (size_t)row * D;
    float4 v = *(const float4*)(xr + t * 4);
    float s  = v.x + v.y + v.z + v.w;
    float sq = v.x * v.x + v.y * v.y + v.z * v.z + v.w * v.w;
#pragma unroll
    for (int o = 16; o > 0; o >>= 1) {
        s  += __shfl_xor_sync(0xffffffffu, s, o);
        sq += __shfl_xor_sync(0xffffffffu, sq, o);
    }
    __shared__ float ss[4], sqs[4];
    if ((t & 31) == 0) { ss[t >> 5] = s; sqs[t >> 5] = sq; }
    __syncthreads();
    s  = ss[0] + ss[1] + ss[2] + ss[3];
    sq = sqs[0] + sqs[1] + sqs[2] + sqs[3];
    float mean = s * (1.0f / D);
    float var  = sq * (1.0f / D) - mean * mean;
    float r = rsqrtf(var + 1e-5f);
    float4 wv = *(const float4*)(w + t * 4);
    float4 bv = *(const float4*)(bb + t * 4);
    float4 o;
    o.x = (v.x - mean) * r * wv.x + bv.x;
    o.y = (v.y - mean) * r * wv.y + bv.y;
    o.z = (v.z - mean) * r * wv.z + bv.z;
    o.w = (v.w - mean) * r * wv.w + bv.w;
    *(float4*)(Y + (size_t)row * D + t * 4) = o;
}

// ---------------- split-bf16 3-term tensor-core GEMM (~fp32 accurate) ----------------
// C[M,N] = A[M,K] @ W[K,N] + bias[N] (+ Rsd[M,N] if RES)
// Each fp32 input -> bf16 hi + bf16 lo; acc += al*bh + ah*bl + ah*bh.
// BM=128 BN=128 BK=32, 256 threads, warp tile 64x32, m16n8k16 bf16 mma.
// A smem [128][40] bf16 (80B rows: ldmatrix conflict-free: 20r mod 32 distinct).
// B smem [32 k][136 n] bf16 (272B rows: 4r mod 32 distinct), loaded via ldmatrix.trans.
// Double-buffered; one __syncthreads per k-tile.
template <bool RES>
__global__ void __launch_bounds__(256)
gemm_kernel(const float* __restrict__ A, const float* __restrict__ W,
            const float* __restrict__ bias, const float* __restrict__ Rsd,
            float* __restrict__ C, int K, int N)
{
    extern __shared__ uint16_t sm[];
    uint16_t* AsH = sm;                       // [2 buf][A_PLANE]
    uint16_t* AsL = AsH + 2 * A_PLANE;        // [2 buf][A_PLANE]
    uint16_t* BsH = AsL + 2 * A_PLANE;        // [2 buf][B_PLANE]
    uint16_t* BsL = BsH + 2 * B_PLANE;        // [2 buf][B_PLANE]

    const int tid  = threadIdx.x;
    const int lane = tid & 31;
    const int warp = tid >> 5;
    const int wm   = (warp & 1) * 64;
    const int wn   = (warp >> 1) * 32;
    const int grp  = lane >> 2;
    const int t4   = lane & 3;

    const int bm = blockIdx.x;
    const int bn = blockIdx.y;

    float acc[4][4][4];
#pragma unroll
    for (int i = 0; i < 4; ++i)
#pragma unroll
        for (int j = 0; j < 4; ++j)
#pragma unroll
            for (int r = 0; r < 4; ++r) acc[i][j][r] = 0.0f;

    const int ar  = tid >> 3;          // A tile row (0..31), +p*32
    const int ac  = (tid & 7) * 4;     // A tile col (k)
    const int brr = tid >> 5;          // B tile k-row (0..7), +p*8
    const int bcc = (tid & 31) * 4;    // B tile n-col

    const float* Ag = A + (size_t)(bm * 128 + ar) * K + ac;
    const float* Wg = W + (size_t)brr * N + (size_t)bn * 128 + bcc;

    // ldmatrix per-lane addresses (byte offsets into shared)
    // A: mats (m0-7,k0-7),(m8-15,k0-7),(m0-7,k8-15),(m8-15,k8-15) -> a0..a3
    const int arowL = lane & 15;
    const int kofA  = (lane >> 4) * 8;
    uint32_t aH0 = (uint32_t)__cvta_generic_to_shared(AsH) +
                   (uint32_t)(((wm + arowL) * A_STRIDE + kofA) * 2);
    // B: mats (k0-7,nA),(k8-15,nA),(k0-7,nB),(k8-15,nB) -> b0(ni),b1(ni),b0(ni+1),b1(ni+1)
    const int krowL = lane & 15;
    const int nofB  = (lane >> 4) * 8;
    uint32_t bH0 = (uint32_t)__cvta_generic_to_shared(BsH) +
                   (uint32_t)((krowL * B_STRIDE + wn + nofB) * 2);

    const uint32_t A_BUF_B  = A_PLANE * 2;        // bytes per buffer (10240)
    const uint32_t A_PLN_B  = 2 * A_PLANE * 2;    // hi->lo plane offset (20480)
    const uint32_t B_BUF_B  = B_PLANE * 2;        // 8704
    const uint32_t B_PLN_B  = 2 * B_PLANE * 2;    // 17408

    float4 ra[4], rb[4];
    const int KT = K >> 5;

#define GLOAD(kt)                                                              \
    do {                                                                       \
        _Pragma("unroll")                                                      \
        for (int p = 0; p < 4; ++p)                                            \
            ra[p] = *(const float4*)(Ag + (size_t)(p * 32) * K + (kt) * 32);   \
        _Pragma("unroll")                                                      \
        for (int p = 0; p < 4; ++p)                                            \
            rb[p] = *(const float4*)(Wg + (size_t)((kt) * 32 + p * 8) * N);    \
    } while (0)

#define SSTORE(buf)                                                            \
    do {                                                                       \
        _Pragma("unroll")                                                      \
        for (int p = 0; p < 4; ++p) {                                          \
            uint32_t h0, l0, h1, l1;                                           \
            split2(ra[p].x, ra[p].y, h0, l0);                                  \
            split2(ra[p].z, ra[p].w, h1, l1);                                  \
            uint16_t* pa = AsH + (buf) * A_PLANE + (ar + p * 32) * A_STRIDE + ac; \
            *(uint2*)pa = make_uint2(h0, h1);                                  \
            *(uint2*)(pa + 2 * A_PLANE) = make_uint2(l0, l1);                  \
        }                                                                      \
        _Pragma("unroll")                                                      \
        for (int p = 0; p < 4; ++p) {                                          \
            uint32_t h0, l0, h1, l1;                                           \
            split2(rb[p].x, rb[p].y, h0, l0);                                  \
            split2(rb[p].z, rb[p].w, h1, l1);                                  \
            uint16_t* pb = BsH + (buf) * B_PLANE + (brr + p * 8) * B_STRIDE + bcc; \
            ((uint32_t*)pb)[0] = h0;                                           \
            ((uint32_t*)pb)[1] = h1;                                           \
            uint16_t* pl = pb + 2 * B_PLANE;                                   \
            ((uint32_t*)pl)[0] = l0;                                           \
            ((uint32_t*)pl)[1] = l1;                                           \
        }                                                                      \
    } while (0)

    GLOAD(0);
    SSTORE(0);
    __syncthreads();

    for (int kt = 0; kt < KT; ++kt) {
        const int buf = kt & 1;
        if (kt + 1 < KT) GLOAD(kt + 1);

#pragma unroll
        for (int ks = 0; ks < 2; ++ks) {
            uint32_t ah[4][4], al[4][4], bh[4][2], bl[4][2];
#pragma unroll
            for (int mi = 0; mi < 4; ++mi) {
                uint32_t ad = aH0 + buf * A_BUF_B + mi * (16 * A_STRIDE * 2) + ks * 32;
                ldmx4(ad, ah[mi][0], ah[mi][1], ah[mi][2], ah[mi][3]);
                ldmx4(ad + A_PLN_B, al[mi][0], al[mi][1], al[mi][2], al[mi][3]);
            }
#pragma unroll
            for (int pr = 0; pr < 2; ++pr) {
                uint32_t bd = bH0 + buf * B_BUF_B + pr * 32 + ks * (16 * B_STRIDE * 2);
                ldmx4t(bd, bh[2 * pr][0], bh[2 * pr][1], bh[2 * pr + 1][0], bh[2 * pr + 1][1]);
                ldmx4t(bd + B_PLN_B, bl[2 * pr][0], bl[2 * pr][1], bl[2 * pr + 1][0], bl[2 * pr + 1][1]);
            }
#pragma unroll
            for (int mi = 0; mi < 4; ++mi)
#pragma unroll
                for (int ni = 0; ni < 4; ++ni) {
                    mma16(acc[mi][ni], al[mi], bh[ni]);  // cross terms first
                    mma16(acc[mi][ni], ah[mi], bl[ni]);
                    mma16(acc[mi][ni], ah[mi], bh[ni]);  // main term
                }
        }

        if (kt + 1 < KT) SSTORE(buf ^ 1);
        __syncthreads();
    }
#undef GLOAD
#undef SSTORE

    // epilogue
#pragma unroll
    for (int mi = 0; mi < 4; ++mi) {
        int r0 = bm * 128 + wm + mi * 16 + grp;
#pragma unroll
        for (int ni = 0; ni < 4; ++ni) {
            int c0 = bn * 128 + wn + ni * 8 + 2 * t4;
            float b0 = bias[c0], b1 = bias[c0 + 1];
            float2 o0 = make_float2(acc[mi][ni][0] + b0, acc[mi][ni][1] + b1);
            float2 o1 = make_float2(acc[mi][ni][2] + b0, acc[mi][ni][3] + b1);
            if (RES) {
                float2 rv0 = *(const float2*)(Rsd + (size_t)r0 * N + c0);
                float2 rv1 = *(const float2*)(Rsd + (size_t)(r0 + 8) * N + c0);
                o0.x += rv0.x; o0.y += rv0.y;
                o1.x += rv1.x; o1.y += rv1.y;
            }
            *(float2*)(C + (size_t)r0 * N + c0)       = o0;
            *(float2*)(C + (size_t)(r0 + 8) * N + c0) = o1;
        }
    }
}

// ---------------- attention (one block per (batch, head)) ----------------
__global__ void attn_kernel(const float* __restrict__ Q, const float* __restrict__ Kk,
                            const float* __restrict__ V,
                            const unsigned char* __restrict__ mask,
                            float* __restrict__ O)
{
    int bh = blockIdx.x;
    int h  = bh % NH;
    int b  = bh / NH;
    int t  = threadIdx.x;   // 256

    __shared__ float qs[S][DH];
    __shared__ float ks[S][DH];
    __shared__ float vs[S][DH];
    __shared__ float sc[S][S + 3];

    const size_t base = (size_t)(b * S) * D + h * DH;
    for (int i = t; i < S * DH; i += 256) {
        int s = i / DH, d = i % DH;
        qs[s][d] = Q[base + (size_t)s * D + d];
        ks[s][d] = Kk[base + (size_t)s * D + d];
        vs[s][d] = V[base + (size_t)s * D + d];
    }
    __syncthreads();

    const float scale = 0.125f;  // 1/sqrt(64)
    for (int p = t; p < S * S; p += 256) {
        int i = p / S, j = p % S;
        float s = 0.0f;
#pragma unroll 16
        for (int d = 0; d < DH; ++d) s += qs[i][d] * ks[j][d];
        s *= scale;
        if (!mask[i * S + j]) s = -1e9f;
        sc[i][j] = s;
    }
    __syncthreads();

    if (t < S) {
        float mx = -1e30f;
        for (int j = 0; j < S; ++j) mx = fmaxf(mx, sc[t][j]);
        float sum = 0.0f;
        for (int j = 0; j < S; ++j) { float e = __expf(sc[t][j] - mx); sc[t][j] = e; sum += e; }
        float inv = 1.0f / sum;
        for (int j = 0; j < S; ++j) sc[t][j] *= inv;
    }
    __syncthreads();

    for (int p = t; p < S * DH; p += 256) {
        int i = p / DH, d = p % DH;
        float o = 0.0f;
#pragma unroll
        for (int j = 0; j < S; ++j) o += sc[i][j] * vs[j][d];
        O[base + (size_t)i * D + d] = o;
    }
}

// ---------------- ReGLU: u = a * relu(g) ----------------
__global__ void reglu_kernel(const float* __restrict__ F, float* __restrict__ U)
{
    int idx = blockIdx.x * blockDim.x + threadIdx.x;   // over M*FH/4
    const int total = M * (FH / 4);
    if (idx >= total) return;
    int m  = idx / (FH / 4);
    int j4 = (idx % (FH / 4)) * 4;
    float4 a = *(const float4*)(F + (size_t)m * 2 * FH + j4);
    float4 g = *(const float4*)(F + (size_t)m * 2 * FH + FH + j4);
    float4 o;
    o.x = a.x * fmaxf(g.x, 0.0f);
    o.y = a.y * fmaxf(g.y, 0.0f);
    o.z = a.z * fmaxf(g.z, 0.0f);
    o.w = a.w * fmaxf(g.w, 0.0f);
    *(float4*)(U + (size_t)m * FH + j4) = o;
}

// ---------------- head: LN(cls) -> relu -> dot Wh + bh ----------------
__global__ void head_kernel(const float* __restrict__ X,
                            const float* __restrict__ hw, const float* __restrict__ hb,
                            const float* __restrict__ Wh, const float* __restrict__ bh,
                            float* __restrict__ out)
{
    int b = blockIdx.x;
    int t = threadIdx.x;   // 128
    const float* xr = X + ((size_t)b * S + (S - 1)) * D;
    float4 v = *(const float4*)(xr + t * 4);
    float s  = v.x + v.y + v.z + v.w;
    float sq = v.x * v.x + v.y * v.y + v.z * v.z + v.w * v.w;
#pragma unroll
    for (int o = 16; o > 0; o >>= 1) {
        s  += __shfl_xor_sync(0xffffffffu, s, o);
        sq += __shfl_xor_sync(0xffffffffu, sq, o);
    }
    __shared__ float ss[4], sqs[4], ds[4];
    if ((t & 31) == 0) { ss[t >> 5] = s; sqs[t >> 5] = sq; }
    __syncthreads();
    s  = ss[0] + ss[1] + ss[2] + ss[3];
    sq = sqs[0] + sqs[1] + sqs[2] + sqs[3];
    float mean = s * (1.0f / D);
    float var  = sq * (1.0f / D) - mean * mean;
    float r = rsqrtf(var + 1e-5f);
    float4 wv = *(const float4*)(hw + t * 4);
    float4 bv = *(const float4*)(hb + t * 4);
    float4 wh = *(const float4*)(Wh + t * 4);   // DOUT == 1
    float dot = 0.0f;
    dot += fmaxf((v.x - mean) * r * wv.x + bv.x, 0.0f) * wh.x;
    dot += fmaxf((v.y - mean) * r * wv.y + bv.y, 0.0f) * wh.y;
    dot += fmaxf((v.z - mean) * r * wv.z + bv.z, 0.0f) * wh.z;
    dot += fmaxf((v.w - mean) * r * wv.w + bv.w, 0.0f) * wh.w;
#pragma unroll
    for (int o = 16; o > 0; o >>= 1) dot += __shfl_xor_sync(0xffffffffu, dot, o);
    if ((t & 31) == 0) ds[t >> 5] = dot;
    __syncthreads();
    if (t == 0) out[b] = ds[0] + ds[1] + ds[2] + ds[3] + bh[0];
}

// ---------------- launcher ----------------
extern "C" void kernel_launch(void* const* d_in, const int* in_sizes, int n_in,
                              void* d_out, int out_size)
{
    (void)in_sizes; (void)n_in; (void)out_size;
    const float* x_num    = (const float*)d_in[0];
    const int*   x_cat    = (const int*)d_in[1];
    const float* w_num    = (const float*)d_in[2];
    const float* b_num    = (const float*)d_in[3];
    const float* emb_cat  = (const float*)d_in[4];
    const float* b_cat    = (const float*)d_in[5];
    const float* cls      = (const float*)d_in[6];
    const float* ln1_w    = (const float*)d_in[7];
    const float* ln1_b    = (const float*)d_in[8];
    const float* Wq       = (const float*)d_in[9];
    const float* bq       = (const float*)d_in[10];
    const float* Wk       = (const float*)d_in[11];
    const float* bk       = (const float*)d_in[12];
    const float* Wv       = (const float*)d_in[13];
    const float* bv       = (const float*)d_in[14];
    const float* Wo       = (const float*)d_in[15];
    const float* bo       = (const float*)d_in[16];
    const float* ln2_w    = (const float*)d_in[17];
    const float* ln2_b    = (const float*)d_in[18];
    const float* Wf1      = (const float*)d_in[19];
    const float* bf1      = (const float*)d_in[20];
    const float* Wf2      = (const float*)d_in[21];
    const float* bf2      = (const float*)d_in[22];
    const unsigned char* mask_raw = (const unsigned char*)d_in[23];
    const int*   cat_offsets  = (const int*)d_in[24];
    const float* hln_w    = (const float*)d_in[25];
    const float* hln_b    = (const float*)d_in[26];
    const float* Wh       = (const float*)d_in[27];
    const float* bh       = (const float*)d_in[28];
    float* out = (float*)d_out;

    float *X, *Hn, *Q, *Kb, *Vb, *O, *F, *U;
    unsigned char* Mk;
    cudaGetSymbolAddress((void**)&X,  g_X);
    cudaGetSymbolAddress((void**)&Hn, g_Hn);
    cudaGetSymbolAddress((void**)&Q,  g_Q);
    cudaGetSymbolAddress((void**)&Kb, g_K);
    cudaGetSymbolAddress((void**)&Vb, g_V);
    cudaGetSymbolAddress((void**)&O,  g_O);
    cudaGetSymbolAddress((void**)&F,  g_F);
    cudaGetSymbolAddress((void**)&U,  g_U);
    cudaGetSymbolAddress((void**)&Mk, g_mask);

    cudaFuncSetAttribute(gemm_kernel<false>,
                         cudaFuncAttributeMaxDynamicSharedMemorySize, (int)GEMM_SMEM);
    cudaFuncSetAttribute(gemm_kernel<true>,
                         cudaFuncAttributeMaxDynamicSharedMemorySize, (int)GEMM_SMEM);

    mask_convert_kernel<<<(L * S * S + 255) / 256, 256>>>(mask_raw);

    tokenize_kernel<<<(M * (D / 4) + 255) / 256, 256>>>(
        x_num, x_cat, w_num, b_num, emb_cat, b_cat, cls, cat_offsets);

    const dim3 g512(M / 128, D / 128);        // N = 512
    const dim3 g2048(M / 128, (2 * FH) / 128);// N = 2048

    for (int l = 0; l < L; ++l) {
        ln_kernel<<<M, 128>>>(X, Hn, ln1_w + (size_t)l * D, ln1_b + (size_t)l * D);

        gemm_kernel<false><<<g512, 256, GEMM_SMEM>>>(Hn, Wq + (size_t)l * D * D, bq + (size_t)l * D, nullptr, Q,  D, D);
        gemm_kernel<false><<<g512, 256, GEMM_SMEM>>>(Hn, Wk + (size_t)l * D * D, bk + (size_t)l * D, nullptr, Kb, D, D);
        gemm_kernel<false><<<g512, 256, GEMM_SMEM>>>(Hn, Wv + (size_t)l * D * D, bv + (size_t)l * D, nullptr, Vb, D, D);

        attn_kernel<<<B * NH, 256>>>(Q, Kb, Vb, Mk + (size_t)l * S * S, O);

        gemm_kernel<true><<<g512, 256, GEMM_SMEM>>>(O, Wo + (size_t)l * D * D, bo + (size_t)l * D, X, X, D, D);

        ln_kernel<<<M, 128>>>(X, Hn, ln2_w + (size_t)l * D, ln2_b + (size_t)l * D);

        gemm_kernel<false><<<g2048, 256, GEMM_SMEM>>>(Hn, Wf1 + (size_t)l * D * 2 * FH, bf1 + (size_t)l * 2 * FH, nullptr, F, D, 2 * FH);

        reglu_kernel<<<(M * (FH / 4) + 255) / 256, 256>>>(F, U);

        gemm_kernel<true><<<g512, 256, GEMM_SMEM>>>(U, Wf2 + (size_t)l * FH * D, bf2 + (size_t)l * D, X, X, FH, D);
    }

    head_kernel<<<B, 128>>>(X, hln_w, hln_b, Wh, bh, out);
}

// round 6
// speedup vs baseline: 1.7288x; 1.1632x over previous
#include <cuda_runtime.h>
#include <cuda_bf16.h>
#include <cstdint>

// ---------------- problem constants ----------------
namespace {
constexpr int B   = 2048;
constexpr int NN  = 24;
constexpr int NC  = 8;
constexpr int D   = 512;
constexpr int NH  = 8;     // heads
constexpr int L   = 3;
constexpr int FH  = 1024;
constexpr int S   = 33;    // NN + NC + 1
constexpr int DH  = 64;    // D / NH
constexpr int M   = B * S; // 67584 rows; divisible by 128

// weight plane layout ([K][N] bf16 hi/lo), per-layer stride
constexpr size_t W_QO   = (size_t)D * D;
constexpr size_t W_F1   = (size_t)D * (2 * FH);
constexpr size_t W_F2   = (size_t)FH * D;
constexpr size_t W_LSTR = 4 * W_QO + W_F1 + W_F2;
constexpr size_t W_TOT  = 3 * W_LSTR;

// GEMM smem geometry (bf16 elements), BM=128 BN=128 BK=32
constexpr int A_STRIDE = 40;               // 80B rows -> ldmatrix conflict-free
constexpr int B_STRIDE = 136;              // 272B rows -> ldmatrix.trans conflict-free
constexpr int A_PLANE  = 128 * A_STRIDE;   // 5120
constexpr int B_PLANE  = 32 * B_STRIDE;    // 4352
constexpr size_t GEMM_SMEM = (size_t)(2 * 2 * A_PLANE + 2 * 2 * B_PLANE) * 2; // 75776 B
}

// ---------------- scratch (device globals; allocation-free) ----------------
__device__ float g_X[(size_t)M * D];          // residual stream (fp32)
__device__ float g_Q[(size_t)M * D];
__device__ float g_K[(size_t)M * D];
__device__ float g_V[(size_t)M * D];
__device__ float g_F[(size_t)M * 2 * FH];     // FFN pre-activation (fp32)
__device__ uint16_t g_HnH[(size_t)M * D];     // LN out hi/lo bf16 planes
__device__ uint16_t g_HnL[(size_t)M * D];
__device__ uint16_t g_OH[(size_t)M * D];      // attn out planes
__device__ uint16_t g_OL[(size_t)M * D];
__device__ uint16_t g_UH[(size_t)M * FH];     // reglu out planes
__device__ uint16_t g_UL[(size_t)M * FH];
__device__ uint16_t g_WH[W_TOT];              // weight planes [K][N]
__device__ uint16_t g_WL[W_TOT];
__device__ unsigned char g_mask[L * S * S];

// ---------------- helpers ----------------
__device__ __forceinline__ void split2(float x, float y, uint32_t& hi, uint32_t& lo)
{
    __nv_bfloat162 h = __floats2bfloat162_rn(x, y);
    float hx = __bfloat162float(h.x), hy = __bfloat162float(h.y);
    __nv_bfloat162 l = __floats2bfloat162_rn(x - hx, y - hy);
    hi = *reinterpret_cast<uint32_t*>(&h);
    lo = *reinterpret_cast<uint32_t*>(&l);
}

__device__ __forceinline__ void ldmx4(uint32_t addr, uint32_t& r0, uint32_t& r1,
                                      uint32_t& r2, uint32_t& r3)
{
    asm volatile("ldmatrix.sync.aligned.m8n8.x4.shared.b16 {%0,%1,%2,%3},[%4];"
                 : "=r"(r0), "=r"(r1), "=r"(r2), "=r"(r3) : "r"(addr));
}

__device__ __forceinline__ void ldmx4t(uint32_t addr, uint32_t& r0, uint32_t& r1,
                                       uint32_t& r2, uint32_t& r3)
{
    asm volatile("ldmatrix.sync.aligned.m8n8.x4.trans.shared.b16 {%0,%1,%2,%3},[%4];"
                 : "=r"(r0), "=r"(r1), "=r"(r2), "=r"(r3) : "r"(addr));
}

__device__ __forceinline__ void mma16(float* c, const uint32_t* a, const uint32_t* b)
{
    asm volatile(
        "mma.sync.aligned.m16n8k16.row.col.f32.bf16.bf16.f32 "
        "{%0,%1,%2,%3},{%4,%5,%6,%7},{%8,%9},{%0,%1,%2,%3};\n"
        : "+f"(c[0]), "+f"(c[1]), "+f"(c[2]), "+f"(c[3])
        : "r"(a[0]), "r"(a[1]), "r"(a[2]), "r"(a[3]),
          "r"(b[0]), "r"(b[1]));
}

__device__ __forceinline__ void cpasync16(uint32_t dst, const void* src) {
    asm volatile("cp.async.cg.shared.global [%0], [%1], 16;" :: "r"(dst), "l"(src));
}

// ---------------- mask canonicalization ----------------
__global__ void mask_convert_kernel(const unsigned char* __restrict__ raw)
{
    int i = blockIdx.x * blockDim.x + threadIdx.x;
    if (i >= L * S * S) return;
    bool v;
    if (raw[34] == 1)            v = raw[i] != 0;
    else if (raw[3] == 0x3f)     v = ((const float*)raw)[i] != 0.0f;
    else                         v = ((const int*)raw)[i] != 0;
    g_mask[i] = v ? 1 : 0;
}

// ---------------- weight bf16 split (same [K][N] layout) ----------------
__global__ void wsplit_kernel(const float* __restrict__ W,
                              uint16_t* __restrict__ TH, uint16_t* __restrict__ TL,
                              int n4)   // total elems / 4
{
    int idx = blockIdx.x * blockDim.x + threadIdx.x;
    if (idx >= n4) return;
    float4 v = *(const float4*)(W + (size_t)idx * 4);
    uint32_t h0, l0, h1, l1;
    split2(v.x, v.y, h0, l0);
    split2(v.z, v.w, h1, l1);
    *(uint2*)(TH + (size_t)idx * 4) = make_uint2(h0, h1);
    *(uint2*)(TL + (size_t)idx * 4) = make_uint2(l0, l1);
}

// ---------------- tokenizer ----------------
__global__ void tokenize_kernel(const float* __restrict__ x_num,
                                const int* __restrict__ x_cat,
                                const float* __restrict__ w_num,
                                const float* __restrict__ b_num,
                                const float* __restrict__ emb_cat,
                                const float* __restrict__ b_cat,
                                const float* __restrict__ cls,
                                const int* __restrict__ cat_offsets)
{
    int idx = blockIdx.x * blockDim.x + threadIdx.x;
    const int total = M * (D / 4);
    if (idx >= total) return;
    int d4 = idx & (D / 4 - 1);
    int ms = idx >> 7;
    int s  = ms % S;
    int b  = ms / S;
    int d  = d4 * 4;
    float4 o;
    if (s < NN) {
        float xv  = x_num[b * NN + s];
        float4 w  = *(const float4*)(w_num + (size_t)s * D + d);
        float4 bb = *(const float4*)(b_num + (size_t)s * D + d);
        o.x = xv * w.x + bb.x;
        o.y = xv * w.y + bb.y;
        o.z = xv * w.z + bb.z;
        o.w = xv * w.w + bb.w;
    } else if (s < NN + NC) {
        int c   = s - NN;
        int row = x_cat[b * NC + c] + cat_offsets[c];
        float4 e  = *(const float4*)(emb_cat + (size_t)row * D + d);
        float4 bb = *(const float4*)(b_cat + (size_t)c * D + d);
        o.x = e.x + bb.x; o.y = e.y + bb.y; o.z = e.z + bb.z; o.w = e.w + bb.w;
    } else {
        o = *(const float4*)(cls + d);
    }
    *(float4*)(g_X + (size_t)ms * D + d) = o;
}

// ---------------- LayerNorm -> hi/lo bf16 planes ----------------
__global__ void ln_split_kernel(const float* __restrict__ X,
                                uint16_t* __restrict__ YH, uint16_t* __restrict__ YL,
                                const float* __restrict__ w, const float* __restrict__ bb)
{
    int row = blockIdx.x;
    int t   = threadIdx.x;     // 128 threads; 4 floats each
    const float* xr = X + (size_t)row * D;
    float4 v = *(const float4*)(xr + t * 4);
    float s  = v.x + v.y + v.z + v.w;
    float sq = v.x * v.x + v.y * v.y + v.z * v.z + v.w * v.w;
#pragma unroll
    for (int o = 16; o > 0; o >>= 1) {
        s  += __shfl_xor_sync(0xffffffffu, s, o);
        sq += __shfl_xor_sync(0xffffffffu, sq, o);
    }
    __shared__ float ss[4], sqs[4];
    if ((t & 31) == 0) { ss[t >> 5] = s; sqs[t >> 5] = sq; }
    __syncthreads();
    s  = ss[0] + ss[1] + ss[2] + ss[3];
    sq = sqs[0] + sqs[1] + sqs[2] + sqs[3];
    float mean = s * (1.0f / D);
    float var  = sq * (1.0f / D) - mean * mean;
    float r = rsqrtf(var + 1e-5f);
    float4 wv = *(const float4*)(w + t * 4);
    float4 bv = *(const float4*)(bb + t * 4);
    float4 o;
    o.x = (v.x - mean) * r * wv.x + bv.x;
    o.y = (v.y - mean) * r * wv.y + bv.y;
    o.z = (v.z - mean) * r * wv.z + bv.z;
    o.w = (v.w - mean) * r * wv.w + bv.w;
    uint32_t h0, l0, h1, l1;
    split2(o.x, o.y, h0, l0);
    split2(o.z, o.w, h1, l1);
    size_t off = (size_t)row * D + t * 4;
    *(uint2*)(YH + off) = make_uint2(h0, h1);
    *(uint2*)(YL + off) = make_uint2(l0, l1);
}

// ---------------- split-bf16 3-term tensor-core GEMM ----------------
// C[M,N] = A[M,K] @ W[K,N] + bias (+ Rsd).  A,B pre-split bf16 hi/lo planes.
// BM=128 BN=128 BK=32, 256 threads, warp tile 64x32, m16n8k16 bf16 mma.
// cp.async double-buffered; 2 CTAs/SM.
template <bool RES>
__global__ void __launch_bounds__(256, 2)
gemm_kernel(const uint16_t* __restrict__ AH, const uint16_t* __restrict__ AL,
            const uint16_t* __restrict__ BH, const uint16_t* __restrict__ BL,
            const float* __restrict__ bias, const float* __restrict__ Rsd,
            float* __restrict__ C, int K, int N)
{
    extern __shared__ uint16_t sm[];
    uint16_t* AsH = sm;                       // [2 buf][A_PLANE]
    uint16_t* AsL = AsH + 2 * A_PLANE;
    uint16_t* BsH = AsL + 2 * A_PLANE;        // [2 buf][B_PLANE]
    uint16_t* BsL = BsH + 2 * B_PLANE;

    const int tid  = threadIdx.x;
    const int lane = tid & 31;
    const int warp = tid >> 5;
    const int wm   = (warp & 1) * 64;
    const int wn   = (warp >> 1) * 32;
    const int grp  = lane >> 2;
    const int t4   = lane & 3;

    const int bm = blockIdx.x;
    const int bn = blockIdx.y;
    const int KT = K >> 5;

    const uint32_t shAH = (uint32_t)__cvta_generic_to_shared(AsH);
    const uint32_t shAL = (uint32_t)__cvta_generic_to_shared(AsL);
    const uint32_t shBH = (uint32_t)__cvta_generic_to_shared(BsH);
    const uint32_t shBL = (uint32_t)__cvta_generic_to_shared(BsL);

    float acc[4][4][4];
#pragma unroll
    for (int i = 0; i < 4; ++i)
#pragma unroll
        for (int j = 0; j < 4; ++j)
#pragma unroll
            for (int r = 0; r < 4; ++r) acc[i][j][r] = 0.0f;

    // cp.async tile loader: A 512 chunks/plane, B 512 chunks/plane (16B each)
    const int agr = tid >> 1;                    // A row (0..127)
    const int agc = (tid & 1) * 2;               // A chunk col base (0 or 2) -> 2 chunks
    const int bgr = tid >> 3;                    // B k-row (0..31)
    const int bgc = (tid & 7) * 2;               // B chunk col base -> 2 chunks

    auto load_tile = [&](int kt, int b) {
        {
            uint32_t doff = (uint32_t)(b * A_PLANE + agr * A_STRIDE) * 2 + agc * 16;
            const uint16_t* sH = AH + (size_t)(bm * 128 + agr) * K + kt * 32 + agc * 8;
            const uint16_t* sL = AL + (size_t)(bm * 128 + agr) * K + kt * 32 + agc * 8;
            cpasync16(shAH + doff,      sH);
            cpasync16(shAH + doff + 16, sH + 8);
            cpasync16(shAL + doff,      sL);
            cpasync16(shAL + doff + 16, sL + 8);
        }
        {
            uint32_t doff = (uint32_t)(b * B_PLANE + bgr * B_STRIDE) * 2 + bgc * 16;
            const uint16_t* sH = BH + (size_t)(kt * 32 + bgr) * N + bn * 128 + bgc * 8;
            const uint16_t* sL = BL + (size_t)(kt * 32 + bgr) * N + bn * 128 + bgc * 8;
            cpasync16(shBH + doff,      sH);
            cpasync16(shBH + doff + 16, sH + 8);
            cpasync16(shBL + doff,      sL);
            cpasync16(shBL + doff + 16, sL + 8);
        }
        asm volatile("cp.async.commit_group;" ::: "memory");
    };

    // ldmatrix per-lane addresses
    const int arowL = lane & 15;
    const int kofA  = (lane >> 4) * 8;
    const uint32_t aH0 = shAH + (uint32_t)(((wm + arowL) * A_STRIDE + kofA) * 2);
    const int krowL = lane & 15;
    const int nofB  = (lane >> 4) * 8;
    const uint32_t bH0 = shBH + (uint32_t)((krowL * B_STRIDE + wn + nofB) * 2);
    const uint32_t A_PLN = shAL - shAH;       // hi->lo plane byte offset
    const uint32_t B_PLN = shBL - shBH;
    const uint32_t A_BUF = A_PLANE * 2;       // per-buffer bytes
    const uint32_t B_BUF = B_PLANE * 2;

    load_tile(0, 0);
    load_tile(1, 1);

    for (int kt = 0; kt < KT; ++kt) {
        const int b = kt & 1;
        if (kt + 1 < KT) asm volatile("cp.async.wait_group 1;" ::: "memory");
        else             asm volatile("cp.async.wait_group 0;" ::: "memory");
        __syncthreads();

#pragma unroll
        for (int ks = 0; ks < 2; ++ks) {
            uint32_t ah[4][4], al[4][4], bh[4][2], bl[4][2];
#pragma unroll
            for (int mi = 0; mi < 4; ++mi) {
                uint32_t ad = aH0 + b * A_BUF + mi * (16 * A_STRIDE * 2) + ks * 32;
                ldmx4(ad, ah[mi][0], ah[mi][1], ah[mi][2], ah[mi][3]);
                ldmx4(ad + A_PLN, al[mi][0], al[mi][1], al[mi][2], al[mi][3]);
            }
#pragma unroll
            for (int pr = 0; pr < 2; ++pr) {
                uint32_t bd = bH0 + b * B_BUF + pr * 32 + ks * (16 * B_STRIDE * 2);
                ldmx4t(bd, bh[2 * pr][0], bh[2 * pr][1], bh[2 * pr + 1][0], bh[2 * pr + 1][1]);
                ldmx4t(bd + B_PLN, bl[2 * pr][0], bl[2 * pr][1], bl[2 * pr + 1][0], bl[2 * pr + 1][1]);
            }
#pragma unroll
            for (int mi = 0; mi < 4; ++mi)
#pragma unroll
                for (int ni = 0; ni < 4; ++ni) {
                    mma16(acc[mi][ni], al[mi], bh[ni]);
                    mma16(acc[mi][ni], ah[mi], bl[ni]);
                    mma16(acc[mi][ni], ah[mi], bh[ni]);
                }
        }

        __syncthreads();
        if (kt + 2 < KT) load_tile(kt + 2, b);
    }

    // epilogue
#pragma unroll
    for (int mi = 0; mi < 4; ++mi) {
        int r0 = bm * 128 + wm + mi * 16 + grp;
#pragma unroll
        for (int ni = 0; ni < 4; ++ni) {
            int c0 = bn * 128 + wn + ni * 8 + 2 * t4;
            float b0 = bias[c0], b1 = bias[c0 + 1];
            float2 o0 = make_float2(acc[mi][ni][0] + b0, acc[mi][ni][1] + b1);
            float2 o1 = make_float2(acc[mi][ni][2] + b0, acc[mi][ni][3] + b1);
            if (RES) {
                float2 rv0 = *(const float2*)(Rsd + (size_t)r0 * N + c0);
                float2 rv1 = *(const float2*)(Rsd + (size_t)(r0 + 8) * N + c0);
                o0.x += rv0.x; o0.y += rv0.y;
                o1.x += rv1.x; o1.y += rv1.y;
            }
            *(float2*)(C + (size_t)r0 * N + c0)       = o0;
            *(float2*)(C + (size_t)(r0 + 8) * N + c0) = o1;
        }
    }
}

// ---------------- attention (one block per (batch, head)) ----------------
__global__ void attn_kernel(const float* __restrict__ Q, const float* __restrict__ Kk,
                            const float* __restrict__ V,
                            const unsigned char* __restrict__ mask,
                            uint16_t* __restrict__ OH, uint16_t* __restrict__ OL)
{
    int bh = blockIdx.x;
    int h  = bh % NH;
    int b  = bh / NH;
    int t  = threadIdx.x;   // 256

    __shared__ float qs[S][DH + 1];   // odd stride: conflict-free QK loop
    __shared__ float ks[S][DH + 1];
    __shared__ float vs[S][DH + 1];
    __shared__ float sc[S][S + 3];

    const size_t base = (size_t)(b * S) * D + h * DH;
    for (int i = t; i < S * DH; i += 256) {
        int s = i / DH, d = i % DH;
        qs[s][d] = Q[base + (size_t)s * D + d];
        ks[s][d] = Kk[base + (size_t)s * D + d];
        vs[s][d] = V[base + (size_t)s * D + d];
    }
    __syncthreads();

    const float scale = 0.125f;  // 1/sqrt(64)
    for (int p = t; p < S * S; p += 256) {
        int i = p / S, j = p % S;
        float s = 0.0f;
#pragma unroll 16
        for (int d = 0; d < DH; ++d) s += qs[i][d] * ks[j][d];
        s *= scale;
        if (!mask[i * S + j]) s = -1e9f;
        sc[i][j] = s;
    }
    __syncthreads();

    if (t < S) {
        float mx = -1e30f;
        for (int j = 0; j < S; ++j) mx = fmaxf(mx, sc[t][j]);
        float sum = 0.0f;
        for (int j = 0; j < S; ++j) { float e = __expf(sc[t][j] - mx); sc[t][j] = e; sum += e; }
        float inv = 1.0f / sum;
        for (int j = 0; j < S; ++j) sc[t][j] *= inv;
    }
    __syncthreads();

    for (int p = t; p < S * (DH / 2); p += 256) {
        int i  = p / (DH / 2);
        int dd = (p % (DH / 2)) * 2;
        float o0 = 0.0f, o1 = 0.0f;
#pragma unroll
        for (int j = 0; j < S; ++j) {
            float a = sc[i][j];
            o0 += a * vs[j][dd];
            o1 += a * vs[j][dd + 1];
        }
        uint32_t hi, lo;
        split2(o0, o1, hi, lo);
        size_t off = base + (size_t)i * D + dd;
        *(uint32_t*)(OH + off) = hi;
        *(uint32_t*)(OL + off) = lo;
    }
}

// ---------------- ReGLU -> hi/lo planes ----------------
__global__ void reglu_split_kernel(const float* __restrict__ F,
                                   uint16_t* __restrict__ UH, uint16_t* __restrict__ UL)
{
    int idx = blockIdx.x * blockDim.x + threadIdx.x;   // over M*FH/4
    const int total = M * (FH / 4);
    if (idx >= total) return;
    int m  = idx / (FH / 4);
    int j4 = (idx % (FH / 4)) * 4;
    float4 a = *(const float4*)(F + (size_t)m * 2 * FH + j4);
    float4 g = *(const float4*)(F + (size_t)m * 2 * FH + FH + j4);
    float u0 = a.x * fmaxf(g.x, 0.0f);
    float u1 = a.y * fmaxf(g.y, 0.0f);
    float u2 = a.z * fmaxf(g.z, 0.0f);
    float u3 = a.w * fmaxf(g.w, 0.0f);
    uint32_t h0, l0, h1, l1;
    split2(u0, u1, h0, l0);
    split2(u2, u3, h1, l1);
    size_t off = (size_t)m * FH + j4;
    *(uint2*)(UH + off) = make_uint2(h0, h1);
    *(uint2*)(UL + off) = make_uint2(l0, l1);
}

// ---------------- head: LN(cls) -> relu -> dot Wh + bh ----------------
__global__ void head_kernel(const float* __restrict__ X,
                            const float* __restrict__ hw, const float* __restrict__ hb,
                            const float* __restrict__ Wh, const float* __restrict__ bh,
                            float* __restrict__ out)
{
    int b = blockIdx.x;
    int t = threadIdx.x;   // 128
    const float* xr = X + ((size_t)b * S + (S - 1)) * D;
    float4 v = *(const float4*)(xr + t * 4);
    float s  = v.x + v.y + v.z + v.w;
    float sq = v.x * v.x + v.y * v.y + v.z * v.z + v.w * v.w;
#pragma unroll
    for (int o = 16; o > 0; o >>= 1) {
        s  += __shfl_xor_sync(0xffffffffu, s, o);
        sq += __shfl_xor_sync(0xffffffffu, sq, o);
    }
    __shared__ float ss[4], sqs[4], ds[4];
    if ((t & 31) == 0) { ss[t >> 5] = s; sqs[t >> 5] = sq; }
    __syncthreads();
    s  = ss[0] + ss[1] + ss[2] + ss[3];
    sq = sqs[0] + sqs[1] + sqs[2] + sqs[3];
    float mean = s * (1.0f / D);
    float var  = sq * (1.0f / D) - mean * mean;
    float r = rsqrtf(var + 1e-5f);
    float4 wv = *(const float4*)(hw + t * 4);
    float4 bv = *(const float4*)(hb + t * 4);
    float4 wh = *(const float4*)(Wh + t * 4);   // DOUT == 1
    float dot = 0.0f;
    dot += fmaxf((v.x - mean) * r * wv.x + bv.x, 0.0f) * wh.x;
    dot += fmaxf((v.y - mean) * r * wv.y + bv.y, 0.0f) * wh.y;
    dot += fmaxf((v.z - mean) * r * wv.z + bv.z, 0.0f) * wh.z;
    dot += fmaxf((v.w - mean) * r * wv.w + bv.w, 0.0f) * wh.w;
#pragma unroll
    for (int o = 16; o > 0; o >>= 1) dot += __shfl_xor_sync(0xffffffffu, dot, o);
    if ((t & 31) == 0) ds[t >> 5] = dot;
    __syncthreads();
    if (t == 0) out[b] = ds[0] + ds[1] + ds[2] + ds[3] + bh[0];
}

// ---------------- launcher ----------------
extern "C" void kernel_launch(void* const* d_in, const int* in_sizes, int n_in,
                              void* d_out, int out_size)
{
    (void)in_sizes; (void)n_in; (void)out_size;
    const float* x_num    = (const float*)d_in[0];
    const int*   x_cat    = (const int*)d_in[1];
    const float* w_num    = (const float*)d_in[2];
    const float* b_num    = (const float*)d_in[3];
    const float* emb_cat  = (const float*)d_in[4];
    const float* b_cat    = (const float*)d_in[5];
    const float* cls      = (const float*)d_in[6];
    const float* ln1_w    = (const float*)d_in[7];
    const float* ln1_b    = (const float*)d_in[8];
    const float* Wq       = (const float*)d_in[9];
    const float* bq       = (const float*)d_in[10];
    const float* Wk       = (const float*)d_in[11];
    const float* bk       = (const float*)d_in[12];
    const float* Wv       = (const float*)d_in[13];
    const float* bv       = (const float*)d_in[14];
    const float* Wo       = (const float*)d_in[15];
    const float* bo       = (const float*)d_in[16];
    const float* ln2_w    = (const float*)d_in[17];
    const float* ln2_b    = (const float*)d_in[18];
    const float* Wf1      = (const float*)d_in[19];
    const float* bf1      = (const float*)d_in[20];
    const float* Wf2      = (const float*)d_in[21];
    const float* bf2      = (const float*)d_in[22];
    const unsigned char* mask_raw = (const unsigned char*)d_in[23];
    const int*   cat_offsets  = (const int*)d_in[24];
    const float* hln_w    = (const float*)d_in[25];
    const float* hln_b    = (const float*)d_in[26];
    const float* Wh       = (const float*)d_in[27];
    const float* bh       = (const float*)d_in[28];
    float* out = (float*)d_out;

    float *X, *Q, *Kb, *Vb, *F;
    uint16_t *HnH, *HnL, *OH, *OL, *UH, *UL, *WHp, *WLp;
    unsigned char* Mk;
    cudaGetSymbolAddress((void**)&X,   g_X);
    cudaGetSymbolAddress((void**)&Q,   g_Q);
    cudaGetSymbolAddress((void**)&Kb,  g_K);
    cudaGetSymbolAddress((void**)&Vb,  g_V);
    cudaGetSymbolAddress((void**)&F,   g_F);
    cudaGetSymbolAddress((void**)&HnH, g_HnH);
    cudaGetSymbolAddress((void**)&HnL, g_HnL);
    cudaGetSymbolAddress((void**)&OH,  g_OH);
    cudaGetSymbolAddress((void**)&OL,  g_OL);
    cudaGetSymbolAddress((void**)&UH,  g_UH);
    cudaGetSymbolAddress((void**)&UL,  g_UL);
    cudaGetSymbolAddress((void**)&WHp, g_WH);
    cudaGetSymbolAddress((void**)&WLp, g_WL);
    cudaGetSymbolAddress((void**)&Mk,  g_mask);

    cudaFuncSetAttribute(gemm_kernel<false>,
                         cudaFuncAttributeMaxDynamicSharedMemorySize, (int)GEMM_SMEM);
    cudaFuncSetAttribute(gemm_kernel<true>,
                         cudaFuncAttributeMaxDynamicSharedMemorySize, (int)GEMM_SMEM);

    mask_convert_kernel<<<(L * S * S + 255) / 256, 256>>>(mask_raw);
    tokenize_kernel<<<(M * (D / 4) + 255) / 256, 256>>>(
        x_num, x_cat, w_num, b_num, emb_cat, b_cat, cls, cat_offsets);

    // weight bf16 split (per layer: Wq,Wk,Wv,Wo,Wf1,Wf2), layout preserved [K][N]
    for (int l = 0; l < L; ++l) {
        size_t lo = (size_t)l * W_LSTR;
        int nQO = (int)(W_QO / 4), nF1 = (int)(W_F1 / 4), nF2 = (int)(W_F2 / 4);
        wsplit_kernel<<<(nQO + 255) / 256, 256>>>(Wq  + (size_t)l * W_QO, WHp + lo,            WLp + lo,            nQO);
        wsplit_kernel<<<(nQO + 255) / 256, 256>>>(Wk  + (size_t)l * W_QO, WHp + lo + W_QO,     WLp + lo + W_QO,     nQO);
        wsplit_kernel<<<(nQO + 255) / 256, 256>>>(Wv  + (size_t)l * W_QO, WHp + lo + 2 * W_QO, WLp + lo + 2 * W_QO, nQO);
        wsplit_kernel<<<(nQO + 255) / 256, 256>>>(Wo  + (size_t)l * W_QO, WHp + lo + 3 * W_QO, WLp + lo + 3 * W_QO, nQO);
        wsplit_kernel<<<(nF1 + 255) / 256, 256>>>(Wf1 + (size_t)l * W_F1, WHp + lo + 4 * W_QO, WLp + lo + 4 * W_QO, nF1);
        wsplit_kernel<<<(nF2 + 255) / 256, 256>>>(Wf2 + (size_t)l * W_F2, WHp + lo + 4 * W_QO + W_F1, WLp + lo + 4 * W_QO + W_F1, nF2);
    }

    const dim3 g512(M / 128, D / 128);         // N = 512
    const dim3 g2048(M / 128, (2 * FH) / 128); // N = 2048

    for (int l = 0; l < L; ++l) {
        size_t lo = (size_t)l * W_LSTR;
        ln_split_kernel<<<M, 128>>>(X, HnH, HnL, ln1_w + (size_t)l * D, ln1_b + (size_t)l * D);

        gemm_kernel<false><<<g512, 256, GEMM_SMEM>>>(HnH, HnL, WHp + lo,            WLp + lo,            bq + (size_t)l * D, nullptr, Q,  D, D);
        gemm_kernel<false><<<g512, 256, GEMM_SMEM>>>(HnH, HnL, WHp + lo + W_QO,     WLp + lo + W_QO,     bk + (size_t)l * D, nullptr, Kb, D, D);
        gemm_kernel<false><<<g512, 256, GEMM_SMEM>>>(HnH, HnL, WHp + lo + 2 * W_QO, WLp + lo + 2 * W_QO, bv + (size_t)l * D, nullptr, Vb, D, D);

        attn_kernel<<<B * NH, 256>>>(Q, Kb, Vb, Mk + (size_t)l * S * S, OH, OL);

        gemm_kernel<true><<<g512, 256, GEMM_SMEM>>>(OH, OL, WHp + lo + 3 * W_QO, WLp + lo + 3 * W_QO, bo + (size_t)l * D, X, X, D, D);

        ln_split_kernel<<<M, 128>>>(X, HnH, HnL, ln2_w + (size_t)l * D, ln2_b + (size_t)l * D);

        gemm_kernel<false><<<g2048, 256, GEMM_SMEM>>>(HnH, HnL, WHp + lo + 4 * W_QO, WLp + lo + 4 * W_QO, bf1 + (size_t)l * 2 * FH, nullptr, F, D, 2 * FH);

        reglu_split_kernel<<<(M * (FH / 4) + 255) / 256, 256>>>(F, UH, UL);

        gemm_kernel<true><<<g512, 256, GEMM_SMEM>>>(UH, UL, WHp + lo + 4 * W_QO + W_F1, WLp + lo + 4 * W_QO + W_F1, bf2 + (size_t)l * D, X, X, FH, D);
    }

    head_kernel<<<B, 128>>>(X, hln_w, hln_b, Wh, bh, out);
}

// round 7
// speedup vs baseline: 1.7971x; 1.0395x over previous
#include <cuda_runtime.h>
#include <cuda_bf16.h>
#include <cstdint>

// ---------------- problem constants ----------------
namespace {
constexpr int B   = 2048;
constexpr int NN  = 24;
constexpr int NC  = 8;
constexpr int D   = 512;
constexpr int NH  = 8;     // heads
constexpr int L   = 3;
constexpr int FH  = 1024;
constexpr int S   = 33;    // NN + NC + 1
constexpr int DH  = 64;    // D / NH
constexpr int M   = B * S; // 67584 rows; divisible by 128
constexpr int NQKV = 3 * D; // 1536 packed QKV width

// weight plane layout (bf16 hi/lo), per-layer: QKV[512][1536] | O[512][512] | F1[512][2048] | F2[1024][512]
constexpr size_t W_QKV  = (size_t)D * NQKV;        // 786432
constexpr size_t W_O    = (size_t)D * D;           // 262144
constexpr size_t W_F1   = (size_t)D * (2 * FH);    // 1048576
constexpr size_t W_F2   = (size_t)FH * D;          // 524288
constexpr size_t OFF_O  = W_QKV;
constexpr size_t OFF_F1 = W_QKV + W_O;
constexpr size_t OFF_F2 = W_QKV + W_O + W_F1;
constexpr size_t W_LSTR = W_QKV + W_O + W_F1 + W_F2;
constexpr size_t W_TOT  = 3 * W_LSTR;

// GEMM smem geometry (bf16 elements), BM=128 BN=128 BK=32, 3 stages
constexpr int A_STRIDE = 40;               // 80B rows -> ldmatrix conflict-free
constexpr int B_STRIDE = 136;              // 272B rows -> ldmatrix.trans conflict-free
constexpr int A_PLANE  = 128 * A_STRIDE;   // 5120 elems
constexpr int B_PLANE  = 32 * B_STRIDE;    // 4352 elems
// per-stage byte layout: AsH | AsL | BsH | BsL
constexpr uint32_t ST_AH = 0;
constexpr uint32_t ST_AL = (uint32_t)A_PLANE * 2;            // 10240
constexpr uint32_t ST_BH = 2u * A_PLANE * 2;                 // 20480
constexpr uint32_t ST_BL = 2u * A_PLANE * 2 + B_PLANE * 2;   // 29184
constexpr uint32_t STAGE_BYTES = 2u * (A_PLANE + B_PLANE) * 2; // 37888
constexpr size_t GEMM_SMEM = 3 * (size_t)STAGE_BYTES;        // 113664
}

// ---------------- scratch (device globals; allocation-free) ----------------
__device__ float g_X[(size_t)M * D];            // residual stream (fp32)
__device__ float g_QKV[(size_t)M * NQKV];       // packed Q|K|V (fp32)
__device__ float g_F[(size_t)M * 2 * FH];       // FFN pre-activation (fp32)
__device__ float g_bqkv[L * NQKV];              // packed qkv bias
__device__ uint16_t g_HnH[(size_t)M * D];       // LN out hi/lo bf16 planes
__device__ uint16_t g_HnL[(size_t)M * D];
__device__ uint16_t g_OH[(size_t)M * D];        // attn out planes
__device__ uint16_t g_OL[(size_t)M * D];
__device__ uint16_t g_UH[(size_t)M * FH];       // reglu out planes
__device__ uint16_t g_UL[(size_t)M * FH];
__device__ uint16_t g_WH[W_TOT];                // weight planes
__device__ uint16_t g_WL[W_TOT];
__device__ unsigned char g_mask[L * S * S];

// ---------------- helpers ----------------
__device__ __forceinline__ void split2(float x, float y, uint32_t& hi, uint32_t& lo)
{
    __nv_bfloat162 h = __floats2bfloat162_rn(x, y);
    float hx = __bfloat162float(h.x), hy = __bfloat162float(h.y);
    __nv_bfloat162 l = __floats2bfloat162_rn(x - hx, y - hy);
    hi = *reinterpret_cast<uint32_t*>(&h);
    lo = *reinterpret_cast<uint32_t*>(&l);
}

__device__ __forceinline__ void ldmx4(uint32_t addr, uint32_t& r0, uint32_t& r1,
                                      uint32_t& r2, uint32_t& r3)
{
    asm volatile("ldmatrix.sync.aligned.m8n8.x4.shared.b16 {%0,%1,%2,%3},[%4];"
                 : "=r"(r0), "=r"(r1), "=r"(r2), "=r"(r3) : "r"(addr));
}

__device__ __forceinline__ void ldmx4t(uint32_t addr, uint32_t& r0, uint32_t& r1,
                                       uint32_t& r2, uint32_t& r3)
{
    asm volatile("ldmatrix.sync.aligned.m8n8.x4.trans.shared.b16 {%0,%1,%2,%3},[%4];"
                 : "=r"(r0), "=r"(r1), "=r"(r2), "=r"(r3) : "r"(addr));
}

__device__ __forceinline__ void mma16(float* c, const uint32_t* a, const uint32_t* b)
{
    asm volatile(
        "mma.sync.aligned.m16n8k16.row.col.f32.bf16.bf16.f32 "
        "{%0,%1,%2,%3},{%4,%5,%6,%7},{%8,%9},{%0,%1,%2,%3};\n"
        : "+f"(c[0]), "+f"(c[1]), "+f"(c[2]), "+f"(c[3])
        : "r"(a[0]), "r"(a[1]), "r"(a[2]), "r"(a[3]),
          "r"(b[0]), "r"(b[1]));
}

__device__ __forceinline__ void cpasync16(uint32_t dst, const void* src) {
    asm volatile("cp.async.cg.shared.global [%0], [%1], 16;" :: "r"(dst), "l"(src));
}

// ---------------- mask canonicalization ----------------
__global__ void mask_convert_kernel(const unsigned char* __restrict__ raw)
{
    int i = blockIdx.x * blockDim.x + threadIdx.x;
    if (i >= L * S * S) return;
    bool v;
    if (raw[34] == 1)            v = raw[i] != 0;
    else if (raw[3] == 0x3f)     v = ((const float*)raw)[i] != 0.0f;
    else                         v = ((const int*)raw)[i] != 0;
    g_mask[i] = v ? 1 : 0;
}

// ---------------- weight bf16 split with N-packing ----------------
// dst[k][off + n] = split(W[k][n]); dst rows are Nd wide.
__global__ void wsplit_kernel(const float* __restrict__ W,
                              uint16_t* __restrict__ TH, uint16_t* __restrict__ TL,
                              int n4, int Ns4, int Nd, int off)
{
    int idx = blockIdx.x * blockDim.x + threadIdx.x;
    if (idx >= n4) return;
    int k  = idx / Ns4;
    int n  = (idx - k * Ns4) * 4;
    float4 v = *(const float4*)(W + (size_t)k * (Ns4 * 4) + n);
    uint32_t h0, l0, h1, l1;
    split2(v.x, v.y, h0, l0);
    split2(v.z, v.w, h1, l1);
    size_t o = (size_t)k * Nd + off + n;
    *(uint2*)(TH + o) = make_uint2(h0, h1);
    *(uint2*)(TL + o) = make_uint2(l0, l1);
}

// ---------------- qkv bias pack ----------------
__global__ void biaspack_kernel(const float* __restrict__ bq, const float* __restrict__ bk,
                                const float* __restrict__ bv)
{
    int i = blockIdx.x * blockDim.x + threadIdx.x;
    if (i >= L * NQKV) return;
    int l = i / NQKV, c = i % NQKV;
    float v = (c < D) ? bq[l * D + c] : (c < 2 * D) ? bk[l * D + c - D] : bv[l * D + c - 2 * D];
    g_bqkv[i] = v;
}

// ---------------- tokenizer ----------------
__global__ void tokenize_kernel(const float* __restrict__ x_num,
                                const int* __restrict__ x_cat,
                                const float* __restrict__ w_num,
                                const float* __restrict__ b_num,
                                const float* __restrict__ emb_cat,
                                const float* __restrict__ b_cat,
                                const float* __restrict__ cls,
                                const int* __restrict__ cat_offsets)
{
    int idx = blockIdx.x * blockDim.x + threadIdx.x;
    const int total = M * (D / 4);
    if (idx >= total) return;
    int d4 = idx & (D / 4 - 1);
    int ms = idx >> 7;
    int s  = ms % S;
    int b  = ms / S;
    int d  = d4 * 4;
    float4 o;
    if (s < NN) {
        float xv  = x_num[b * NN + s];
        float4 w  = *(const float4*)(w_num + (size_t)s * D + d);
        float4 bb = *(const float4*)(b_num + (size_t)s * D + d);
        o.x = xv * w.x + bb.x;
        o.y = xv * w.y + bb.y;
        o.z = xv * w.z + bb.z;
        o.w = xv * w.w + bb.w;
    } else if (s < NN + NC) {
        int c   = s - NN;
        int row = x_cat[b * NC + c] + cat_offsets[c];
        float4 e  = *(const float4*)(emb_cat + (size_t)row * D + d);
        float4 bb = *(const float4*)(b_cat + (size_t)c * D + d);
        o.x = e.x + bb.x; o.y = e.y + bb.y; o.z = e.z + bb.z; o.w = e.w + bb.w;
    } else {
        o = *(const float4*)(cls + d);
    }
    *(float4*)(g_X + (size_t)ms * D + d) = o;
}

// ---------------- LayerNorm -> hi/lo bf16 planes ----------------
__global__ void ln_split_kernel(const float* __restrict__ X,
                                uint16_t* __restrict__ YH, uint16_t* __restrict__ YL,
                                const float* __restrict__ w, const float* __restrict__ bb)
{
    int row = blockIdx.x;
    int t   = threadIdx.x;     // 128 threads; 4 floats each
    const float* xr = X + (size_t)row * D;
    float4 v = *(const float4*)(xr + t * 4);
    float s  = v.x + v.y + v.z + v.w;
    float sq = v.x * v.x + v.y * v.y + v.z * v.z + v.w * v.w;
#pragma unroll
    for (int o = 16; o > 0; o >>= 1) {
        s  += __shfl_xor_sync(0xffffffffu, s, o);
        sq += __shfl_xor_sync(0xffffffffu, sq, o);
    }
    __shared__ float ss[4], sqs[4];
    if ((t & 31) == 0) { ss[t >> 5] = s; sqs[t >> 5] = sq; }
    __syncthreads();
    s  = ss[0] + ss[1] + ss[2] + ss[3];
    sq = sqs[0] + sqs[1] + sqs[2] + sqs[3];
    float mean = s * (1.0f / D);
    float var  = sq * (1.0f / D) - mean * mean;
    float r = rsqrtf(var + 1e-5f);
    float4 wv = *(const float4*)(w + t * 4);
    float4 bv = *(const float4*)(bb + t * 4);
    float4 o;
    o.x = (v.x - mean) * r * wv.x + bv.x;
    o.y = (v.y - mean) * r * wv.y + bv.y;
    o.z = (v.z - mean) * r * wv.z + bv.z;
    o.w = (v.w - mean) * r * wv.w + bv.w;
    uint32_t h0, l0, h1, l1;
    split2(o.x, o.y, h0, l0);
    split2(o.z, o.w, h1, l1);
    size_t off = (size_t)row * D + t * 4;
    *(uint2*)(YH + off) = make_uint2(h0, h1);
    *(uint2*)(YL + off) = make_uint2(l0, l1);
}

// ---------------- split-bf16 3-term tensor-core GEMM, 3-stage cp.async ----------------
// C[M,N] = A[M,K] @ W[K,N] + bias (+ Rsd).  A,B pre-split bf16 hi/lo planes.
// BM=128 BN=128 BK=32, 256 threads, warp tile 64x32, m16n8k16 bf16 mma.
// One __syncthreads per k-tile; 2 CTAs/SM.
template <bool RES>
__global__ void __launch_bounds__(256, 2)
gemm_kernel(const uint16_t* __restrict__ AH, const uint16_t* __restrict__ AL,
            const uint16_t* __restrict__ BH, const uint16_t* __restrict__ BL,
            const float* __restrict__ bias, const float* __restrict__ Rsd,
            float* __restrict__ C, int K, int N)
{
    extern __shared__ uint16_t sm[];
    const uint32_t shBase = (uint32_t)__cvta_generic_to_shared(sm);

    const int tid  = threadIdx.x;
    const int lane = tid & 31;
    const int warp = tid >> 5;
    const int wm   = (warp & 1) * 64;
    const int wn   = (warp >> 1) * 32;
    const int grp  = lane >> 2;
    const int t4   = lane & 3;

    const int bm = blockIdx.x;
    const int bn = blockIdx.y;
    const int KT = K >> 5;

    float acc[4][4][4];
#pragma unroll
    for (int i = 0; i < 4; ++i)
#pragma unroll
        for (int j = 0; j < 4; ++j)
#pragma unroll
            for (int r = 0; r < 4; ++r) acc[i][j][r] = 0.0f;

    // cp.async tile loader
    const int agr = tid >> 1;                    // A row (0..127)
    const int aco = (tid & 1) * 32;              // A byte col base (2 chunks of 16B)
    const int bgr = tid >> 3;                    // B k-row (0..31)
    const int bco = (tid & 7) * 32;              // B byte col base

    auto load_tile = [&](int kt, int st) {
        const uint32_t sb = shBase + (uint32_t)st * STAGE_BYTES;
        {
            uint32_t doff = sb + (uint32_t)(agr * A_STRIDE) * 2 + aco;
            const uint16_t* sH = AH + (size_t)(bm * 128 + agr) * K + kt * 32 + (aco >> 1);
            const uint16_t* sL = AL + (size_t)(bm * 128 + agr) * K + kt * 32 + (aco >> 1);
            cpasync16(doff,               sH);
            cpasync16(doff + 16,          sH + 8);
            cpasync16(doff + ST_AL,       sL);
            cpasync16(doff + ST_AL + 16,  sL + 8);
        }
        {
            uint32_t doff = sb + ST_BH + (uint32_t)(bgr * B_STRIDE) * 2 + bco;
            const uint16_t* sH = BH + (size_t)(kt * 32 + bgr) * N + bn * 128 + (bco >> 1);
            const uint16_t* sL = BL + (size_t)(kt * 32 + bgr) * N + bn * 128 + (bco >> 1);
            cpasync16(doff,                         sH);
            cpasync16(doff + 16,                    sH + 8);
            cpasync16(doff + (ST_BL - ST_BH),       sL);
            cpasync16(doff + (ST_BL - ST_BH) + 16,  sL + 8);
        }
        asm volatile("cp.async.commit_group;" ::: "memory");
    };

    // ldmatrix per-lane addresses (stage 0 base)
    const int arowL = lane & 15;
    const int kofA  = (lane >> 4) * 8;
    const uint32_t aBase = shBase + (uint32_t)(((wm + arowL) * A_STRIDE + kofA) * 2);
    const int krowL = lane & 15;
    const int nofB  = (lane >> 4) * 8;
    const uint32_t bBase = shBase + ST_BH + (uint32_t)((krowL * B_STRIDE + wn + nofB) * 2);

    load_tile(0, 0);
    load_tile(1, 1);

    for (int kt = 0; kt < KT; ++kt) {
        const int st = kt % 3;
        if (kt + 1 < KT) asm volatile("cp.async.wait_group 1;" ::: "memory");
        else             asm volatile("cp.async.wait_group 0;" ::: "memory");
        __syncthreads();
        // stage (kt+2)%3 was consumed in iteration kt-1 (all threads past the
        // barrier above) -> safe to refill now, overlapping this tile's mma.
        if (kt + 2 < KT) load_tile(kt + 2, (kt + 2) % 3);

        const uint32_t aSt = aBase + (uint32_t)st * STAGE_BYTES;
        const uint32_t bSt = bBase + (uint32_t)st * STAGE_BYTES;
#pragma unroll
        for (int ks = 0; ks < 2; ++ks) {
            uint32_t ah[4][4], al[4][4], bh[4][2], bl[4][2];
#pragma unroll
            for (int mi = 0; mi < 4; ++mi) {
                uint32_t ad = aSt + mi * (16 * A_STRIDE * 2) + ks * 32;
                ldmx4(ad, ah[mi][0], ah[mi][1], ah[mi][2], ah[mi][3]);
                ldmx4(ad + ST_AL, al[mi][0], al[mi][1], al[mi][2], al[mi][3]);
            }
#pragma unroll
            for (int pr = 0; pr < 2; ++pr) {
                uint32_t bd = bSt + pr * 32 + ks * (16 * B_STRIDE * 2);
                ldmx4t(bd, bh[2 * pr][0], bh[2 * pr][1], bh[2 * pr + 1][0], bh[2 * pr + 1][1]);
                ldmx4t(bd + (ST_BL - ST_BH), bl[2 * pr][0], bl[2 * pr][1], bl[2 * pr + 1][0], bl[2 * pr + 1][1]);
            }
#pragma unroll
            for (int mi = 0; mi < 4; ++mi)
#pragma unroll
                for (int ni = 0; ni < 4; ++ni) {
                    mma16(acc[mi][ni], al[mi], bh[ni]);
                    mma16(acc[mi][ni], ah[mi], bl[ni]);
                    mma16(acc[mi][ni], ah[mi], bh[ni]);
                }
        }
    }

    // epilogue
#pragma unroll
    for (int mi = 0; mi < 4; ++mi) {
        int r0 = bm * 128 + wm + mi * 16 + grp;
#pragma unroll
        for (int ni = 0; ni < 4; ++ni) {
            int c0 = bn * 128 + wn + ni * 8 + 2 * t4;
            float b0 = bias[c0], b1 = bias[c0 + 1];
            float2 o0 = make_float2(acc[mi][ni][0] + b0, acc[mi][ni][1] + b1);
            float2 o1 = make_float2(acc[mi][ni][2] + b0, acc[mi][ni][3] + b1);
            if (RES) {
                float2 rv0 = *(const float2*)(Rsd + (size_t)r0 * N + c0);
                float2 rv1 = *(const float2*)(Rsd + (size_t)(r0 + 8) * N + c0);
                o0.x += rv0.x; o0.y += rv0.y;
                o1.x += rv1.x; o1.y += rv1.y;
            }
            *(float2*)(C + (size_t)r0 * N + c0)       = o0;
            *(float2*)(C + (size_t)(r0 + 8) * N + c0) = o1;
        }
    }
}

// ---------------- attention (one block per (batch, head); packed QKV) ----------------
__global__ void attn_kernel(const float* __restrict__ QKV,
                            const unsigned char* __restrict__ mask,
                            uint16_t* __restrict__ OH, uint16_t* __restrict__ OL)
{
    int bh = blockIdx.x;
    int h  = bh % NH;
    int b  = bh / NH;
    int t  = threadIdx.x;   // 256

    __shared__ float qs[S][DH + 1];   // odd stride: conflict-free
    __shared__ float ks[S][DH + 1];
    __shared__ float vs[S][DH + 1];
    __shared__ float sc[S][S + 3];

    const size_t rbase = (size_t)(b * S) * NQKV + h * DH;
    for (int i = t; i < S * DH; i += 256) {
        int s = i / DH, d = i % DH;
        size_t p = rbase + (size_t)s * NQKV + d;
        qs[s][d] = QKV[p];
        ks[s][d] = QKV[p + D];
        vs[s][d] = QKV[p + 2 * D];
    }
    __syncthreads();

    const float scale = 0.125f;  // 1/sqrt(64)
    for (int p = t; p < S * S; p += 256) {
        int i = p / S, j = p % S;
        float s = 0.0f;
#pragma unroll 16
        for (int d = 0; d < DH; ++d) s += qs[i][d] * ks[j][d];
        s *= scale;
        if (!mask[i * S + j]) s = -1e9f;
        sc[i][j] = s;
    }
    __syncthreads();

    if (t < S) {
        float mx = -1e30f;
        for (int j = 0; j < S; ++j) mx = fmaxf(mx, sc[t][j]);
        float sum = 0.0f;
        for (int j = 0; j < S; ++j) { float e = __expf(sc[t][j] - mx); sc[t][j] = e; sum += e; }
        float inv = 1.0f / sum;
        for (int j = 0; j < S; ++j) sc[t][j] *= inv;
    }
    __syncthreads();

    const size_t obase = (size_t)(b * S) * D + h * DH;
    for (int p = t; p < S * (DH / 2); p += 256) {
        int i  = p / (DH / 2);
        int dd = (p % (DH / 2)) * 2;
        float o0 = 0.0f, o1 = 0.0f;
#pragma unroll
        for (int j = 0; j < S; ++j) {
            float a = sc[i][j];
            o0 += a * vs[j][dd];
            o1 += a * vs[j][dd + 1];
        }
        uint32_t hi, lo;
        split2(o0, o1, hi, lo);
        size_t off = obase + (size_t)i * D + dd;
        *(uint32_t*)(OH + off) = hi;
        *(uint32_t*)(OL + off) = lo;
    }
}

// ---------------- ReGLU -> hi/lo planes ----------------
__global__ void reglu_split_kernel(const float* __restrict__ F,
                                   uint16_t* __restrict__ UH, uint16_t* __restrict__ UL)
{
    int idx = blockIdx.x * blockDim.x + threadIdx.x;   // over M*FH/4
    const int total = M * (FH / 4);
    if (idx >= total) return;
    int m  = idx / (FH / 4);
    int j4 = (idx % (FH / 4)) * 4;
    float4 a = *(const float4*)(F + (size_t)m * 2 * FH + j4);
    float4 g = *(const float4*)(F + (size_t)m * 2 * FH + FH + j4);
    float u0 = a.x * fmaxf(g.x, 0.0f);
    float u1 = a.y * fmaxf(g.y, 0.0f);
    float u2 = a.z * fmaxf(g.z, 0.0f);
    float u3 = a.w * fmaxf(g.w, 0.0f);
    uint32_t h0, l0, h1, l1;
    split2(u0, u1, h0, l0);
    split2(u2, u3, h1, l1);
    size_t off = (size_t)m * FH + j4;
    *(uint2*)(UH + off) = make_uint2(h0, h1);
    *(uint2*)(UL + off) = make_uint2(l0, l1);
}

// ---------------- head: LN(cls) -> relu -> dot Wh + bh ----------------
__global__ void head_kernel(const float* __restrict__ X,
                            const float* __restrict__ hw, const float* __restrict__ hb,
                            const float* __restrict__ Wh, const float* __restrict__ bh,
                            float* __restrict__ out)
{
    int b = blockIdx.x;
    int t = threadIdx.x;   // 128
    const float* xr = X + ((size_t)b * S + (S - 1)) * D;
    float4 v = *(const float4*)(xr + t * 4);
    float s  = v.x + v.y + v.z + v.w;
    float sq = v.x * v.x + v.y * v.y + v.z * v.z + v.w * v.w;
#pragma unroll
    for (int o = 16; o > 0; o >>= 1) {
        s  += __shfl_xor_sync(0xffffffffu, s, o);
        sq += __shfl_xor_sync(0xffffffffu, sq, o);
    }
    __shared__ float ss[4], sqs[4], ds[4];
    if ((t & 31) == 0) { ss[t >> 5] = s; sqs[t >> 5] = sq; }
    __syncthreads();
    s  = ss[0] + ss[1] + ss[2] + ss[3];
    sq = sqs[0] + sqs[1] + sqs[2] + sqs[3];
    float mean = s * (1.0f / D);
    float var  = sq * (1.0f / D) - mean * mean;
    float r = rsqrtf(var + 1e-5f);
    float4 wv = *(const float4*)(hw + t * 4);
    float4 bv = *(const float4*)(hb + t * 4);
    float4 wh = *(const float4*)(Wh + t * 4);   // DOUT == 1
    float dot = 0.0f;
    dot += fmaxf((v.x - mean) * r * wv.x + bv.x, 0.0f) * wh.x;
    dot += fmaxf((v.y - mean) * r * wv.y + bv.y, 0.0f) * wh.y;
    dot += fmaxf((v.z - mean) * r * wv.z + bv.z, 0.0f) * wh.z;
    dot += fmaxf((v.w - mean) * r * wv.w + bv.w, 0.0f) * wh.w;
#pragma unroll
    for (int o = 16; o > 0; o >>= 1) dot += __shfl_xor_sync(0xffffffffu, dot, o);
    if ((t & 31) == 0) ds[t >> 5] = dot;
    __syncthreads();
    if (t == 0) out[b] = ds[0] + ds[1] + ds[2] + ds[3] + bh[0];
}

// ---------------- launcher ----------------
extern "C" void kernel_launch(void* const* d_in, const int* in_sizes, int n_in,
                              void* d_out, int out_size)
{
    (void)in_sizes; (void)n_in; (void)out_size;
    const float* x_num    = (const float*)d_in[0];
    const int*   x_cat    = (const int*)d_in[1];
    const float* w_num    = (const float*)d_in[2];
    const float* b_num    = (const float*)d_in[3];
    const float* emb_cat  = (const float*)d_in[4];
    const float* b_cat    = (const float*)d_in[5];
    const float* cls      = (const float*)d_in[6];
    const float* ln1_w    = (const float*)d_in[7];
    const float* ln1_b    = (const float*)d_in[8];
    const float* Wq       = (const float*)d_in[9];
    const float* bq       = (const float*)d_in[10];
    const float* Wk       = (const float*)d_in[11];
    const float* bk       = (const float*)d_in[12];
    const float* Wv       = (const float*)d_in[13];
    const float* bv       = (const float*)d_in[14];
    const float* Wo       = (const float*)d_in[15];
    const float* bo       = (const float*)d_in[16];
    const float* ln2_w    = (const float*)d_in[17];
    const float* ln2_b    = (const float*)d_in[18];
    const float* Wf1      = (const float*)d_in[19];
    const float* bf1      = (const float*)d_in[20];
    const float* Wf2      = (const float*)d_in[21];
    const float* bf2      = (const float*)d_in[22];
    const unsigned char* mask_raw = (const unsigned char*)d_in[23];
    const int*   cat_offsets  = (const int*)d_in[24];
    const float* hln_w    = (const float*)d_in[25];
    const float* hln_b    = (const float*)d_in[26];
    const float* Wh       = (const float*)d_in[27];
    const float* bh       = (const float*)d_in[28];
    float* out = (float*)d_out;

    float *X, *QKV, *F, *BQKV;
    uint16_t *HnH, *HnL, *OH, *OL, *UH, *UL, *WHp, *WLp;
    unsigned char* Mk;
    cudaGetSymbolAddress((void**)&X,    g_X);
    cudaGetSymbolAddress((void**)&QKV,  g_QKV);
    cudaGetSymbolAddress((void**)&F,    g_F);
    cudaGetSymbolAddress((void**)&BQKV, g_bqkv);
    cudaGetSymbolAddress((void**)&HnH,  g_HnH);
    cudaGetSymbolAddress((void**)&HnL,  g_HnL);
    cudaGetSymbolAddress((void**)&OH,   g_OH);
    cudaGetSymbolAddress((void**)&OL,   g_OL);
    cudaGetSymbolAddress((void**)&UH,   g_UH);
    cudaGetSymbolAddress((void**)&UL,   g_UL);
    cudaGetSymbolAddress((void**)&WHp,  g_WH);
    cudaGetSymbolAddress((void**)&WLp,  g_WL);
    cudaGetSymbolAddress((void**)&Mk,   g_mask);

    cudaFuncSetAttribute(gemm_kernel<false>,
                         cudaFuncAttributeMaxDynamicSharedMemorySize, (int)GEMM_SMEM);
    cudaFuncSetAttribute(gemm_kernel<true>,
                         cudaFuncAttributeMaxDynamicSharedMemorySize, (int)GEMM_SMEM);

    mask_convert_kernel<<<(L * S * S + 255) / 256, 256>>>(mask_raw);
    biaspack_kernel<<<(L * NQKV + 255) / 256, 256>>>(bq, bk, bv);
    tokenize_kernel<<<(M * (D / 4) + 255) / 256, 256>>>(
        x_num, x_cat, w_num, b_num, emb_cat, b_cat, cls, cat_offsets);

    // weight bf16 split into packed planes
    for (int l = 0; l < L; ++l) {
        size_t lo = (size_t)l * W_LSTR;
        int nQO = (int)((size_t)D * D / 4);
        int nF1 = (int)(W_F1 / 4), nF2 = (int)(W_F2 / 4);
        wsplit_kernel<<<(nQO + 255) / 256, 256>>>(Wq  + (size_t)l * D * D, WHp + lo, WLp + lo, nQO, D / 4, NQKV, 0);
        wsplit_kernel<<<(nQO + 255) / 256, 256>>>(Wk  + (size_t)l * D * D, WHp + lo, WLp + lo, nQO, D / 4, NQKV, D);
        wsplit_kernel<<<(nQO + 255) / 256, 256>>>(Wv  + (size_t)l * D * D, WHp + lo, WLp + lo, nQO, D / 4, NQKV, 2 * D);
        wsplit_kernel<<<(nQO + 255) / 256, 256>>>(Wo  + (size_t)l * D * D, WHp + lo + OFF_O,  WLp + lo + OFF_O,  nQO, D / 4,  D,       0);
        wsplit_kernel<<<(nF1 + 255) / 256, 256>>>(Wf1 + (size_t)l * W_F1,  WHp + lo + OFF_F1, WLp + lo + OFF_F1, nF1, 2 * FH / 4, 2 * FH, 0);
        wsplit_kernel<<<(nF2 + 255) / 256, 256>>>(Wf2 + (size_t)l * W_F2,  WHp + lo + OFF_F2, WLp + lo + OFF_F2, nF2, D / 4,  D,       0);
    }

    const dim3 gQKV(M / 128, NQKV / 128);       // N = 1536
    const dim3 g512(M / 128, D / 128);          // N = 512
    const dim3 g2048(M / 128, (2 * FH) / 128);  // N = 2048

    for (int l = 0; l < L; ++l) {
        size_t lo = (size_t)l * W_LSTR;
        ln_split_kernel<<<M, 128>>>(X, HnH, HnL, ln1_w + (size_t)l * D, ln1_b + (size_t)l * D);

        gemm_kernel<false><<<gQKV, 256, GEMM_SMEM>>>(HnH, HnL, WHp + lo, WLp + lo, BQKV + l * NQKV, nullptr, QKV, D, NQKV);

        attn_kernel<<<B * NH, 256>>>(QKV, Mk + (size_t)l * S * S, OH, OL);

        gemm_kernel<true><<<g512, 256, GEMM_SMEM>>>(OH, OL, WHp + lo + OFF_O, WLp + lo + OFF_O, bo + (size_t)l * D, X, X, D, D);

        ln_split_kernel<<<M, 128>>>(X, HnH, HnL, ln2_w + (size_t)l * D, ln2_b + (size_t)l * D);

        gemm_kernel<false><<<g2048, 256, GEMM_SMEM>>>(HnH, HnL, WHp + lo + OFF_F1, WLp + lo + OFF_F1, bf1 + (size_t)l * 2 * FH, nullptr, F, D, 2 * FH);

        reglu_split_kernel<<<(M * (FH / 4) + 255) / 256, 256>>>(F, UH, UL);

        gemm_kernel<true><<<g512, 256, GEMM_SMEM>>>(UH, UL, WHp + lo + OFF_F2, WLp + lo + OFF_F2, bf2 + (size_t)l * D, X, X, FH, D);
    }

    head_kernel<<<B, 128>>>(X, hln_w, hln_b, Wh, bh, out);
}

// round 8
// speedup vs baseline: 1.8071x; 1.0055x over previous
#include <cuda_runtime.h>
#include <cuda_bf16.h>
#include <cstdint>

// ---------------- problem constants ----------------
namespace {
constexpr int B   = 2048;
constexpr int NN  = 24;
constexpr int NC  = 8;
constexpr int D   = 512;
constexpr int NH  = 8;     // heads
constexpr int L   = 3;
constexpr int FH  = 1024;
constexpr int S   = 33;    // NN + NC + 1
constexpr int DH  = 64;    // D / NH
constexpr int M   = B * S; // 67584 rows; divisible by 128
constexpr int NQKV = 3 * D; // 1536 packed QKV width

// weight plane layout (bf16 hi/lo), per-layer: QKV[512][1536] | O[512][512] | F1[512][2048 interleaved] | F2[1024][512]
constexpr size_t W_QKV  = (size_t)D * NQKV;
constexpr size_t W_O    = (size_t)D * D;
constexpr size_t W_F1   = (size_t)D * (2 * FH);
constexpr size_t W_F2   = (size_t)FH * D;
constexpr size_t OFF_O  = W_QKV;
constexpr size_t OFF_F1 = W_QKV + W_O;
constexpr size_t OFF_F2 = W_QKV + W_O + W_F1;
constexpr size_t W_LSTR = W_QKV + W_O + W_F1 + W_F2;
constexpr size_t W_TOT  = 3 * W_LSTR;

// GEMM smem geometry (bf16 elements), BM=128 BN=128 BK=32, 3 stages
constexpr int A_STRIDE = 40;               // 80B rows -> ldmatrix conflict-free
constexpr int B_STRIDE = 136;              // 272B rows -> ldmatrix.trans conflict-free
constexpr int A_PLANE  = 128 * A_STRIDE;   // 5120 elems
constexpr int B_PLANE  = 32 * B_STRIDE;    // 4352 elems
constexpr uint32_t ST_AL = (uint32_t)A_PLANE * 2;
constexpr uint32_t ST_BH = 2u * A_PLANE * 2;
constexpr uint32_t ST_BL = 2u * A_PLANE * 2 + B_PLANE * 2;
constexpr uint32_t STAGE_BYTES = 2u * (A_PLANE + B_PLANE) * 2; // 37888
constexpr size_t GEMM_SMEM = 3 * (size_t)STAGE_BYTES;          // 113664

constexpr int EPI_PLAIN = 0;
constexpr int EPI_RES   = 1;
constexpr int EPI_REGLU = 2;
}

// ---------------- scratch (device globals; allocation-free) ----------------
__device__ float g_X[(size_t)M * D];            // residual stream (fp32)
__device__ float g_QKV[(size_t)M * NQKV];       // packed Q|K|V (fp32)
__device__ float g_bqkv[L * NQKV];              // packed qkv bias
__device__ uint16_t g_HnH[(size_t)M * D];       // LN out hi/lo bf16 planes
__device__ uint16_t g_HnL[(size_t)M * D];
__device__ uint16_t g_OH[(size_t)M * D];        // attn out planes
__device__ uint16_t g_OL[(size_t)M * D];
__device__ uint16_t g_UH[(size_t)M * FH];       // reglu out planes
__device__ uint16_t g_UL[(size_t)M * FH];
__device__ uint16_t g_WH[W_TOT];                // weight planes
__device__ uint16_t g_WL[W_TOT];
__device__ unsigned char g_mask[L * S * S];

// ---------------- helpers ----------------
__device__ __forceinline__ void split2(float x, float y, uint32_t& hi, uint32_t& lo)
{
    __nv_bfloat162 h = __floats2bfloat162_rn(x, y);
    float hx = __bfloat162float(h.x), hy = __bfloat162float(h.y);
    __nv_bfloat162 l = __floats2bfloat162_rn(x - hx, y - hy);
    hi = *reinterpret_cast<uint32_t*>(&h);
    lo = *reinterpret_cast<uint32_t*>(&l);
}

__device__ __forceinline__ void split1(float x, uint16_t& hi, uint16_t& lo)
{
    __nv_bfloat16 h = __float2bfloat16(x);
    float hf = __bfloat162float(h);
    __nv_bfloat16 l = __float2bfloat16(x - hf);
    hi = *reinterpret_cast<uint16_t*>(&h);
    lo = *reinterpret_cast<uint16_t*>(&l);
}

__device__ __forceinline__ void ldmx4(uint32_t addr, uint32_t& r0, uint32_t& r1,
                                      uint32_t& r2, uint32_t& r3)
{
    asm volatile("ldmatrix.sync.aligned.m8n8.x4.shared.b16 {%0,%1,%2,%3},[%4];"
                 : "=r"(r0), "=r"(r1), "=r"(r2), "=r"(r3) : "r"(addr));
}

__device__ __forceinline__ void ldmx4t(uint32_t addr, uint32_t& r0, uint32_t& r1,
                                       uint32_t& r2, uint32_t& r3)
{
    asm volatile("ldmatrix.sync.aligned.m8n8.x4.trans.shared.b16 {%0,%1,%2,%3},[%4];"
                 : "=r"(r0), "=r"(r1), "=r"(r2), "=r"(r3) : "r"(addr));
}

__device__ __forceinline__ void mma16(float* c, const uint32_t* a, const uint32_t* b)
{
    asm volatile(
        "mma.sync.aligned.m16n8k16.row.col.f32.bf16.bf16.f32 "
        "{%0,%1,%2,%3},{%4,%5,%6,%7},{%8,%9},{%0,%1,%2,%3};\n"
        : "+f"(c[0]), "+f"(c[1]), "+f"(c[2]), "+f"(c[3])
        : "r"(a[0]), "r"(a[1]), "r"(a[2]), "r"(a[3]),
          "r"(b[0]), "r"(b[1]));
}

__device__ __forceinline__ void cpasync16(uint32_t dst, const void* src) {
    asm volatile("cp.async.cg.shared.global [%0], [%1], 16;" :: "r"(dst), "l"(src));
}

// ---------------- mask canonicalization ----------------
__global__ void mask_convert_kernel(const unsigned char* __restrict__ raw)
{
    int i = blockIdx.x * blockDim.x + threadIdx.x;
    if (i >= L * S * S) return;
    bool v;
    if (raw[34] == 1)            v = raw[i] != 0;
    else if (raw[3] == 0x3f)     v = ((const float*)raw)[i] != 0.0f;
    else                         v = ((const int*)raw)[i] != 0;
    g_mask[i] = v ? 1 : 0;
}

// ---------------- weight bf16 split with N-packing ----------------
// dst[k][off + n] = split(W[k][n]); dst rows are Nd wide.
__global__ void wsplit_kernel(const float* __restrict__ W,
                              uint16_t* __restrict__ TH, uint16_t* __restrict__ TL,
                              int n4, int Ns4, int Nd, int off)
{
    int idx = blockIdx.x * blockDim.x + threadIdx.x;
    if (idx >= n4) return;
    int k  = idx / Ns4;
    int n  = (idx - k * Ns4) * 4;
    float4 v = *(const float4*)(W + (size_t)k * (Ns4 * 4) + n);
    uint32_t h0, l0, h1, l1;
    split2(v.x, v.y, h0, l0);
    split2(v.z, v.w, h1, l1);
    size_t o = (size_t)k * Nd + off + n;
    *(uint2*)(TH + o) = make_uint2(h0, h1);
    *(uint2*)(TL + o) = make_uint2(l0, l1);
}

// ---------------- F1 weight split, interleaved a/g packing ----------------
// src Wf1[k][n], n in [0,2FH): a-col j=n (n<FH) -> dst col 2j; g-col j=n-FH -> dst 2j+1.
__global__ void wsplit_f1_kernel(const float* __restrict__ W,
                                 uint16_t* __restrict__ TH, uint16_t* __restrict__ TL)
{
    int idx = blockIdx.x * blockDim.x + threadIdx.x;   // over D * 2FH / 4
    if (idx >= D * 2 * FH / 4) return;
    int k = idx / (2 * FH / 4);
    int n = (idx - k * (2 * FH / 4)) * 4;
    float4 v = *(const float4*)(W + (size_t)k * (2 * FH) + n);
    int dc0 = (n < FH) ? 2 * n : 2 * (n - FH) + 1;     // stride 2 for the quad
    size_t base = (size_t)k * (2 * FH);
    float vv[4] = {v.x, v.y, v.z, v.w};
#pragma unroll
    for (int i = 0; i < 4; ++i) {
        uint16_t h, l;
        split1(vv[i], h, l);
        TH[base + dc0 + 2 * i] = h;
        TL[base + dc0 + 2 * i] = l;
    }
}

// ---------------- qkv bias pack ----------------
__global__ void biaspack_kernel(const float* __restrict__ bq, const float* __restrict__ bk,
                                const float* __restrict__ bv)
{
    int i = blockIdx.x * blockDim.x + threadIdx.x;
    if (i >= L * NQKV) return;
    int l = i / NQKV, c = i % NQKV;
    float v = (c < D) ? bq[l * D + c] : (c < 2 * D) ? bk[l * D + c - D] : bv[l * D + c - 2 * D];
    g_bqkv[i] = v;
}

// ---------------- tokenizer ----------------
__global__ void tokenize_kernel(const float* __restrict__ x_num,
                                const int* __restrict__ x_cat,
                                const float* __restrict__ w_num,
                                const float* __restrict__ b_num,
                                const float* __restrict__ emb_cat,
                                const float* __restrict__ b_cat,
                                const float* __restrict__ cls,
                                const int* __restrict__ cat_offsets)
{
    int idx = blockIdx.x * blockDim.x + threadIdx.x;
    const int total = M * (D / 4);
    if (idx >= total) return;
    int d4 = idx & (D / 4 - 1);
    int ms = idx >> 7;
    int s  = ms % S;
    int b  = ms / S;
    int d  = d4 * 4;
    float4 o;
    if (s < NN) {
        float xv  = x_num[b * NN + s];
        float4 w  = *(const float4*)(w_num + (size_t)s * D + d);
        float4 bb = *(const float4*)(b_num + (size_t)s * D + d);
        o.x = xv * w.x + bb.x;
        o.y = xv * w.y + bb.y;
        o.z = xv * w.z + bb.z;
        o.w = xv * w.w + bb.w;
    } else if (s < NN + NC) {
        int c   = s - NN;
        int row = x_cat[b * NC + c] + cat_offsets[c];
        float4 e  = *(const float4*)(emb_cat + (size_t)row * D + d);
        float4 bb = *(const float4*)(b_cat + (size_t)c * D + d);
        o.x = e.x + bb.x; o.y = e.y + bb.y; o.z = e.z + bb.z; o.w = e.w + bb.w;
    } else {
        o = *(const float4*)(cls + d);
    }
    *(float4*)(g_X + (size_t)ms * D + d) = o;
}

// ---------------- LayerNorm (warp per row) -> hi/lo bf16 planes ----------------
__global__ void ln_split_kernel(const float* __restrict__ X,
                                uint16_t* __restrict__ YH, uint16_t* __restrict__ YL,
                                const float* __restrict__ w, const float* __restrict__ bb)
{
    int warp = threadIdx.x >> 5;
    int lane = threadIdx.x & 31;
    int row  = blockIdx.x * 8 + warp;
    const float* xr = X + (size_t)row * D;
    float4 v[4];
    float s = 0.0f, sq = 0.0f;
#pragma unroll
    for (int c = 0; c < 4; ++c) {
        v[c] = *(const float4*)(xr + c * 128 + lane * 4);
        s  += v[c].x + v[c].y + v[c].z + v[c].w;
        sq += v[c].x * v[c].x + v[c].y * v[c].y + v[c].z * v[c].z + v[c].w * v[c].w;
    }
#pragma unroll
    for (int o = 16; o > 0; o >>= 1) {
        s  += __shfl_xor_sync(0xffffffffu, s, o);
        sq += __shfl_xor_sync(0xffffffffu, sq, o);
    }
    float mean = s * (1.0f / D);
    float var  = sq * (1.0f / D) - mean * mean;
    float r = rsqrtf(var + 1e-5f);
#pragma unroll
    for (int c = 0; c < 4; ++c) {
        int col = c * 128 + lane * 4;
        float4 wv = *(const float4*)(w + col);
        float4 bv = *(const float4*)(bb + col);
        float4 o;
        o.x = (v[c].x - mean) * r * wv.x + bv.x;
        o.y = (v[c].y - mean) * r * wv.y + bv.y;
        o.z = (v[c].z - mean) * r * wv.z + bv.z;
        o.w = (v[c].w - mean) * r * wv.w + bv.w;
        uint32_t h0, l0, h1, l1;
        split2(o.x, o.y, h0, l0);
        split2(o.z, o.w, h1, l1);
        size_t off = (size_t)row * D + col;
        *(uint2*)(YH + off) = make_uint2(h0, h1);
        *(uint2*)(YL + off) = make_uint2(l0, l1);
    }
}

// ---------------- split-bf16 3-term tensor-core GEMM, 3-stage cp.async ----------------
// EPI_PLAIN: C = A@W + bias
// EPI_RES:   C = A@W + bias + Rsd
// EPI_REGLU: W interleaved [a_j,g_j]; U(bf16 hi/lo) = (a+ba)*relu(g+bg), width N/2
template <int EPI>
__global__ void __launch_bounds__(256, 2)
gemm_kernel(const uint16_t* __restrict__ AH, const uint16_t* __restrict__ AL,
            const uint16_t* __restrict__ BH, const uint16_t* __restrict__ BL,
            const float* __restrict__ bias, const float* __restrict__ Rsd,
            float* __restrict__ C, uint16_t* __restrict__ UH, uint16_t* __restrict__ UL,
            int K, int N)
{
    extern __shared__ uint16_t sm[];
    const uint32_t shBase = (uint32_t)__cvta_generic_to_shared(sm);

    const int tid  = threadIdx.x;
    const int lane = tid & 31;
    const int warp = tid >> 5;
    const int wm   = (warp & 1) * 64;
    const int wn   = (warp >> 1) * 32;
    const int grp  = lane >> 2;
    const int t4   = lane & 3;

    const int bm = blockIdx.x;
    const int bn = blockIdx.y;
    const int KT = K >> 5;

    float acc[4][4][4];
#pragma unroll
    for (int i = 0; i < 4; ++i)
#pragma unroll
        for (int j = 0; j < 4; ++j)
#pragma unroll
            for (int r = 0; r < 4; ++r) acc[i][j][r] = 0.0f;

    const int agr = tid >> 1;
    const int aco = (tid & 1) * 32;
    const int bgr = tid >> 3;
    const int bco = (tid & 7) * 32;

    auto load_tile = [&](int kt, int st) {
        const uint32_t sb = shBase + (uint32_t)st * STAGE_BYTES;
        {
            uint32_t doff = sb + (uint32_t)(agr * A_STRIDE) * 2 + aco;
            const uint16_t* sH = AH + (size_t)(bm * 128 + agr) * K + kt * 32 + (aco >> 1);
            const uint16_t* sL = AL + (size_t)(bm * 128 + agr) * K + kt * 32 + (aco >> 1);
            cpasync16(doff,               sH);
            cpasync16(doff + 16,          sH + 8);
            cpasync16(doff + ST_AL,       sL);
            cpasync16(doff + ST_AL + 16,  sL + 8);
        }
        {
            uint32_t doff = sb + ST_BH + (uint32_t)(bgr * B_STRIDE) * 2 + bco;
            const uint16_t* sH = BH + (size_t)(kt * 32 + bgr) * N + bn * 128 + (bco >> 1);
            const uint16_t* sL = BL + (size_t)(kt * 32 + bgr) * N + bn * 128 + (bco >> 1);
            cpasync16(doff,                         sH);
            cpasync16(doff + 16,                    sH + 8);
            cpasync16(doff + (ST_BL - ST_BH),       sL);
            cpasync16(doff + (ST_BL - ST_BH) + 16,  sL + 8);
        }
        asm volatile("cp.async.commit_group;" ::: "memory");
    };

    const int arowL = lane & 15;
    const int kofA  = (lane >> 4) * 8;
    const uint32_t aBase = shBase + (uint32_t)(((wm + arowL) * A_STRIDE + kofA) * 2);
    const int krowL = lane & 15;
    const int nofB  = (lane >> 4) * 8;
    const uint32_t bBase = shBase + ST_BH + (uint32_t)((krowL * B_STRIDE + wn + nofB) * 2);

    load_tile(0, 0);
    load_tile(1, 1);

    for (int kt = 0; kt < KT; ++kt) {
        const int st = kt % 3;
        if (kt + 1 < KT) asm volatile("cp.async.wait_group 1;" ::: "memory");
        else             asm volatile("cp.async.wait_group 0;" ::: "memory");
        __syncthreads();
        if (kt + 2 < KT) load_tile(kt + 2, (kt + 2) % 3);

        const uint32_t aSt = aBase + (uint32_t)st * STAGE_BYTES;
        const uint32_t bSt = bBase + (uint32_t)st * STAGE_BYTES;
#pragma unroll
        for (int ks = 0; ks < 2; ++ks) {
            uint32_t ah[4][4], al[4][4], bh[4][2], bl[4][2];
#pragma unroll
            for (int mi = 0; mi < 4; ++mi) {
                uint32_t ad = aSt + mi * (16 * A_STRIDE * 2) + ks * 32;
                ldmx4(ad, ah[mi][0], ah[mi][1], ah[mi][2], ah[mi][3]);
                ldmx4(ad + ST_AL, al[mi][0], al[mi][1], al[mi][2], al[mi][3]);
            }
#pragma unroll
            for (int pr = 0; pr < 2; ++pr) {
                uint32_t bd = bSt + pr * 32 + ks * (16 * B_STRIDE * 2);
                ldmx4t(bd, bh[2 * pr][0], bh[2 * pr][1], bh[2 * pr + 1][0], bh[2 * pr + 1][1]);
                ldmx4t(bd + (ST_BL - ST_BH), bl[2 * pr][0], bl[2 * pr][1], bl[2 * pr + 1][0], bl[2 * pr + 1][1]);
            }
#pragma unroll
            for (int mi = 0; mi < 4; ++mi)
#pragma unroll
                for (int ni = 0; ni < 4; ++ni) {
                    mma16(acc[mi][ni], al[mi], bh[ni]);
                    mma16(acc[mi][ni], ah[mi], bl[ni]);
                    mma16(acc[mi][ni], ah[mi], bh[ni]);
                }
        }
    }

    // epilogue
#pragma unroll
    for (int mi = 0; mi < 4; ++mi) {
        int r0 = bm * 128 + wm + mi * 16 + grp;
#pragma unroll
        for (int ni = 0; ni < 4; ++ni) {
            int c0 = bn * 128 + wn + ni * 8 + 2 * t4;
            if (EPI == EPI_REGLU) {
                int j = c0 >> 1;
                float ba = bias[j], bg = bias[FH + j];
                float u0 = (acc[mi][ni][0] + ba) * fmaxf(acc[mi][ni][1] + bg, 0.0f);
                float u1 = (acc[mi][ni][2] + ba) * fmaxf(acc[mi][ni][3] + bg, 0.0f);
                uint16_t h, l;
                split1(u0, h, l);
                UH[(size_t)r0 * FH + j] = h;
                UL[(size_t)r0 * FH + j] = l;
                split1(u1, h, l);
                UH[(size_t)(r0 + 8) * FH + j] = h;
                UL[(size_t)(r0 + 8) * FH + j] = l;
            } else {
                float b0 = bias[c0], b1 = bias[c0 + 1];
                float2 o0 = make_float2(acc[mi][ni][0] + b0, acc[mi][ni][1] + b1);
                float2 o1 = make_float2(acc[mi][ni][2] + b0, acc[mi][ni][3] + b1);
                if (EPI == EPI_RES) {
                    float2 rv0 = *(const float2*)(Rsd + (size_t)r0 * N + c0);
                    float2 rv1 = *(const float2*)(Rsd + (size_t)(r0 + 8) * N + c0);
                    o0.x += rv0.x; o0.y += rv0.y;
                    o1.x += rv1.x; o1.y += rv1.y;
                }
                *(float2*)(C + (size_t)r0 * N + c0)       = o0;
                *(float2*)(C + (size_t)(r0 + 8) * N + c0) = o1;
            }
        }
    }
}

// ---------------- attention (one block per (batch, head); packed QKV) ----------------
__global__ void attn_kernel(const float* __restrict__ QKV,
                            const unsigned char* __restrict__ mask,
                            uint16_t* __restrict__ OH, uint16_t* __restrict__ OL)
{
    int bh = blockIdx.x;
    int h  = bh % NH;
    int b  = bh / NH;
    int t  = threadIdx.x;   // 256

    __shared__ float qs[S][DH + 1];
    __shared__ float ks[S][DH + 1];
    __shared__ float vs[S][DH + 1];
    __shared__ float sc[S][S + 3];

    const size_t rbase = (size_t)(b * S) * NQKV + h * DH;
    for (int i = t; i < S * DH; i += 256) {
        int s = i / DH, d = i % DH;
        size_t p = rbase + (size_t)s * NQKV + d;
        qs[s][d] = QKV[p];
        ks[s][d] = QKV[p + D];
        vs[s][d] = QKV[p + 2 * D];
    }
    __syncthreads();

    const float scale = 0.125f;  // 1/sqrt(64)
    for (int p = t; p < S * S; p += 256) {
        int i = p / S, j = p % S;
        float s = 0.0f;
#pragma unroll 16
        for (int d = 0; d < DH; ++d) s += qs[i][d] * ks[j][d];
        s *= scale;
        if (!mask[i * S + j]) s = -1e9f;
        sc[i][j] = s;
    }
    __syncthreads();

    if (t < S) {
        float mx = -1e30f;
        for (int j = 0; j < S; ++j) mx = fmaxf(mx, sc[t][j]);
        float sum = 0.0f;
        for (int j = 0; j < S; ++j) { float e = __expf(sc[t][j] - mx); sc[t][j] = e; sum += e; }
        float inv = 1.0f / sum;
        for (int j = 0; j < S; ++j) sc[t][j] *= inv;
    }
    __syncthreads();

    const size_t obase = (size_t)(b * S) * D + h * DH;
    for (int p = t; p < S * (DH / 2); p += 256) {
        int i  = p / (DH / 2);
        int dd = (p % (DH / 2)) * 2;
        float o0 = 0.0f, o1 = 0.0f;
#pragma unroll
        for (int j = 0; j < S; ++j) {
            float a = sc[i][j];
            o0 += a * vs[j][dd];
            o1 += a * vs[j][dd + 1];
        }
        uint32_t hi, lo;
        split2(o0, o1, hi, lo);
        size_t off = obase + (size_t)i * D + dd;
        *(uint32_t*)(OH + off) = hi;
        *(uint32_t*)(OL + off) = lo;
    }
}

// ---------------- head: LN(cls) -> relu -> dot Wh + bh ----------------
__global__ void head_kernel(const float* __restrict__ X,
                            const float* __restrict__ hw, const float* __restrict__ hb,
                            const float* __restrict__ Wh, const float* __restrict__ bh,
                            float* __restrict__ out)
{
    int b = blockIdx.x;
    int t = threadIdx.x;   // 128
    const float* xr = X + ((size_t)b * S + (S - 1)) * D;
    float4 v = *(const float4*)(xr + t * 4);
    float s  = v.x + v.y + v.z + v.w;
    float sq = v.x * v.x + v.y * v.y + v.z * v.z + v.w * v.w;
#pragma unroll
    for (int o = 16; o > 0; o >>= 1) {
        s  += __shfl_xor_sync(0xffffffffu, s, o);
        sq += __shfl_xor_sync(0xffffffffu, sq, o);
    }
    __shared__ float ss[4], sqs[4], ds[4];
    if ((t & 31) == 0) { ss[t >> 5] = s; sqs[t >> 5] = sq; }
    __syncthreads();
    s  = ss[0] + ss[1] + ss[2] + ss[3];
    sq = sqs[0] + sqs[1] + sqs[2] + sqs[3];
    float mean = s * (1.0f / D);
    float var  = sq * (1.0f / D) - mean * mean;
    float r = rsqrtf(var + 1e-5f);
    float4 wv = *(const float4*)(hw + t * 4);
    float4 bv = *(const float4*)(hb + t * 4);
    float4 wh = *(const float4*)(Wh + t * 4);   // DOUT == 1
    float dot = 0.0f;
    dot += fmaxf((v.x - mean) * r * wv.x + bv.x, 0.0f) * wh.x;
    dot += fmaxf((v.y - mean) * r * wv.y + bv.y, 0.0f) * wh.y;
    dot += fmaxf((v.z - mean) * r * wv.z + bv.z, 0.0f) * wh.z;
    dot += fmaxf((v.w - mean) * r * wv.w + bv.w, 0.0f) * wh.w;
#pragma unroll
    for (int o = 16; o > 0; o >>= 1) dot += __shfl_xor_sync(0xffffffffu, dot, o);
    if ((t & 31) == 0) ds[t >> 5] = dot;
    __syncthreads();
    if (t == 0) out[b] = ds[0] + ds[1] + ds[2] + ds[3] + bh[0];
}

// ---------------- launcher ----------------
extern "C" void kernel_launch(void* const* d_in, const int* in_sizes, int n_in,
                              void* d_out, int out_size)
{
    (void)in_sizes; (void)n_in; (void)out_size;
    const float* x_num    = (const float*)d_in[0];
    const int*   x_cat    = (const int*)d_in[1];
    const float* w_num    = (const float*)d_in[2];
    const float* b_num    = (const float*)d_in[3];
    const float* emb_cat  = (const float*)d_in[4];
    const float* b_cat    = (const float*)d_in[5];
    const float* cls      = (const float*)d_in[6];
    const float* ln1_w    = (const float*)d_in[7];
    const float* ln1_b    = (const float*)d_in[8];
    const float* Wq       = (const float*)d_in[9];
    const float* bq       = (const float*)d_in[10];
    const float* Wk       = (const float*)d_in[11];
    const float* bk       = (const float*)d_in[12];
    const float* Wv       = (const float*)d_in[13];
    const float* bv       = (const float*)d_in[14];
    const float* Wo       = (const float*)d_in[15];
    const float* bo       = (const float*)d_in[16];
    const float* ln2_w    = (const float*)d_in[17];
    const float* ln2_b    = (const float*)d_in[18];
    const float* Wf1      = (const float*)d_in[19];
    const float* bf1      = (const float*)d_in[20];
    const float* Wf2      = (const float*)d_in[21];
    const float* bf2      = (const float*)d_in[22];
    const unsigned char* mask_raw = (const unsigned char*)d_in[23];
    const int*   cat_offsets  = (const int*)d_in[24];
    const float* hln_w    = (const float*)d_in[25];
    const float* hln_b    = (const float*)d_in[26];
    const float* Wh       = (const float*)d_in[27];
    const float* bh       = (const float*)d_in[28];
    float* out = (float*)d_out;

    float *X, *QKV, *BQKV;
    uint16_t *HnH, *HnL, *OH, *OL, *UH, *UL, *WHp, *WLp;
    unsigned char* Mk;
    cudaGetSymbolAddress((void**)&X,    g_X);
    cudaGetSymbolAddress((void**)&QKV,  g_QKV);
    cudaGetSymbolAddress((void**)&BQKV, g_bqkv);
    cudaGetSymbolAddress((void**)&HnH,  g_HnH);
    cudaGetSymbolAddress((void**)&HnL,  g_HnL);
    cudaGetSymbolAddress((void**)&OH,   g_OH);
    cudaGetSymbolAddress((void**)&OL,   g_OL);
    cudaGetSymbolAddress((void**)&UH,   g_UH);
    cudaGetSymbolAddress((void**)&UL,   g_UL);
    cudaGetSymbolAddress((void**)&WHp,  g_WH);
    cudaGetSymbolAddress((void**)&WLp,  g_WL);
    cudaGetSymbolAddress((void**)&Mk,   g_mask);

    cudaFuncSetAttribute(gemm_kernel<EPI_PLAIN>,
                         cudaFuncAttributeMaxDynamicSharedMemorySize, (int)GEMM_SMEM);
    cudaFuncSetAttribute(gemm_kernel<EPI_RES>,
                         cudaFuncAttributeMaxDynamicSharedMemorySize, (int)GEMM_SMEM);
    cudaFuncSetAttribute(gemm_kernel<EPI_REGLU>,
                         cudaFuncAttributeMaxDynamicSharedMemorySize, (int)GEMM_SMEM);

    mask_convert_kernel<<<(L * S * S + 255) / 256, 256>>>(mask_raw);
    biaspack_kernel<<<(L * NQKV + 255) / 256, 256>>>(bq, bk, bv);
    tokenize_kernel<<<(M * (D / 4) + 255) / 256, 256>>>(
        x_num, x_cat, w_num, b_num, emb_cat, b_cat, cls, cat_offsets);

    // weight bf16 split into packed planes
    for (int l = 0; l < L; ++l) {
        size_t lo = (size_t)l * W_LSTR;
        int nQO = (int)((size_t)D * D / 4);
        int nF1 = (int)(W_F1 / 4), nF2 = (int)(W_F2 / 4);
        wsplit_kernel<<<(nQO + 255) / 256, 256>>>(Wq  + (size_t)l * D * D, WHp + lo, WLp + lo, nQO, D / 4, NQKV, 0);
        wsplit_kernel<<<(nQO + 255) / 256, 256>>>(Wk  + (size_t)l * D * D, WHp + lo, WLp + lo, nQO, D / 4, NQKV, D);
        wsplit_kernel<<<(nQO + 255) / 256, 256>>>(Wv  + (size_t)l * D * D, WHp + lo, WLp + lo, nQO, D / 4, NQKV, 2 * D);
        wsplit_kernel<<<(nQO + 255) / 256, 256>>>(Wo  + (size_t)l * D * D, WHp + lo + OFF_O,  WLp + lo + OFF_O,  nQO, D / 4,  D, 0);
        wsplit_f1_kernel<<<(nF1 + 255) / 256, 256>>>(Wf1 + (size_t)l * W_F1, WHp + lo + OFF_F1, WLp + lo + OFF_F1);
        wsplit_kernel<<<(nF2 + 255) / 256, 256>>>(Wf2 + (size_t)l * W_F2,  WHp + lo + OFF_F2, WLp + lo + OFF_F2, nF2, D / 4,  D, 0);
    }

    const dim3 gQKV(M / 128, NQKV / 128);       // N = 1536
    const dim3 g512(M / 128, D / 128);          // N = 512
    const dim3 g2048(M / 128, (2 * FH) / 128);  // N = 2048 (interleaved a/g)

    for (int l = 0; l < L; ++l) {
        size_t lo = (size_t)l * W_LSTR;
        ln_split_kernel<<<M / 8, 256>>>(X, HnH, HnL, ln1_w + (size_t)l * D, ln1_b + (size_t)l * D);

        gemm_kernel<EPI_PLAIN><<<gQKV, 256, GEMM_SMEM>>>(HnH, HnL, WHp + lo, WLp + lo,
            BQKV + l * NQKV, nullptr, QKV, nullptr, nullptr, D, NQKV);

        attn_kernel<<<B * NH, 256>>>(QKV, Mk + (size_t)l * S * S, OH, OL);

        gemm_kernel<EPI_RES><<<g512, 256, GEMM_SMEM>>>(OH, OL, WHp + lo + OFF_O, WLp + lo + OFF_O,
            bo + (size_t)l * D, X, X, nullptr, nullptr, D, D);

        ln_split_kernel<<<M / 8, 256>>>(X, HnH, HnL, ln2_w + (size_t)l * D, ln2_b + (size_t)l * D);

        gemm_kernel<EPI_REGLU><<<g2048, 256, GEMM_SMEM>>>(HnH, HnL, WHp + lo + OFF_F1, WLp + lo + OFF_F1,
            bf1 + (size_t)l * 2 * FH, nullptr, nullptr, UH, UL, D, 2 * FH);

        gemm_kernel<EPI_RES><<<g512, 256, GEMM_SMEM>>>(UH, UL, WHp + lo + OFF_F2, WLp + lo + OFF_F2,
            bf2 + (size_t)l * D, X, X, nullptr, nullptr, FH, D);
    }

    head_kernel<<<B, 128>>>(X, hln_w, hln_b, Wh, bh, out);
}

// round 9
// speedup vs baseline: 1.8155x; 1.0047x over previous
#include <cuda_runtime.h>
#include <cuda_bf16.h>
#include <cstdint>

// ---------------- problem constants ----------------
namespace {
constexpr int B   = 2048;
constexpr int NN  = 24;
constexpr int NC  = 8;
constexpr int D   = 512;
constexpr int NH  = 8;     // heads
constexpr int L   = 3;
constexpr int FH  = 1024;
constexpr int S   = 33;    // NN + NC + 1
constexpr int DH  = 64;    // D / NH
constexpr int M   = B * S; // 67584 rows; divisible by 128
constexpr int NQKV = 3 * D; // 1536 packed QKV width

// weight plane layout (bf16 hi/lo), per-layer: QKV[512][1536] | O[512][512] | F1[512][2048 interleaved] | F2[1024][512]
constexpr size_t W_QKV  = (size_t)D * NQKV;
constexpr size_t W_O    = (size_t)D * D;
constexpr size_t W_F1   = (size_t)D * (2 * FH);
constexpr size_t W_F2   = (size_t)FH * D;
constexpr size_t OFF_O  = W_QKV;
constexpr size_t OFF_F1 = W_QKV + W_O;
constexpr size_t OFF_F2 = W_QKV + W_O + W_F1;
constexpr size_t W_LSTR = W_QKV + W_O + W_F1 + W_F2;   // 2621440
constexpr size_t W_TOT  = 3 * W_LSTR;

// GEMM smem geometry (bf16 elements), BM=128 BN=128 BK=32, 3 stages
constexpr int A_STRIDE = 40;               // 80B rows -> ldmatrix conflict-free
constexpr int B_STRIDE = 136;              // 272B rows -> ldmatrix.trans conflict-free
constexpr int A_PLANE  = 128 * A_STRIDE;   // 5120 elems
constexpr int B_PLANE  = 32 * B_STRIDE;    // 4352 elems
constexpr uint32_t ST_AL = (uint32_t)A_PLANE * 2;
constexpr uint32_t ST_BH = 2u * A_PLANE * 2;
constexpr uint32_t ST_BL = 2u * A_PLANE * 2 + B_PLANE * 2;
constexpr uint32_t STAGE_BYTES = 2u * (A_PLANE + B_PLANE) * 2; // 37888
constexpr size_t GEMM_SMEM = 3 * (size_t)STAGE_BYTES;          // 113664

constexpr int EPI_PLAIN = 0;
constexpr int EPI_RES   = 1;
constexpr int EPI_REGLU = 2;
}

// ---------------- scratch (device globals; allocation-free) ----------------
__device__ float g_X[(size_t)M * D];            // residual stream (fp32)
__device__ float g_QKV[(size_t)M * NQKV];       // packed Q|K|V (fp32)
__device__ float g_bqkv[L * NQKV];              // packed qkv bias
__device__ uint16_t g_HnH[(size_t)M * D];       // LN out hi/lo bf16 planes
__device__ uint16_t g_HnL[(size_t)M * D];
__device__ uint16_t g_OH[(size_t)M * D];        // attn out planes
__device__ uint16_t g_OL[(size_t)M * D];
__device__ uint16_t g_UH[(size_t)M * FH];       // reglu out planes
__device__ uint16_t g_UL[(size_t)M * FH];
__device__ uint16_t g_WH[W_TOT];                // weight planes
__device__ uint16_t g_WL[W_TOT];
__device__ unsigned char g_mask[L * S * S];

// ---------------- helpers ----------------
__device__ __forceinline__ void split2(float x, float y, uint32_t& hi, uint32_t& lo)
{
    __nv_bfloat162 h = __floats2bfloat162_rn(x, y);
    float hx = __bfloat162float(h.x), hy = __bfloat162float(h.y);
    __nv_bfloat162 l = __floats2bfloat162_rn(x - hx, y - hy);
    hi = *reinterpret_cast<uint32_t*>(&h);
    lo = *reinterpret_cast<uint32_t*>(&l);
}

__device__ __forceinline__ void split1(float x, uint16_t& hi, uint16_t& lo)
{
    __nv_bfloat16 h = __float2bfloat16(x);
    float hf = __bfloat162float(h);
    __nv_bfloat16 l = __float2bfloat16(x - hf);
    hi = *reinterpret_cast<uint16_t*>(&h);
    lo = *reinterpret_cast<uint16_t*>(&l);
}

__device__ __forceinline__ void ldmx4(uint32_t addr, uint32_t& r0, uint32_t& r1,
                                      uint32_t& r2, uint32_t& r3)
{
    asm volatile("ldmatrix.sync.aligned.m8n8.x4.shared.b16 {%0,%1,%2,%3},[%4];"
                 : "=r"(r0), "=r"(r1), "=r"(r2), "=r"(r3) : "r"(addr));
}

__device__ __forceinline__ void ldmx4t(uint32_t addr, uint32_t& r0, uint32_t& r1,
                                       uint32_t& r2, uint32_t& r3)
{
    asm volatile("ldmatrix.sync.aligned.m8n8.x4.trans.shared.b16 {%0,%1,%2,%3},[%4];"
                 : "=r"(r0), "=r"(r1), "=r"(r2), "=r"(r3) : "r"(addr));
}

__device__ __forceinline__ void mma16(float* c, const uint32_t* a, const uint32_t* b)
{
    asm volatile(
        "mma.sync.aligned.m16n8k16.row.col.f32.bf16.bf16.f32 "
        "{%0,%1,%2,%3},{%4,%5,%6,%7},{%8,%9},{%0,%1,%2,%3};\n"
        : "+f"(c[0]), "+f"(c[1]), "+f"(c[2]), "+f"(c[3])
        : "r"(a[0]), "r"(a[1]), "r"(a[2]), "r"(a[3]),
          "r"(b[0]), "r"(b[1]));
}

__device__ __forceinline__ void cpasync16(uint32_t dst, const void* src) {
    asm volatile("cp.async.cg.shared.global [%0], [%1], 16;" :: "r"(dst), "l"(src));
}

// ---------------- mask canonicalization ----------------
__global__ void mask_convert_kernel(const unsigned char* __restrict__ raw)
{
    int i = blockIdx.x * blockDim.x + threadIdx.x;
    if (i >= L * S * S) return;
    bool v;
    if (raw[34] == 1)            v = raw[i] != 0;
    else if (raw[3] == 0x3f)     v = ((const float*)raw)[i] != 0.0f;
    else                         v = ((const int*)raw)[i] != 0;
    g_mask[i] = v ? 1 : 0;
}

// ---------------- qkv bias pack ----------------
__global__ void biaspack_kernel(const float* __restrict__ bq, const float* __restrict__ bk,
                                const float* __restrict__ bv)
{
    int i = blockIdx.x * blockDim.x + threadIdx.x;
    if (i >= L * NQKV) return;
    int l = i / NQKV, c = i % NQKV;
    float v = (c < D) ? bq[l * D + c] : (c < 2 * D) ? bk[l * D + c - D] : bv[l * D + c - 2 * D];
    g_bqkv[i] = v;
}

// ---------------- tokenizer ----------------
__global__ void tokenize_kernel(const float* __restrict__ x_num,
                                const int* __restrict__ x_cat,
                                const float* __restrict__ w_num,
                                const float* __restrict__ b_num,
                                const float* __restrict__ emb_cat,
                                const float* __restrict__ b_cat,
                                const float* __restrict__ cls,
                                const int* __restrict__ cat_offsets)
{
    int idx = blockIdx.x * blockDim.x + threadIdx.x;
    const int total = M * (D / 4);
    if (idx >= total) return;
    int d4 = idx & (D / 4 - 1);
    int ms = idx >> 7;
    int s  = ms % S;
    int b  = ms / S;
    int d  = d4 * 4;
    float4 o;
    if (s < NN) {
        float xv  = x_num[b * NN + s];
        float4 w  = *(const float4*)(w_num + (size_t)s * D + d);
        float4 bb = *(const float4*)(b_num + (size_t)s * D + d);
        o.x = xv * w.x + bb.x;
        o.y = xv * w.y + bb.y;
        o.z = xv * w.z + bb.z;
        o.w = xv * w.w + bb.w;
    } else if (s < NN + NC) {
        int c   = s - NN;
        int row = x_cat[b * NC + c] + cat_offsets[c];
        float4 e  = *(const float4*)(emb_cat + (size_t)row * D + d);
        float4 bb = *(const float4*)(b_cat + (size_t)c * D + d);
        o.x = e.x + bb.x; o.y = e.y + bb.y; o.z = e.z + bb.z; o.w = e.w + bb.w;
    } else {
        o = *(const float4*)(cls + d);
    }
    *(float4*)(g_X + (size_t)ms * D + d) = o;
}

// ---------------- mega weight split: ALL layers, ALL weights, one launch ----------------
// Flat over dst quads of the packed plane. Regions per layer:
//   [0, W_QKV)        : QKV pack   dst[k][n], src Wq/Wk/Wv[l][k][n&511]
//   [OFF_O, OFF_F1)   : O          dst[k][n], src Wo[l][k][n]
//   [OFF_F1, OFF_F2)  : F1 interleaved: dst col c -> (c even: a_{c/2}, c odd: g_{c/2})
//   [OFF_F2, W_LSTR)  : F2         dst[k][n], src Wf2[l][k][n]
__global__ void wsplit_mega_kernel(const float* __restrict__ Wq, const float* __restrict__ Wk,
                                   const float* __restrict__ Wv, const float* __restrict__ Wo,
                                   const float* __restrict__ Wf1, const float* __restrict__ Wf2)
{
    size_t idx = (size_t)blockIdx.x * blockDim.x + threadIdx.x;
    const size_t total = L * W_LSTR / 4;
    if (idx >= total) return;
    size_t d0 = idx * 4;
    int l = (int)(d0 / W_LSTR);
    size_t o = d0 - (size_t)l * W_LSTR;

    float v[4];
    if (o < W_QKV) {
        int k = (int)(o / NQKV);
        int n = (int)(o % NQKV);
        const float* src = (n < D) ? Wq : (n < 2 * D) ? Wk : Wv;
        float4 vv = *(const float4*)(src + ((size_t)l * D + k) * D + (n & (D - 1)));
        v[0] = vv.x; v[1] = vv.y; v[2] = vv.z; v[3] = vv.w;
    } else if (o < OFF_F1) {
        size_t oo = o - OFF_O;
        int k = (int)(oo / D), n = (int)(oo % D);
        float4 vv = *(const float4*)(Wo + ((size_t)l * D + k) * D + n);
        v[0] = vv.x; v[1] = vv.y; v[2] = vv.z; v[3] = vv.w;
    } else if (o < OFF_F2) {
        size_t oo = o - OFF_F1;
        int k = (int)(oo / (2 * FH));
        int c = (int)(oo % (2 * FH));        // quad-aligned, even
        int j = c >> 1;
        const float* row = Wf1 + ((size_t)l * D + k) * (2 * FH);
        v[0] = row[j];          v[1] = row[FH + j];
        v[2] = row[j + 1];      v[3] = row[FH + j + 1];
    } else {
        size_t oo = o - OFF_F2;
        int k = (int)(oo / D), n = (int)(oo % D);
        float4 vv = *(const float4*)(Wf2 + ((size_t)l * FH + k) * D + n);
        v[0] = vv.x; v[1] = vv.y; v[2] = vv.z; v[3] = vv.w;
    }

    uint32_t h0, l0, h1, l1;
    split2(v[0], v[1], h0, l0);
    split2(v[2], v[3], h1, l1);
    *(uint2*)(g_WH + d0) = make_uint2(h0, h1);
    *(uint2*)(g_WL + d0) = make_uint2(l0, l1);
}

// ---------------- LayerNorm (warp per row) -> hi/lo bf16 planes ----------------
__global__ void ln_split_kernel(const float* __restrict__ X,
                                uint16_t* __restrict__ YH, uint16_t* __restrict__ YL,
                                const float* __restrict__ w, const float* __restrict__ bb)
{
    int warp = threadIdx.x >> 5;
    int lane = threadIdx.x & 31;
    int row  = blockIdx.x * 8 + warp;
    const float* xr = X + (size_t)row * D;
    float4 v[4];
    float s = 0.0f, sq = 0.0f;
#pragma unroll
    for (int c = 0; c < 4; ++c) {
        v[c] = *(const float4*)(xr + c * 128 + lane * 4);
        s  += v[c].x + v[c].y + v[c].z + v[c].w;
        sq += v[c].x * v[c].x + v[c].y * v[c].y + v[c].z * v[c].z + v[c].w * v[c].w;
    }
#pragma unroll
    for (int o = 16; o > 0; o >>= 1) {
        s  += __shfl_xor_sync(0xffffffffu, s, o);
        sq += __shfl_xor_sync(0xffffffffu, sq, o);
    }
    float mean = s * (1.0f / D);
    float var  = sq * (1.0f / D) - mean * mean;
    float r = rsqrtf(var + 1e-5f);
#pragma unroll
    for (int c = 0; c < 4; ++c) {
        int col = c * 128 + lane * 4;
        float4 wv = *(const float4*)(w + col);
        float4 bv = *(const float4*)(bb + col);
        float4 o;
        o.x = (v[c].x - mean) * r * wv.x + bv.x;
        o.y = (v[c].y - mean) * r * wv.y + bv.y;
        o.z = (v[c].z - mean) * r * wv.z + bv.z;
        o.w = (v[c].w - mean) * r * wv.w + bv.w;
        uint32_t h0, l0, h1, l1;
        split2(o.x, o.y, h0, l0);
        split2(o.z, o.w, h1, l1);
        size_t off = (size_t)row * D + col;
        *(uint2*)(YH + off) = make_uint2(h0, h1);
        *(uint2*)(YL + off) = make_uint2(l0, l1);
    }
}

// ---------------- split-bf16 3-term tensor-core GEMM, 3-stage cp.async ----------------
// EPI_PLAIN: C = A@W + bias
// EPI_RES:   C = A@W + bias + Rsd
// EPI_REGLU: W interleaved [a_j,g_j]; U(bf16 hi/lo) = (a+ba)*relu(g+bg), width N/2
template <int EPI>
__global__ void __launch_bounds__(256, 2)
gemm_kernel(const uint16_t* __restrict__ AH, const uint16_t* __restrict__ AL,
            const uint16_t* __restrict__ BH, const uint16_t* __restrict__ BL,
            const float* __restrict__ bias, const float* __restrict__ Rsd,
            float* __restrict__ C, uint16_t* __restrict__ UH, uint16_t* __restrict__ UL,
            int K, int N)
{
    extern __shared__ uint16_t sm[];
    const uint32_t shBase = (uint32_t)__cvta_generic_to_shared(sm);

    const int tid  = threadIdx.x;
    const int lane = tid & 31;
    const int warp = tid >> 5;
    const int wm   = (warp & 1) * 64;
    const int wn   = (warp >> 1) * 32;
    const int grp  = lane >> 2;
    const int t4   = lane & 3;

    const int bm = blockIdx.x;
    const int bn = blockIdx.y;
    const int KT = K >> 5;

    float acc[4][4][4];
#pragma unroll
    for (int i = 0; i < 4; ++i)
#pragma unroll
        for (int j = 0; j < 4; ++j)
#pragma unroll
            for (int r = 0; r < 4; ++r) acc[i][j][r] = 0.0f;

    const int agr = tid >> 1;
    const int aco = (tid & 1) * 32;
    const int bgr = tid >> 3;
    const int bco = (tid & 7) * 32;

    auto load_tile = [&](int kt, int st) {
        const uint32_t sb = shBase + (uint32_t)st * STAGE_BYTES;
        {
            uint32_t doff = sb + (uint32_t)(agr * A_STRIDE) * 2 + aco;
            const uint16_t* sH = AH + (size_t)(bm * 128 + agr) * K + kt * 32 + (aco >> 1);
            const uint16_t* sL = AL + (size_t)(bm * 128 + agr) * K + kt * 32 + (aco >> 1);
            cpasync16(doff,               sH);
            cpasync16(doff + 16,          sH + 8);
            cpasync16(doff + ST_AL,       sL);
            cpasync16(doff + ST_AL + 16,  sL + 8);
        }
        {
            uint32_t doff = sb + ST_BH + (uint32_t)(bgr * B_STRIDE) * 2 + bco;
            const uint16_t* sH = BH + (size_t)(kt * 32 + bgr) * N + bn * 128 + (bco >> 1);
            const uint16_t* sL = BL + (size_t)(kt * 32 + bgr) * N + bn * 128 + (bco >> 1);
            cpasync16(doff,                         sH);
            cpasync16(doff + 16,                    sH + 8);
            cpasync16(doff + (ST_BL - ST_BH),       sL);
            cpasync16(doff + (ST_BL - ST_BH) + 16,  sL + 8);
        }
        asm volatile("cp.async.commit_group;" ::: "memory");
    };

    const int arowL = lane & 15;
    const int kofA  = (lane >> 4) * 8;
    const uint32_t aBase = shBase + (uint32_t)(((wm + arowL) * A_STRIDE + kofA) * 2);
    const int krowL = lane & 15;
    const int nofB  = (lane >> 4) * 8;
    const uint32_t bBase = shBase + ST_BH + (uint32_t)((krowL * B_STRIDE + wn + nofB) * 2);

    load_tile(0, 0);
    load_tile(1, 1);

    for (int kt = 0; kt < KT; ++kt) {
        const int st = kt % 3;
        if (kt + 1 < KT) asm volatile("cp.async.wait_group 1;" ::: "memory");
        else             asm volatile("cp.async.wait_group 0;" ::: "memory");
        __syncthreads();
        if (kt + 2 < KT) load_tile(kt + 2, (kt + 2) % 3);

        const uint32_t aSt = aBase + (uint32_t)st * STAGE_BYTES;
        const uint32_t bSt = bBase + (uint32_t)st * STAGE_BYTES;
#pragma unroll
        for (int ks = 0; ks < 2; ++ks) {
            uint32_t ah[4][4], al[4][4], bh[4][2], bl[4][2];
#pragma unroll
            for (int mi = 0; mi < 4; ++mi) {
                uint32_t ad = aSt + mi * (16 * A_STRIDE * 2) + ks * 32;
                ldmx4(ad, ah[mi][0], ah[mi][1], ah[mi][2], ah[mi][3]);
                ldmx4(ad + ST_AL, al[mi][0], al[mi][1], al[mi][2], al[mi][3]);
            }
#pragma unroll
            for (int pr = 0; pr < 2; ++pr) {
                uint32_t bd = bSt + pr * 32 + ks * (16 * B_STRIDE * 2);
                ldmx4t(bd, bh[2 * pr][0], bh[2 * pr][1], bh[2 * pr + 1][0], bh[2 * pr + 1][1]);
                ldmx4t(bd + (ST_BL - ST_BH), bl[2 * pr][0], bl[2 * pr][1], bl[2 * pr + 1][0], bl[2 * pr + 1][1]);
            }
#pragma unroll
            for (int mi = 0; mi < 4; ++mi)
#pragma unroll
                for (int ni = 0; ni < 4; ++ni) {
                    mma16(acc[mi][ni], al[mi], bh[ni]);
                    mma16(acc[mi][ni], ah[mi], bl[ni]);
                    mma16(acc[mi][ni], ah[mi], bh[ni]);
                }
        }
    }

    // epilogue
#pragma unroll
    for (int mi = 0; mi < 4; ++mi) {
        int r0 = bm * 128 + wm + mi * 16 + grp;
#pragma unroll
        for (int ni = 0; ni < 4; ++ni) {
            int c0 = bn * 128 + wn + ni * 8 + 2 * t4;
            if (EPI == EPI_REGLU) {
                int j = c0 >> 1;
                float ba = bias[j], bg = bias[FH + j];
                float u0 = (acc[mi][ni][0] + ba) * fmaxf(acc[mi][ni][1] + bg, 0.0f);
                float u1 = (acc[mi][ni][2] + ba) * fmaxf(acc[mi][ni][3] + bg, 0.0f);
                uint16_t h, l;
                split1(u0, h, l);
                UH[(size_t)r0 * FH + j] = h;
                UL[(size_t)r0 * FH + j] = l;
                split1(u1, h, l);
                UH[(size_t)(r0 + 8) * FH + j] = h;
                UL[(size_t)(r0 + 8) * FH + j] = l;
            } else {
                float b0 = bias[c0], b1 = bias[c0 + 1];
                float2 o0 = make_float2(acc[mi][ni][0] + b0, acc[mi][ni][1] + b1);
                float2 o1 = make_float2(acc[mi][ni][2] + b0, acc[mi][ni][3] + b1);
                if (EPI == EPI_RES) {
                    float2 rv0 = *(const float2*)(Rsd + (size_t)r0 * N + c0);
                    float2 rv1 = *(const float2*)(Rsd + (size_t)(r0 + 8) * N + c0);
                    o0.x += rv0.x; o0.y += rv0.y;
                    o1.x += rv1.x; o1.y += rv1.y;
                }
                *(float2*)(C + (size_t)r0 * N + c0)       = o0;
                *(float2*)(C + (size_t)(r0 + 8) * N + c0) = o1;
            }
        }
    }
}

// ---------------- attention (one block per (batch, head); packed QKV) ----------------
__global__ void attn_kernel(const float* __restrict__ QKV,
                            const unsigned char* __restrict__ mask,
                            uint16_t* __restrict__ OH, uint16_t* __restrict__ OL)
{
    int bh = blockIdx.x;
    int h  = bh % NH;
    int b  = bh / NH;
    int t  = threadIdx.x;   // 256

    __shared__ float qs[S][DH + 1];
    __shared__ float ks[S][DH + 1];
    __shared__ float vs[S][DH + 1];
    __shared__ float sc[S][S + 3];

    const size_t rbase = (size_t)(b * S) * NQKV + h * DH;
    for (int i = t; i < S * DH; i += 256) {
        int s = i / DH, d = i % DH;
        size_t p = rbase + (size_t)s * NQKV + d;
        qs[s][d] = QKV[p];
        ks[s][d] = QKV[p + D];
        vs[s][d] = QKV[p + 2 * D];
    }
    __syncthreads();

    const float scale = 0.125f;  // 1/sqrt(64)
    for (int p = t; p < S * S; p += 256) {
        int i = p / S, j = p % S;
        float s = 0.0f;
#pragma unroll 16
        for (int d = 0; d < DH; ++d) s += qs[i][d] * ks[j][d];
        s *= scale;
        if (!mask[i * S + j]) s = -1e9f;
        sc[i][j] = s;
    }
    __syncthreads();

    if (t < S) {
        float mx = -1e30f;
        for (int j = 0; j < S; ++j) mx = fmaxf(mx, sc[t][j]);
        float sum = 0.0f;
        for (int j = 0; j < S; ++j) { float e = __expf(sc[t][j] - mx); sc[t][j] = e; sum += e; }
        float inv = 1.0f / sum;
        for (int j = 0; j < S; ++j) sc[t][j] *= inv;
    }
    __syncthreads();

    const size_t obase = (size_t)(b * S) * D + h * DH;
    for (int p = t; p < S * (DH / 2); p += 256) {
        int i  = p / (DH / 2);
        int dd = (p % (DH / 2)) * 2;
        float o0 = 0.0f, o1 = 0.0f;
#pragma unroll
        for (int j = 0; j < S; ++j) {
            float a = sc[i][j];
            o0 += a * vs[j][dd];
            o1 += a * vs[j][dd + 1];
        }
        uint32_t hi, lo;
        split2(o0, o1, hi, lo);
        size_t off = obase + (size_t)i * D + dd;
        *(uint32_t*)(OH + off) = hi;
        *(uint32_t*)(OL + off) = lo;
    }
}

// ---------------- head: LN(cls) -> relu -> dot Wh + bh ----------------
__global__ void head_kernel(const float* __restrict__ X,
                            const float* __restrict__ hw, const float* __restrict__ hb,
                            const float* __restrict__ Wh, const float* __restrict__ bh,
                            float* __restrict__ out)
{
    int b = blockIdx.x;
    int t = threadIdx.x;   // 128
    const float* xr = X + ((size_t)b * S + (S - 1)) * D;
    float4 v = *(const float4*)(xr + t * 4);
    float s  = v.x + v.y + v.z + v.w;
    float sq = v.x * v.x + v.y * v.y + v.z * v.z + v.w * v.w;
#pragma unroll
    for (int o = 16; o > 0; o >>= 1) {
        s  += __shfl_xor_sync(0xffffffffu, s, o);
        sq += __shfl_xor_sync(0xffffffffu, sq, o);
    }
    __shared__ float ss[4], sqs[4], ds[4];
    if ((t & 31) == 0) { ss[t >> 5] = s; sqs[t >> 5] = sq; }
    __syncthreads();
    s  = ss[0] + ss[1] + ss[2] + ss[3];
    sq = sqs[0] + sqs[1] + sqs[2] + sqs[3];
    float mean = s * (1.0f / D);
    float var  = sq * (1.0f / D) - mean * mean;
    float r = rsqrtf(var + 1e-5f);
    float4 wv = *(const float4*)(hw + t * 4);
    float4 bv = *(const float4*)(hb + t * 4);
    float4 wh = *(const float4*)(Wh + t * 4);   // DOUT == 1
    float dot = 0.0f;
    dot += fmaxf((v.x - mean) * r * wv.x + bv.x, 0.0f) * wh.x;
    dot += fmaxf((v.y - mean) * r * wv.y + bv.y, 0.0f) * wh.y;
    dot += fmaxf((v.z - mean) * r * wv.z + bv.z, 0.0f) * wh.z;
    dot += fmaxf((v.w - mean) * r * wv.w + bv.w, 0.0f) * wh.w;
#pragma unroll
    for (int o = 16; o > 0; o >>= 1) dot += __shfl_xor_sync(0xffffffffu, dot, o);
    if ((t & 31) == 0) ds[t >> 5] = dot;
    __syncthreads();
    if (t == 0) out[b] = ds[0] + ds[1] + ds[2] + ds[3] + bh[0];
}

// ---------------- launcher ----------------
extern "C" void kernel_launch(void* const* d_in, const int* in_sizes, int n_in,
                              void* d_out, int out_size)
{
    (void)in_sizes; (void)n_in; (void)out_size;
    const float* x_num    = (const float*)d_in[0];
    const int*   x_cat    = (const int*)d_in[1];
    const float* w_num    = (const float*)d_in[2];
    const float* b_num    = (const float*)d_in[3];
    const float* emb_cat  = (const float*)d_in[4];
    const float* b_cat    = (const float*)d_in[5];
    const float* cls      = (const float*)d_in[6];
    const float* ln1_w    = (const float*)d_in[7];
    const float* ln1_b    = (const float*)d_in[8];
    const float* Wq       = (const float*)d_in[9];
    const float* bq       = (const float*)d_in[10];
    const float* Wk       = (const float*)d_in[11];
    const float* bk       = (const float*)d_in[12];
    const float* Wv       = (const float*)d_in[13];
    const float* bv       = (const float*)d_in[14];
    const float* Wo       = (const float*)d_in[15];
    const float* bo       = (const float*)d_in[16];
    const float* ln2_w    = (const float*)d_in[17];
    const float* ln2_b    = (const float*)d_in[18];
    const float* Wf1      = (const float*)d_in[19];
    const float* bf1      = (const float*)d_in[20];
    const float* Wf2      = (const float*)d_in[21];
    const float* bf2      = (const float*)d_in[22];
    const unsigned char* mask_raw = (const unsigned char*)d_in[23];
    const int*   cat_offsets  = (const int*)d_in[24];
    const float* hln_w    = (const float*)d_in[25];
    const float* hln_b    = (const float*)d_in[26];
    const float* Wh       = (const float*)d_in[27];
    const float* bh       = (const float*)d_in[28];
    float* out = (float*)d_out;

    float *X, *QKV, *BQKV;
    uint16_t *HnH, *HnL, *OH, *OL, *UH, *UL, *WHp, *WLp;
    unsigned char* Mk;
    cudaGetSymbolAddress((void**)&X,    g_X);
    cudaGetSymbolAddress((void**)&QKV,  g_QKV);
    cudaGetSymbolAddress((void**)&BQKV, g_bqkv);
    cudaGetSymbolAddress((void**)&HnH,  g_HnH);
    cudaGetSymbolAddress((void**)&HnL,  g_HnL);
    cudaGetSymbolAddress((void**)&OH,   g_OH);
    cudaGetSymbolAddress((void**)&OL,   g_OL);
    cudaGetSymbolAddress((void**)&UH,   g_UH);
    cudaGetSymbolAddress((void**)&UL,   g_UL);
    cudaGetSymbolAddress((void**)&WHp,  g_WH);
    cudaGetSymbolAddress((void**)&WLp,  g_WL);
    cudaGetSymbolAddress((void**)&Mk,   g_mask);

    cudaFuncSetAttribute(gemm_kernel<EPI_PLAIN>,
                         cudaFuncAttributeMaxDynamicSharedMemorySize, (int)GEMM_SMEM);
    cudaFuncSetAttribute(gemm_kernel<EPI_RES>,
                         cudaFuncAttributeMaxDynamicSharedMemorySize, (int)GEMM_SMEM);
    cudaFuncSetAttribute(gemm_kernel<EPI_REGLU>,
                         cudaFuncAttributeMaxDynamicSharedMemorySize, (int)GEMM_SMEM);

    // launch order fixed so ncu (-s 5 -c 1) captures the QKV GEMM (launch #6)
    mask_convert_kernel<<<(L * S * S + 255) / 256, 256>>>(mask_raw);                 // 1
    biaspack_kernel<<<(L * NQKV + 255) / 256, 256>>>(bq, bk, bv);                    // 2
    tokenize_kernel<<<(M * (D / 4) + 255) / 256, 256>>>(                             // 3
        x_num, x_cat, w_num, b_num, emb_cat, b_cat, cls, cat_offsets);
    {
        size_t total = L * W_LSTR / 4;
        wsplit_mega_kernel<<<(unsigned)((total + 255) / 256), 256>>>(                // 4
            Wq, Wk, Wv, Wo, Wf1, Wf2);
    }

    const dim3 gQKV(M / 128, NQKV / 128);       // N = 1536
    const dim3 g512(M / 128, D / 128);          // N = 512
    const dim3 g2048(M / 128, (2 * FH) / 128);  // N = 2048 (interleaved a/g)

    for (int l = 0; l < L; ++l) {
        size_t lo = (size_t)l * W_LSTR;
        ln_split_kernel<<<M / 8, 256>>>(X, HnH, HnL, ln1_w + (size_t)l * D, ln1_b + (size_t)l * D);  // 5

        gemm_kernel<EPI_PLAIN><<<gQKV, 256, GEMM_SMEM>>>(HnH, HnL, WHp + lo, WLp + lo,               // 6 <- ncu
            BQKV + l * NQKV, nullptr, QKV, nullptr, nullptr, D, NQKV);

        attn_kernel<<<B * NH, 256>>>(QKV, Mk + (size_t)l * S * S, OH, OL);

        gemm_kernel<EPI_RES><<<g512, 256, GEMM_SMEM>>>(OH, OL, WHp + lo + OFF_O, WLp + lo + OFF_O,
            bo + (size_t)l * D, X, X, nullptr, nullptr, D, D);

        ln_split_kernel<<<M / 8, 256>>>(X, HnH, HnL, ln2_w + (size_t)l * D, ln2_b + (size_t)l * D);

        gemm_kernel<EPI_REGLU><<<g2048, 256, GEMM_SMEM>>>(HnH, HnL, WHp + lo + OFF_F1, WLp + lo + OFF_F1,
            bf1 + (size_t)l * 2 * FH, nullptr, nullptr, UH, UL, D, 2 * FH);

        gemm_kernel<EPI_RES><<<g512, 256, GEMM_SMEM>>>(UH, UL, WHp + lo + OFF_F2, WLp + lo + OFF_F2,
            bf2 + (size_t)l * D, X, X, nullptr, nullptr, FH, D);
    }

    head_kernel<<<B, 128>>>(X, hln_w, hln_b, Wh, bh, out);
}

// round 10
// speedup vs baseline: 1.8233x; 1.0043x over previous
#include <cuda_runtime.h>
#include <cuda_bf16.h>
#include <cstdint>

// ---------------- problem constants ----------------
namespace {
constexpr int B   = 2048;
constexpr int NN  = 24;
constexpr int NC  = 8;
constexpr int D   = 512;
constexpr int NH  = 8;     // heads
constexpr int L   = 3;
constexpr int FH  = 1024;
constexpr int S   = 33;    // NN + NC + 1
constexpr int DH  = 64;    // D / NH
constexpr int M   = B * S; // 67584 rows; divisible by 128
constexpr int NQKV = 3 * D; // 1536 packed QKV width

// weight plane layout (bf16 hi/lo), per-layer: QKV[512][1536] | O[512][512] | F1[512][2048 interleaved] | F2[1024][512]
constexpr size_t W_QKV  = (size_t)D * NQKV;
constexpr size_t W_O    = (size_t)D * D;
constexpr size_t W_F1   = (size_t)D * (2 * FH);
constexpr size_t W_F2   = (size_t)FH * D;
constexpr size_t OFF_O  = W_QKV;
constexpr size_t OFF_F1 = W_QKV + W_O;
constexpr size_t OFF_F2 = W_QKV + W_O + W_F1;
constexpr size_t W_LSTR = W_QKV + W_O + W_F1 + W_F2;   // 2621440
constexpr size_t W_TOT  = 3 * W_LSTR;

// GEMM smem geometry (bf16 elements), BM=128 BN=128 BK=32, 3 stages
constexpr int A_STRIDE = 40;               // 80B rows -> ldmatrix conflict-free
constexpr int B_STRIDE = 136;              // 272B rows -> ldmatrix.trans conflict-free
constexpr int A_PLANE  = 128 * A_STRIDE;   // 5120 elems
constexpr int B_PLANE  = 32 * B_STRIDE;    // 4352 elems
constexpr uint32_t ST_AL = (uint32_t)A_PLANE * 2;
constexpr uint32_t ST_BH = 2u * A_PLANE * 2;
constexpr uint32_t ST_BL = 2u * A_PLANE * 2 + B_PLANE * 2;
constexpr uint32_t STAGE_BYTES = 2u * (A_PLANE + B_PLANE) * 2; // 37888
constexpr size_t GEMM_SMEM = 3 * (size_t)STAGE_BYTES;          // 113664

constexpr int EPI_PLAIN = 0;
constexpr int EPI_RES   = 1;
constexpr int EPI_REGLU = 2;
}

// ---------------- scratch (device globals; allocation-free) ----------------
__device__ float g_X[(size_t)M * D];            // residual stream (fp32)
__device__ float g_QKV[(size_t)M * NQKV];       // packed Q|K|V (fp32)
__device__ float g_bqkv[L * NQKV];              // packed qkv bias
__device__ uint16_t g_HnH[(size_t)M * D];       // LN out hi/lo bf16 planes
__device__ uint16_t g_HnL[(size_t)M * D];
__device__ uint16_t g_OH[(size_t)M * D];        // attn out planes
__device__ uint16_t g_OL[(size_t)M * D];
__device__ uint16_t g_UH[(size_t)M * FH];       // reglu out planes
__device__ uint16_t g_UL[(size_t)M * FH];
__device__ uint16_t g_WH[W_TOT];                // weight planes
__device__ uint16_t g_WL[W_TOT];
__device__ unsigned char g_mask[L * S * S];

// ---------------- helpers ----------------
__device__ __forceinline__ void split2(float x, float y, uint32_t& hi, uint32_t& lo)
{
    __nv_bfloat162 h = __floats2bfloat162_rn(x, y);
    float hx = __bfloat162float(h.x), hy = __bfloat162float(h.y);
    __nv_bfloat162 l = __floats2bfloat162_rn(x - hx, y - hy);
    hi = *reinterpret_cast<uint32_t*>(&h);
    lo = *reinterpret_cast<uint32_t*>(&l);
}

__device__ __forceinline__ void split1(float x, uint16_t& hi, uint16_t& lo)
{
    __nv_bfloat16 h = __float2bfloat16(x);
    float hf = __bfloat162float(h);
    __nv_bfloat16 l = __float2bfloat16(x - hf);
    hi = *reinterpret_cast<uint16_t*>(&h);
    lo = *reinterpret_cast<uint16_t*>(&l);
}

__device__ __forceinline__ void ldmx4(uint32_t addr, uint32_t& r0, uint32_t& r1,
                                      uint32_t& r2, uint32_t& r3)
{
    asm volatile("ldmatrix.sync.aligned.m8n8.x4.shared.b16 {%0,%1,%2,%3},[%4];"
                 : "=r"(r0), "=r"(r1), "=r"(r2), "=r"(r3) : "r"(addr));
}

__device__ __forceinline__ void ldmx4t(uint32_t addr, uint32_t& r0, uint32_t& r1,
                                       uint32_t& r2, uint32_t& r3)
{
    asm volatile("ldmatrix.sync.aligned.m8n8.x4.trans.shared.b16 {%0,%1,%2,%3},[%4];"
                 : "=r"(r0), "=r"(r1), "=r"(r2), "=r"(r3) : "r"(addr));
}

__device__ __forceinline__ void mma16(float* c, const uint32_t* a, const uint32_t* b)
{
    asm volatile(
        "mma.sync.aligned.m16n8k16.row.col.f32.bf16.bf16.f32 "
        "{%0,%1,%2,%3},{%4,%5,%6,%7},{%8,%9},{%0,%1,%2,%3};\n"
        : "+f"(c[0]), "+f"(c[1]), "+f"(c[2]), "+f"(c[3])
        : "r"(a[0]), "r"(a[1]), "r"(a[2]), "r"(a[3]),
          "r"(b[0]), "r"(b[1]));
}

__device__ __forceinline__ void cpasync16(uint32_t dst, const void* src) {
    asm volatile("cp.async.cg.shared.global [%0], [%1], 16;" :: "r"(dst), "l"(src));
}

// ---------------- mask canonicalization ----------------
__global__ void mask_convert_kernel(const unsigned char* __restrict__ raw)
{
    int i = blockIdx.x * blockDim.x + threadIdx.x;
    if (i >= L * S * S) return;
    bool v;
    if (raw[34] == 1)            v = raw[i] != 0;
    else if (raw[3] == 0x3f)     v = ((const float*)raw)[i] != 0.0f;
    else                         v = ((const int*)raw)[i] != 0;
    g_mask[i] = v ? 1 : 0;
}

// ---------------- qkv bias pack ----------------
__global__ void biaspack_kernel(const float* __restrict__ bq, const float* __restrict__ bk,
                                const float* __restrict__ bv)
{
    int i = blockIdx.x * blockDim.x + threadIdx.x;
    if (i >= L * NQKV) return;
    int l = i / NQKV, c = i % NQKV;
    float v = (c < D) ? bq[l * D + c] : (c < 2 * D) ? bk[l * D + c - D] : bv[l * D + c - 2 * D];
    g_bqkv[i] = v;
}

// ---------------- tokenizer ----------------
__global__ void tokenize_kernel(const float* __restrict__ x_num,
                                const int* __restrict__ x_cat,
                                const float* __restrict__ w_num,
                                const float* __restrict__ b_num,
                                const float* __restrict__ emb_cat,
                                const float* __restrict__ b_cat,
                                const float* __restrict__ cls,
                                const int* __restrict__ cat_offsets)
{
    int idx = blockIdx.x * blockDim.x + threadIdx.x;
    const int total = M * (D / 4);
    if (idx >= total) return;
    int d4 = idx & (D / 4 - 1);
    int ms = idx >> 7;
    int s  = ms % S;
    int b  = ms / S;
    int d  = d4 * 4;
    float4 o;
    if (s < NN) {
        float xv  = x_num[b * NN + s];
        float4 w  = *(const float4*)(w_num + (size_t)s * D + d);
        float4 bb = *(const float4*)(b_num + (size_t)s * D + d);
        o.x = xv * w.x + bb.x;
        o.y = xv * w.y + bb.y;
        o.z = xv * w.z + bb.z;
        o.w = xv * w.w + bb.w;
    } else if (s < NN + NC) {
        int c   = s - NN;
        int row = x_cat[b * NC + c] + cat_offsets[c];
        float4 e  = *(const float4*)(emb_cat + (size_t)row * D + d);
        float4 bb = *(const float4*)(b_cat + (size_t)c * D + d);
        o.x = e.x + bb.x; o.y = e.y + bb.y; o.z = e.z + bb.z; o.w = e.w + bb.w;
    } else {
        o = *(const float4*)(cls + d);
    }
    *(float4*)(g_X + (size_t)ms * D + d) = o;
}

// ---------------- mega weight split: ALL layers, ALL weights, one launch ----------------
__global__ void wsplit_mega_kernel(const float* __restrict__ Wq, const float* __restrict__ Wk,
                                   const float* __restrict__ Wv, const float* __restrict__ Wo,
                                   const float* __restrict__ Wf1, const float* __restrict__ Wf2)
{
    size_t idx = (size_t)blockIdx.x * blockDim.x + threadIdx.x;
    const size_t total = L * W_LSTR / 4;
    if (idx >= total) return;
    size_t d0 = idx * 4;
    int l = (int)(d0 / W_LSTR);
    size_t o = d0 - (size_t)l * W_LSTR;

    float v[4];
    if (o < W_QKV) {
        int k = (int)(o / NQKV);
        int n = (int)(o % NQKV);
        const float* src = (n < D) ? Wq : (n < 2 * D) ? Wk : Wv;
        float4 vv = *(const float4*)(src + ((size_t)l * D + k) * D + (n & (D - 1)));
        v[0] = vv.x; v[1] = vv.y; v[2] = vv.z; v[3] = vv.w;
    } else if (o < OFF_F1) {
        size_t oo = o - OFF_O;
        int k = (int)(oo / D), n = (int)(oo % D);
        float4 vv = *(const float4*)(Wo + ((size_t)l * D + k) * D + n);
        v[0] = vv.x; v[1] = vv.y; v[2] = vv.z; v[3] = vv.w;
    } else if (o < OFF_F2) {
        size_t oo = o - OFF_F1;
        int k = (int)(oo / (2 * FH));
        int c = (int)(oo % (2 * FH));        // quad-aligned, even
        int j = c >> 1;
        const float* row = Wf1 + ((size_t)l * D + k) * (2 * FH);
        v[0] = row[j];          v[1] = row[FH + j];
        v[2] = row[j + 1];      v[3] = row[FH + j + 1];
    } else {
        size_t oo = o - OFF_F2;
        int k = (int)(oo / D), n = (int)(oo % D);
        float4 vv = *(const float4*)(Wf2 + ((size_t)l * FH + k) * D + n);
        v[0] = vv.x; v[1] = vv.y; v[2] = vv.z; v[3] = vv.w;
    }

    uint32_t h0, l0, h1, l1;
    split2(v[0], v[1], h0, l0);
    split2(v[2], v[3], h1, l1);
    *(uint2*)(g_WH + d0) = make_uint2(h0, h1);
    *(uint2*)(g_WL + d0) = make_uint2(l0, l1);
}

// ---------------- LayerNorm (warp per row) -> hi/lo bf16 planes ----------------
__global__ void ln_split_kernel(const float* __restrict__ X,
                                uint16_t* __restrict__ YH, uint16_t* __restrict__ YL,
                                const float* __restrict__ w, const float* __restrict__ bb)
{
    int warp = threadIdx.x >> 5;
    int lane = threadIdx.x & 31;
    int row  = blockIdx.x * 8 + warp;
    const float* xr = X + (size_t)row * D;
    float4 v[4];
    float s = 0.0f, sq = 0.0f;
#pragma unroll
    for (int c = 0; c < 4; ++c) {
        v[c] = *(const float4*)(xr + c * 128 + lane * 4);
        s  += v[c].x + v[c].y + v[c].z + v[c].w;
        sq += v[c].x * v[c].x + v[c].y * v[c].y + v[c].z * v[c].z + v[c].w * v[c].w;
    }
#pragma unroll
    for (int o = 16; o > 0; o >>= 1) {
        s  += __shfl_xor_sync(0xffffffffu, s, o);
        sq += __shfl_xor_sync(0xffffffffu, sq, o);
    }
    float mean = s * (1.0f / D);
    float var  = sq * (1.0f / D) - mean * mean;
    float r = rsqrtf(var + 1e-5f);
#pragma unroll
    for (int c = 0; c < 4; ++c) {
        int col = c * 128 + lane * 4;
        float4 wv = *(const float4*)(w + col);
        float4 bv = *(const float4*)(bb + col);
        float4 o;
        o.x = (v[c].x - mean) * r * wv.x + bv.x;
        o.y = (v[c].y - mean) * r * wv.y + bv.y;
        o.z = (v[c].z - mean) * r * wv.z + bv.z;
        o.w = (v[c].w - mean) * r * wv.w + bv.w;
        uint32_t h0, l0, h1, l1;
        split2(o.x, o.y, h0, l0);
        split2(o.z, o.w, h1, l1);
        size_t off = (size_t)row * D + col;
        *(uint2*)(YH + off) = make_uint2(h0, h1);
        *(uint2*)(YL + off) = make_uint2(l0, l1);
    }
}

// ---------------- split-bf16 3-term tensor-core GEMM, 3-stage cp.async ----------------
// Inner loop is TERM-MAJOR: per b-fragment pair, issue 8 independent mmas per term
// (acc reuse distance 8) instead of 3 chained mmas per acc. Per-accumulator
// addition order is unchanged (albh, ahbl, ahbh per k-step) -> bit-identical.
template <int EPI>
__global__ void __launch_bounds__(256, 2)
gemm_kernel(const uint16_t* __restrict__ AH, const uint16_t* __restrict__ AL,
            const uint16_t* __restrict__ BH, const uint16_t* __restrict__ BL,
            const float* __restrict__ bias, const float* __restrict__ Rsd,
            float* __restrict__ C, uint16_t* __restrict__ UH, uint16_t* __restrict__ UL,
            int K, int N)
{
    extern __shared__ uint16_t sm[];
    const uint32_t shBase = (uint32_t)__cvta_generic_to_shared(sm);

    const int tid  = threadIdx.x;
    const int lane = tid & 31;
    const int warp = tid >> 5;
    const int wm   = (warp & 1) * 64;
    const int wn   = (warp >> 1) * 32;
    const int grp  = lane >> 2;
    const int t4   = lane & 3;

    const int bm = blockIdx.x;
    const int bn = blockIdx.y;
    const int KT = K >> 5;

    float acc[4][4][4];
#pragma unroll
    for (int i = 0; i < 4; ++i)
#pragma unroll
        for (int j = 0; j < 4; ++j)
#pragma unroll
            for (int r = 0; r < 4; ++r) acc[i][j][r] = 0.0f;

    const int agr = tid >> 1;
    const int aco = (tid & 1) * 32;
    const int bgr = tid >> 3;
    const int bco = (tid & 7) * 32;

    auto load_tile = [&](int kt, int st) {
        const uint32_t sb = shBase + (uint32_t)st * STAGE_BYTES;
        {
            uint32_t doff = sb + (uint32_t)(agr * A_STRIDE) * 2 + aco;
            const uint16_t* sH = AH + (size_t)(bm * 128 + agr) * K + kt * 32 + (aco >> 1);
            const uint16_t* sL = AL + (size_t)(bm * 128 + agr) * K + kt * 32 + (aco >> 1);
            cpasync16(doff,               sH);
            cpasync16(doff + 16,          sH + 8);
            cpasync16(doff + ST_AL,       sL);
            cpasync16(doff + ST_AL + 16,  sL + 8);
        }
        {
            uint32_t doff = sb + ST_BH + (uint32_t)(bgr * B_STRIDE) * 2 + bco;
            const uint16_t* sH = BH + (size_t)(kt * 32 + bgr) * N + bn * 128 + (bco >> 1);
            const uint16_t* sL = BL + (size_t)(kt * 32 + bgr) * N + bn * 128 + (bco >> 1);
            cpasync16(doff,                         sH);
            cpasync16(doff + 16,                    sH + 8);
            cpasync16(doff + (ST_BL - ST_BH),       sL);
            cpasync16(doff + (ST_BL - ST_BH) + 16,  sL + 8);
        }
        asm volatile("cp.async.commit_group;" ::: "memory");
    };

    const int arowL = lane & 15;
    const int kofA  = (lane >> 4) * 8;
    const uint32_t aBase = shBase + (uint32_t)(((wm + arowL) * A_STRIDE + kofA) * 2);
    const int krowL = lane & 15;
    const int nofB  = (lane >> 4) * 8;
    const uint32_t bBase = shBase + ST_BH + (uint32_t)((krowL * B_STRIDE + wn + nofB) * 2);

    load_tile(0, 0);
    load_tile(1, 1);

    for (int kt = 0; kt < KT; ++kt) {
        const int st = kt % 3;
        if (kt + 1 < KT) asm volatile("cp.async.wait_group 1;" ::: "memory");
        else             asm volatile("cp.async.wait_group 0;" ::: "memory");
        __syncthreads();
        if (kt + 2 < KT) load_tile(kt + 2, (kt + 2) % 3);

        const uint32_t aSt = aBase + (uint32_t)st * STAGE_BYTES;
        const uint32_t bSt = bBase + (uint32_t)st * STAGE_BYTES;
#pragma unroll
        for (int ks = 0; ks < 2; ++ks) {
            uint32_t ah[4][4], al[4][4];
#pragma unroll
            for (int mi = 0; mi < 4; ++mi) {
                uint32_t ad = aSt + mi * (16 * A_STRIDE * 2) + ks * 32;
                ldmx4(ad, ah[mi][0], ah[mi][1], ah[mi][2], ah[mi][3]);
                ldmx4(ad + ST_AL, al[mi][0], al[mi][1], al[mi][2], al[mi][3]);
            }
#pragma unroll
            for (int pr = 0; pr < 2; ++pr) {
                uint32_t bh[2][2], bl[2][2];
                uint32_t bd = bSt + pr * 32 + ks * (16 * B_STRIDE * 2);
                ldmx4t(bd, bh[0][0], bh[0][1], bh[1][0], bh[1][1]);
                ldmx4t(bd + (ST_BL - ST_BH), bl[0][0], bl[0][1], bl[1][0], bl[1][1]);
                // term-major: 8 independent mmas per term, acc reuse distance 8
#pragma unroll
                for (int mi = 0; mi < 4; ++mi)
#pragma unroll
                    for (int nj = 0; nj < 2; ++nj)
                        mma16(acc[mi][2 * pr + nj], al[mi], bh[nj]);
#pragma unroll
                for (int mi = 0; mi < 4; ++mi)
#pragma unroll
                    for (int nj = 0; nj < 2; ++nj)
                        mma16(acc[mi][2 * pr + nj], ah[mi], bl[nj]);
#pragma unroll
                for (int mi = 0; mi < 4; ++mi)
#pragma unroll
                    for (int nj = 0; nj < 2; ++nj)
                        mma16(acc[mi][2 * pr + nj], ah[mi], bh[nj]);
            }
        }
    }

    // epilogue
#pragma unroll
    for (int mi = 0; mi < 4; ++mi) {
        int r0 = bm * 128 + wm + mi * 16 + grp;
#pragma unroll
        for (int ni = 0; ni < 4; ++ni) {
            int c0 = bn * 128 + wn + ni * 8 + 2 * t4;
            if (EPI == EPI_REGLU) {
                int j = c0 >> 1;
                float ba = bias[j], bg = bias[FH + j];
                float u0 = (acc[mi][ni][0] + ba) * fmaxf(acc[mi][ni][1] + bg, 0.0f);
                float u1 = (acc[mi][ni][2] + ba) * fmaxf(acc[mi][ni][3] + bg, 0.0f);
                uint16_t h, l;
                split1(u0, h, l);
                UH[(size_t)r0 * FH + j] = h;
                UL[(size_t)r0 * FH + j] = l;
                split1(u1, h, l);
                UH[(size_t)(r0 + 8) * FH + j] = h;
                UL[(size_t)(r0 + 8) * FH + j] = l;
            } else {
                float b0 = bias[c0], b1 = bias[c0 + 1];
                float2 o0 = make_float2(acc[mi][ni][0] + b0, acc[mi][ni][1] + b1);
                float2 o1 = make_float2(acc[mi][ni][2] + b0, acc[mi][ni][3] + b1);
                if (EPI == EPI_RES) {
                    float2 rv0 = *(const float2*)(Rsd + (size_t)r0 * N + c0);
                    float2 rv1 = *(const float2*)(Rsd + (size_t)(r0 + 8) * N + c0);
                    o0.x += rv0.x; o0.y += rv0.y;
                    o1.x += rv1.x; o1.y += rv1.y;
                }
                *(float2*)(C + (size_t)r0 * N + c0)       = o0;
                *(float2*)(C + (size_t)(r0 + 8) * N + c0) = o1;
            }
        }
    }
}

// ---------------- attention (one block per (batch, head); packed QKV) ----------------
__global__ void attn_kernel(const float* __restrict__ QKV,
                            const unsigned char* __restrict__ mask,
                            uint16_t* __restrict__ OH, uint16_t* __restrict__ OL)
{
    int bh = blockIdx.x;
    int h  = bh % NH;
    int b  = bh / NH;
    int t  = threadIdx.x;   // 256

    __shared__ float qs[S][DH + 1];
    __shared__ float ks[S][DH + 1];
    __shared__ float vs[S][DH + 1];
    __shared__ float sc[S][S + 3];

    const size_t rbase = (size_t)(b * S) * NQKV + h * DH;
    for (int i = t; i < S * DH; i += 256) {
        int s = i / DH, d = i % DH;
        size_t p = rbase + (size_t)s * NQKV + d;
        qs[s][d] = QKV[p];
        ks[s][d] = QKV[p + D];
        vs[s][d] = QKV[p + 2 * D];
    }
    __syncthreads();

    const float scale = 0.125f;  // 1/sqrt(64)
    for (int p = t; p < S * S; p += 256) {
        int i = p / S, j = p % S;
        float s = 0.0f;
#pragma unroll 16
        for (int d = 0; d < DH; ++d) s += qs[i][d] * ks[j][d];
        s *= scale;
        if (!mask[i * S + j]) s = -1e9f;
        sc[i][j] = s;
    }
    __syncthreads();

    if (t < S) {
        float mx = -1e30f;
        for (int j = 0; j < S; ++j) mx = fmaxf(mx, sc[t][j]);
        float sum = 0.0f;
        for (int j = 0; j < S; ++j) { float e = __expf(sc[t][j] - mx); sc[t][j] = e; sum += e; }
        float inv = 1.0f / sum;
        for (int j = 0; j < S; ++j) sc[t][j] *= inv;
    }
    __syncthreads();

    const size_t obase = (size_t)(b * S) * D + h * DH;
    for (int p = t; p < S * (DH / 2); p += 256) {
        int i  = p / (DH / 2);
        int dd = (p % (DH / 2)) * 2;
        float o0 = 0.0f, o1 = 0.0f;
#pragma unroll
        for (int j = 0; j < S; ++j) {
            float a = sc[i][j];
            o0 += a * vs[j][dd];
            o1 += a * vs[j][dd + 1];
        }
        uint32_t hi, lo;
        split2(o0, o1, hi, lo);
        size_t off = obase + (size_t)i * D + dd;
        *(uint32_t*)(OH + off) = hi;
        *(uint32_t*)(OL + off) = lo;
    }
}

// ---------------- head: LN(cls) -> relu -> dot Wh + bh ----------------
__global__ void head_kernel(const float* __restrict__ X,
                            const float* __restrict__ hw, const float* __restrict__ hb,
                            const float* __restrict__ Wh, const float* __restrict__ bh,
                            float* __restrict__ out)
{
    int b = blockIdx.x;
    int t = threadIdx.x;   // 128
    const float* xr = X + ((size_t)b * S + (S - 1)) * D;
    float4 v = *(const float4*)(xr + t * 4);
    float s  = v.x + v.y + v.z + v.w;
    float sq = v.x * v.x + v.y * v.y + v.z * v.z + v.w * v.w;
#pragma unroll
    for (int o = 16; o > 0; o >>= 1) {
        s  += __shfl_xor_sync(0xffffffffu, s, o);
        sq += __shfl_xor_sync(0xffffffffu, sq, o);
    }
    __shared__ float ss[4], sqs[4], ds[4];
    if ((t & 31) == 0) { ss[t >> 5] = s; sqs[t >> 5] = sq; }
    __syncthreads();
    s  = ss[0] + ss[1] + ss[2] + ss[3];
    sq = sqs[0] + sqs[1] + sqs[2] + sqs[3];
    float mean = s * (1.0f / D);
    float var  = sq * (1.0f / D) - mean * mean;
    float r = rsqrtf(var + 1e-5f);
    float4 wv = *(const float4*)(hw + t * 4);
    float4 bv = *(const float4*)(hb + t * 4);
    float4 wh = *(const float4*)(Wh + t * 4);   // DOUT == 1
    float dot = 0.0f;
    dot += fmaxf((v.x - mean) * r * wv.x + bv.x, 0.0f) * wh.x;
    dot += fmaxf((v.y - mean) * r * wv.y + bv.y, 0.0f) * wh.y;
    dot += fmaxf((v.z - mean) * r * wv.z + bv.z, 0.0f) * wh.z;
    dot += fmaxf((v.w - mean) * r * wv.w + bv.w, 0.0f) * wh.w;
#pragma unroll
    for (int o = 16; o > 0; o >>= 1) dot += __shfl_xor_sync(0xffffffffu, dot, o);
    if ((t & 31) == 0) ds[t >> 5] = dot;
    __syncthreads();
    if (t == 0) out[b] = ds[0] + ds[1] + ds[2] + ds[3] + bh[0];
}

// ---------------- launcher ----------------
extern "C" void kernel_launch(void* const* d_in, const int* in_sizes, int n_in,
                              void* d_out, int out_size)
{
    (void)in_sizes; (void)n_in; (void)out_size;
    const float* x_num    = (const float*)d_in[0];
    const int*   x_cat    = (const int*)d_in[1];
    const float* w_num    = (const float*)d_in[2];
    const float* b_num    = (const float*)d_in[3];
    const float* emb_cat  = (const float*)d_in[4];
    const float* b_cat    = (const float*)d_in[5];
    const float* cls      = (const float*)d_in[6];
    const float* ln1_w    = (const float*)d_in[7];
    const float* ln1_b    = (const float*)d_in[8];
    const float* Wq       = (const float*)d_in[9];
    const float* bq       = (const float*)d_in[10];
    const float* Wk       = (const float*)d_in[11];
    const float* bk       = (const float*)d_in[12];
    const float* Wv       = (const float*)d_in[13];
    const float* bv       = (const float*)d_in[14];
    const float* Wo       = (const float*)d_in[15];
    const float* bo       = (const float*)d_in[16];
    const float* ln2_w    = (const float*)d_in[17];
    const float* ln2_b    = (const float*)d_in[18];
    const float* Wf1      = (const float*)d_in[19];
    const float* bf1      = (const float*)d_in[20];
    const float* Wf2      = (const float*)d_in[21];
    const float* bf2      = (const float*)d_in[22];
    const unsigned char* mask_raw = (const unsigned char*)d_in[23];
    const int*   cat_offsets  = (const int*)d_in[24];
    const float* hln_w    = (const float*)d_in[25];
    const float* hln_b    = (const float*)d_in[26];
    const float* Wh       = (const float*)d_in[27];
    const float* bh       = (const float*)d_in[28];
    float* out = (float*)d_out;

    float *X, *QKV, *BQKV;
    uint16_t *HnH, *HnL, *OH, *OL, *UH, *UL, *WHp, *WLp;
    unsigned char* Mk;
    cudaGetSymbolAddress((void**)&X,    g_X);
    cudaGetSymbolAddress((void**)&QKV,  g_QKV);
    cudaGetSymbolAddress((void**)&BQKV, g_bqkv);
    cudaGetSymbolAddress((void**)&HnH,  g_HnH);
    cudaGetSymbolAddress((void**)&HnL,  g_HnL);
    cudaGetSymbolAddress((void**)&OH,   g_OH);
    cudaGetSymbolAddress((void**)&OL,   g_OL);
    cudaGetSymbolAddress((void**)&UH,   g_UH);
    cudaGetSymbolAddress((void**)&UL,   g_UL);
    cudaGetSymbolAddress((void**)&WHp,  g_WH);
    cudaGetSymbolAddress((void**)&WLp,  g_WL);
    cudaGetSymbolAddress((void**)&Mk,   g_mask);

    cudaFuncSetAttribute(gemm_kernel<EPI_PLAIN>,
                         cudaFuncAttributeMaxDynamicSharedMemorySize, (int)GEMM_SMEM);
    cudaFuncSetAttribute(gemm_kernel<EPI_RES>,
                         cudaFuncAttributeMaxDynamicSharedMemorySize, (int)GEMM_SMEM);
    cudaFuncSetAttribute(gemm_kernel<EPI_REGLU>,
                         cudaFuncAttributeMaxDynamicSharedMemorySize, (int)GEMM_SMEM);

    mask_convert_kernel<<<(L * S * S + 255) / 256, 256>>>(mask_raw);
    biaspack_kernel<<<(L * NQKV + 255) / 256, 256>>>(bq, bk, bv);
    tokenize_kernel<<<(M * (D / 4) + 255) / 256, 256>>>(
        x_num, x_cat, w_num, b_num, emb_cat, b_cat, cls, cat_offsets);
    {
        size_t total = L * W_LSTR / 4;
        wsplit_mega_kernel<<<(unsigned)((total + 255) / 256), 256>>>(
            Wq, Wk, Wv, Wo, Wf1, Wf2);
    }

    const dim3 gQKV(M / 128, NQKV / 128);       // N = 1536
    const dim3 g512(M / 128, D / 128);          // N = 512
    const dim3 g2048(M / 128, (2 * FH) / 128);  // N = 2048 (interleaved a/g)

    for (int l = 0; l < L; ++l) {
        size_t lo = (size_t)l * W_LSTR;
        ln_split_kernel<<<M / 8, 256>>>(X, HnH, HnL, ln1_w + (size_t)l * D, ln1_b + (size_t)l * D);

        gemm_kernel<EPI_PLAIN><<<gQKV, 256, GEMM_SMEM>>>(HnH, HnL, WHp + lo, WLp + lo,
            BQKV + l * NQKV, nullptr, QKV, nullptr, nullptr, D, NQKV);

        attn_kernel<<<B * NH, 256>>>(QKV, Mk + (size_t)l * S * S, OH, OL);

        gemm_kernel<EPI_RES><<<g512, 256, GEMM_SMEM>>>(OH, OL, WHp + lo + OFF_O, WLp + lo + OFF_O,
            bo + (size_t)l * D, X, X, nullptr, nullptr, D, D);

        ln_split_kernel<<<M / 8, 256>>>(X, HnH, HnL, ln2_w + (size_t)l * D, ln2_b + (size_t)l * D);

        gemm_kernel<EPI_REGLU><<<g2048, 256, GEMM_SMEM>>>(HnH, HnL, WHp + lo + OFF_F1, WLp + lo + OFF_F1,
            bf1 + (size_t)l * 2 * FH, nullptr, nullptr, UH, UL, D, 2 * FH);

        gemm_kernel<EPI_RES><<<g512, 256, GEMM_SMEM>>>(UH, UL, WHp + lo + OFF_F2, WLp + lo + OFF_F2,
            bf2 + (size_t)l * D, X, X, nullptr, nullptr, FH, D);
    }

    head_kernel<<<B, 128>>>(X, hln_w, hln_b, Wh, bh, out);
}

// round 11
// speedup vs baseline: 2.0390x; 1.1183x over previous
#include <cuda_runtime.h>
#include <cuda_bf16.h>
#include <cstdint>

// ---------------- problem constants ----------------
namespace {
constexpr int B   = 2048;
constexpr int NN  = 24;
constexpr int NC  = 8;
constexpr int D   = 512;
constexpr int NH  = 8;     // heads
constexpr int L   = 3;
constexpr int FH  = 1024;
constexpr int S   = 33;    // NN + NC + 1
constexpr int DH  = 64;    // D / NH
constexpr int M   = B * S; // 67584 rows; divisible by 128
constexpr int NQKV = 3 * D; // 1536 packed QKV width

// weight plane layout (bf16 hi/lo), per-layer: QKV[512][1536] | O[512][512] | F1[512][2048 interleaved] | F2[1024][512]
constexpr size_t W_QKV  = (size_t)D * NQKV;
constexpr size_t W_O    = (size_t)D * D;
constexpr size_t W_F1   = (size_t)D * (2 * FH);
constexpr size_t W_F2   = (size_t)FH * D;
constexpr size_t OFF_O  = W_QKV;
constexpr size_t OFF_F1 = W_QKV + W_O;
constexpr size_t OFF_F2 = W_QKV + W_O + W_F1;
constexpr size_t W_LSTR = W_QKV + W_O + W_F1 + W_F2;   // 2621440
constexpr size_t W_TOT  = 3 * W_LSTR;

// GEMM smem geometry (bf16 elements), BM=128 BN=128 BK=32, 3 stages
constexpr int A_STRIDE = 40;               // 80B rows -> ldmatrix conflict-free
constexpr int B_STRIDE = 136;              // 272B rows -> ldmatrix.trans conflict-free
constexpr int A_PLANE  = 128 * A_STRIDE;   // 5120 elems
constexpr int B_PLANE  = 32 * B_STRIDE;    // 4352 elems
constexpr uint32_t ST_AL = (uint32_t)A_PLANE * 2;
constexpr uint32_t ST_BH = 2u * A_PLANE * 2;
constexpr uint32_t ST_BL = 2u * A_PLANE * 2 + B_PLANE * 2;
constexpr uint32_t STAGE_BYTES = 2u * (A_PLANE + B_PLANE) * 2; // 37888
constexpr size_t GEMM_SMEM = 3 * (size_t)STAGE_BYTES;          // 113664

constexpr int EPI_PLAIN = 0;
constexpr int EPI_RES   = 1;
constexpr int EPI_REGLU = 2;
}

// ---------------- scratch (device globals; allocation-free) ----------------
__device__ float g_X[(size_t)M * D];            // residual stream (fp32)
__device__ float g_QKV[(size_t)M * NQKV];       // packed Q|K|V (fp32)
__device__ float g_bqkv[L * NQKV];              // packed qkv bias
__device__ uint16_t g_HnH[(size_t)M * D];       // LN out hi/lo bf16 planes
__device__ uint16_t g_HnL[(size_t)M * D];
__device__ uint16_t g_OH[(size_t)M * D];        // attn out planes
__device__ uint16_t g_OL[(size_t)M * D];
__device__ uint16_t g_UH[(size_t)M * FH];       // reglu out planes
__device__ uint16_t g_UL[(size_t)M * FH];
__device__ uint16_t g_WH[W_TOT];                // weight planes
__device__ uint16_t g_WL[W_TOT];
__device__ unsigned char g_mask[L * S * S];
// sparse-mask CSR (per layer)
__device__ int g_cnt[L * S];
__device__ int g_rs[L * S];
__device__ unsigned char g_fi[L * S * S];
__device__ unsigned char g_fj[L * S * S];
__device__ int g_T[L];

// ---------------- helpers ----------------
__device__ __forceinline__ void split2(float x, float y, uint32_t& hi, uint32_t& lo)
{
    __nv_bfloat162 h = __floats2bfloat162_rn(x, y);
    float hx = __bfloat162float(h.x), hy = __bfloat162float(h.y);
    __nv_bfloat162 l = __floats2bfloat162_rn(x - hx, y - hy);
    hi = *reinterpret_cast<uint32_t*>(&h);
    lo = *reinterpret_cast<uint32_t*>(&l);
}

__device__ __forceinline__ void split1(float x, uint16_t& hi, uint16_t& lo)
{
    __nv_bfloat16 h = __float2bfloat16(x);
    float hf = __bfloat162float(h);
    __nv_bfloat16 l = __float2bfloat16(x - hf);
    hi = *reinterpret_cast<uint16_t*>(&h);
    lo = *reinterpret_cast<uint16_t*>(&l);
}

__device__ __forceinline__ void ldmx4(uint32_t addr, uint32_t& r0, uint32_t& r1,
                                      uint32_t& r2, uint32_t& r3)
{
    asm volatile("ldmatrix.sync.aligned.m8n8.x4.shared.b16 {%0,%1,%2,%3},[%4];"
                 : "=r"(r0), "=r"(r1), "=r"(r2), "=r"(r3) : "r"(addr));
}

__device__ __forceinline__ void ldmx4t(uint32_t addr, uint32_t& r0, uint32_t& r1,
                                       uint32_t& r2, uint32_t& r3)
{
    asm volatile("ldmatrix.sync.aligned.m8n8.x4.trans.shared.b16 {%0,%1,%2,%3},[%4];"
                 : "=r"(r0), "=r"(r1), "=r"(r2), "=r"(r3) : "r"(addr));
}

__device__ __forceinline__ void mma16(float* c, const uint32_t* a, const uint32_t* b)
{
    asm volatile(
        "mma.sync.aligned.m16n8k16.row.col.f32.bf16.bf16.f32 "
        "{%0,%1,%2,%3},{%4,%5,%6,%7},{%8,%9},{%0,%1,%2,%3};\n"
        : "+f"(c[0]), "+f"(c[1]), "+f"(c[2]), "+f"(c[3])
        : "r"(a[0]), "r"(a[1]), "r"(a[2]), "r"(a[3]),
          "r"(b[0]), "r"(b[1]));
}

__device__ __forceinline__ void cpasync16(uint32_t dst, const void* src) {
    asm volatile("cp.async.cg.shared.global [%0], [%1], 16;" :: "r"(dst), "l"(src));
}

// ---------------- mask canonicalization ----------------
__global__ void mask_convert_kernel(const unsigned char* __restrict__ raw)
{
    int i = blockIdx.x * blockDim.x + threadIdx.x;
    if (i >= L * S * S) return;
    bool v;
    if (raw[34] == 1)            v = raw[i] != 0;
    else if (raw[3] == 0x3f)     v = ((const float*)raw)[i] != 0.0f;
    else                         v = ((const int*)raw)[i] != 0;
    g_mask[i] = v ? 1 : 0;
}

// ---------------- CSR build (per layer; ascending j preserves fp order) ----------------
__global__ void csr_build_kernel()
{
    int l = threadIdx.x;
    if (l >= L) return;
    const unsigned char* m = g_mask + l * S * S;
    int pos = 0;
    for (int i = 0; i < S; ++i) {
        g_rs[l * S + i] = pos;
        int c = 0;
        for (int j = 0; j < S; ++j) {
            if (m[i * S + j]) {
                g_fi[l * S * S + pos] = (unsigned char)i;
                g_fj[l * S * S + pos] = (unsigned char)j;
                ++pos; ++c;
            }
        }
        g_cnt[l * S + i] = c;
    }
    g_T[l] = pos;
}

// ---------------- qkv bias pack ----------------
__global__ void biaspack_kernel(const float* __restrict__ bq, const float* __restrict__ bk,
                                const float* __restrict__ bv)
{
    int i = blockIdx.x * blockDim.x + threadIdx.x;
    if (i >= L * NQKV) return;
    int l = i / NQKV, c = i % NQKV;
    float v = (c < D) ? bq[l * D + c] : (c < 2 * D) ? bk[l * D + c - D] : bv[l * D + c - 2 * D];
    g_bqkv[i] = v;
}

// ---------------- tokenizer ----------------
__global__ void tokenize_kernel(const float* __restrict__ x_num,
                                const int* __restrict__ x_cat,
                                const float* __restrict__ w_num,
                                const float* __restrict__ b_num,
                                const float* __restrict__ emb_cat,
                                const float* __restrict__ b_cat,
                                const float* __restrict__ cls,
                                const int* __restrict__ cat_offsets)
{
    int idx = blockIdx.x * blockDim.x + threadIdx.x;
    const int total = M * (D / 4);
    if (idx >= total) return;
    int d4 = idx & (D / 4 - 1);
    int ms = idx >> 7;
    int s  = ms % S;
    int b  = ms / S;
    int d  = d4 * 4;
    float4 o;
    if (s < NN) {
        float xv  = x_num[b * NN + s];
        float4 w  = *(const float4*)(w_num + (size_t)s * D + d);
        float4 bb = *(const float4*)(b_num + (size_t)s * D + d);
        o.x = xv * w.x + bb.x;
        o.y = xv * w.y + bb.y;
        o.z = xv * w.z + bb.z;
        o.w = xv * w.w + bb.w;
    } else if (s < NN + NC) {
        int c   = s - NN;
        int row = x_cat[b * NC + c] + cat_offsets[c];
        float4 e  = *(const float4*)(emb_cat + (size_t)row * D + d);
        float4 bb = *(const float4*)(b_cat + (size_t)c * D + d);
        o.x = e.x + bb.x; o.y = e.y + bb.y; o.z = e.z + bb.z; o.w = e.w + bb.w;
    } else {
        o = *(const float4*)(cls + d);
    }
    *(float4*)(g_X + (size_t)ms * D + d) = o;
}

// ---------------- mega weight split: ALL layers, ALL weights, one launch ----------------
__global__ void wsplit_mega_kernel(const float* __restrict__ Wq, const float* __restrict__ Wk,
                                   const float* __restrict__ Wv, const float* __restrict__ Wo,
                                   const float* __restrict__ Wf1, const float* __restrict__ Wf2)
{
    size_t idx = (size_t)blockIdx.x * blockDim.x + threadIdx.x;
    const size_t total = L * W_LSTR / 4;
    if (idx >= total) return;
    size_t d0 = idx * 4;
    int l = (int)(d0 / W_LSTR);
    size_t o = d0 - (size_t)l * W_LSTR;

    float v[4];
    if (o < W_QKV) {
        int k = (int)(o / NQKV);
        int n = (int)(o % NQKV);
        const float* src = (n < D) ? Wq : (n < 2 * D) ? Wk : Wv;
        float4 vv = *(const float4*)(src + ((size_t)l * D + k) * D + (n & (D - 1)));
        v[0] = vv.x; v[1] = vv.y; v[2] = vv.z; v[3] = vv.w;
    } else if (o < OFF_F1) {
        size_t oo = o - OFF_O;
        int k = (int)(oo / D), n = (int)(oo % D);
        float4 vv = *(const float4*)(Wo + ((size_t)l * D + k) * D + n);
        v[0] = vv.x; v[1] = vv.y; v[2] = vv.z; v[3] = vv.w;
    } else if (o < OFF_F2) {
        size_t oo = o - OFF_F1;
        int k = (int)(oo / (2 * FH));
        int c = (int)(oo % (2 * FH));        // quad-aligned, even
        int j = c >> 1;
        const float* row = Wf1 + ((size_t)l * D + k) * (2 * FH);
        v[0] = row[j];          v[1] = row[FH + j];
        v[2] = row[j + 1];      v[3] = row[FH + j + 1];
    } else {
        size_t oo = o - OFF_F2;
        int k = (int)(oo / D), n = (int)(oo % D);
        float4 vv = *(const float4*)(Wf2 + ((size_t)l * FH + k) * D + n);
        v[0] = vv.x; v[1] = vv.y; v[2] = vv.z; v[3] = vv.w;
    }

    uint32_t h0, l0, h1, l1;
    split2(v[0], v[1], h0, l0);
    split2(v[2], v[3], h1, l1);
    *(uint2*)(g_WH + d0) = make_uint2(h0, h1);
    *(uint2*)(g_WL + d0) = make_uint2(l0, l1);
}

// ---------------- LayerNorm (warp per row) -> hi/lo bf16 planes ----------------
__global__ void ln_split_kernel(const float* __restrict__ X,
                                uint16_t* __restrict__ YH, uint16_t* __restrict__ YL,
                                const float* __restrict__ w, const float* __restrict__ bb)
{
    int warp = threadIdx.x >> 5;
    int lane = threadIdx.x & 31;
    int row  = blockIdx.x * 8 + warp;
    const float* xr = X + (size_t)row * D;
    float4 v[4];
    float s = 0.0f, sq = 0.0f;
#pragma unroll
    for (int c = 0; c < 4; ++c) {
        v[c] = *(const float4*)(xr + c * 128 + lane * 4);
        s  += v[c].x + v[c].y + v[c].z + v[c].w;
        sq += v[c].x * v[c].x + v[c].y * v[c].y + v[c].z * v[c].z + v[c].w * v[c].w;
    }
#pragma unroll
    for (int o = 16; o > 0; o >>= 1) {
        s  += __shfl_xor_sync(0xffffffffu, s, o);
        sq += __shfl_xor_sync(0xffffffffu, sq, o);
    }
    float mean = s * (1.0f / D);
    float var  = sq * (1.0f / D) - mean * mean;
    float r = rsqrtf(var + 1e-5f);
#pragma unroll
    for (int c = 0; c < 4; ++c) {
        int col = c * 128 + lane * 4;
        float4 wv = *(const float4*)(w + col);
        float4 bv = *(const float4*)(bb + col);
        float4 o;
        o.x = (v[c].x - mean) * r * wv.x + bv.x;
        o.y = (v[c].y - mean) * r * wv.y + bv.y;
        o.z = (v[c].z - mean) * r * wv.z + bv.z;
        o.w = (v[c].w - mean) * r * wv.w + bv.w;
        uint32_t h0, l0, h1, l1;
        split2(o.x, o.y, h0, l0);
        split2(o.z, o.w, h1, l1);
        size_t off = (size_t)row * D + col;
        *(uint2*)(YH + off) = make_uint2(h0, h1);
        *(uint2*)(YL + off) = make_uint2(l0, l1);
    }
}

// ---------------- split-bf16 3-term tensor-core GEMM, 3-stage cp.async ----------------
template <int EPI>
__global__ void __launch_bounds__(256, 2)
gemm_kernel(const uint16_t* __restrict__ AH, const uint16_t* __restrict__ AL,
            const uint16_t* __restrict__ BH, const uint16_t* __restrict__ BL,
            const float* __restrict__ bias, const float* __restrict__ Rsd,
            float* __restrict__ C, uint16_t* __restrict__ UH, uint16_t* __restrict__ UL,
            int K, int N)
{
    extern __shared__ uint16_t sm[];
    const uint32_t shBase = (uint32_t)__cvta_generic_to_shared(sm);

    const int tid  = threadIdx.x;
    const int lane = tid & 31;
    const int warp = tid >> 5;
    const int wm   = (warp & 1) * 64;
    const int wn   = (warp >> 1) * 32;
    const int grp  = lane >> 2;
    const int t4   = lane & 3;

    const int bm = blockIdx.x;
    const int bn = blockIdx.y;
    const int KT = K >> 5;

    float acc[4][4][4];
#pragma unroll
    for (int i = 0; i < 4; ++i)
#pragma unroll
        for (int j = 0; j < 4; ++j)
#pragma unroll
            for (int r = 0; r < 4; ++r) acc[i][j][r] = 0.0f;

    const int agr = tid >> 1;
    const int aco = (tid & 1) * 32;
    const int bgr = tid >> 3;
    const int bco = (tid & 7) * 32;

    auto load_tile = [&](int kt, int st) {
        const uint32_t sb = shBase + (uint32_t)st * STAGE_BYTES;
        {
            uint32_t doff = sb + (uint32_t)(agr * A_STRIDE) * 2 + aco;
            const uint16_t* sH = AH + (size_t)(bm * 128 + agr) * K + kt * 32 + (aco >> 1);
            const uint16_t* sL = AL + (size_t)(bm * 128 + agr) * K + kt * 32 + (aco >> 1);
            cpasync16(doff,               sH);
            cpasync16(doff + 16,          sH + 8);
            cpasync16(doff + ST_AL,       sL);
            cpasync16(doff + ST_AL + 16,  sL + 8);
        }
        {
            uint32_t doff = sb + ST_BH + (uint32_t)(bgr * B_STRIDE) * 2 + bco;
            const uint16_t* sH = BH + (size_t)(kt * 32 + bgr) * N + bn * 128 + (bco >> 1);
            const uint16_t* sL = BL + (size_t)(kt * 32 + bgr) * N + bn * 128 + (bco >> 1);
            cpasync16(doff,                         sH);
            cpasync16(doff + 16,                    sH + 8);
            cpasync16(doff + (ST_BL - ST_BH),       sL);
            cpasync16(doff + (ST_BL - ST_BH) + 16,  sL + 8);
        }
        asm volatile("cp.async.commit_group;" ::: "memory");
    };

    const int arowL = lane & 15;
    const int kofA  = (lane >> 4) * 8;
    const uint32_t aBase = shBase + (uint32_t)(((wm + arowL) * A_STRIDE + kofA) * 2);
    const int krowL = lane & 15;
    const int nofB  = (lane >> 4) * 8;
    const uint32_t bBase = shBase + ST_BH + (uint32_t)((krowL * B_STRIDE + wn + nofB) * 2);

    load_tile(0, 0);
    load_tile(1, 1);

    for (int kt = 0; kt < KT; ++kt) {
        const int st = kt % 3;
        if (kt + 1 < KT) asm volatile("cp.async.wait_group 1;" ::: "memory");
        else             asm volatile("cp.async.wait_group 0;" ::: "memory");
        __syncthreads();
        if (kt + 2 < KT) load_tile(kt + 2, (kt + 2) % 3);

        const uint32_t aSt = aBase + (uint32_t)st * STAGE_BYTES;
        const uint32_t bSt = bBase + (uint32_t)st * STAGE_BYTES;
#pragma unroll
        for (int ks = 0; ks < 2; ++ks) {
            uint32_t ah[4][4], al[4][4];
#pragma unroll
            for (int mi = 0; mi < 4; ++mi) {
                uint32_t ad = aSt + mi * (16 * A_STRIDE * 2) + ks * 32;
                ldmx4(ad, ah[mi][0], ah[mi][1], ah[mi][2], ah[mi][3]);
                ldmx4(ad + ST_AL, al[mi][0], al[mi][1], al[mi][2], al[mi][3]);
            }
#pragma unroll
            for (int pr = 0; pr < 2; ++pr) {
                uint32_t bh[2][2], bl[2][2];
                uint32_t bd = bSt + pr * 32 + ks * (16 * B_STRIDE * 2);
                ldmx4t(bd, bh[0][0], bh[0][1], bh[1][0], bh[1][1]);
                ldmx4t(bd + (ST_BL - ST_BH), bl[0][0], bl[0][1], bl[1][0], bl[1][1]);
#pragma unroll
                for (int mi = 0; mi < 4; ++mi)
#pragma unroll
                    for (int nj = 0; nj < 2; ++nj)
                        mma16(acc[mi][2 * pr + nj], al[mi], bh[nj]);
#pragma unroll
                for (int mi = 0; mi < 4; ++mi)
#pragma unroll
                    for (int nj = 0; nj < 2; ++nj)
                        mma16(acc[mi][2 * pr + nj], ah[mi], bl[nj]);
#pragma unroll
                for (int mi = 0; mi < 4; ++mi)
#pragma unroll
                    for (int nj = 0; nj < 2; ++nj)
                        mma16(acc[mi][2 * pr + nj], ah[mi], bh[nj]);
            }
        }
    }

    // epilogue
#pragma unroll
    for (int mi = 0; mi < 4; ++mi) {
        int r0 = bm * 128 + wm + mi * 16 + grp;
#pragma unroll
        for (int ni = 0; ni < 4; ++ni) {
            int c0 = bn * 128 + wn + ni * 8 + 2 * t4;
            if (EPI == EPI_REGLU) {
                int j = c0 >> 1;
                float ba = bias[j], bg = bias[FH + j];
                float u0 = (acc[mi][ni][0] + ba) * fmaxf(acc[mi][ni][1] + bg, 0.0f);
                float u1 = (acc[mi][ni][2] + ba) * fmaxf(acc[mi][ni][3] + bg, 0.0f);
                uint16_t h, l;
                split1(u0, h, l);
                UH[(size_t)r0 * FH + j] = h;
                UL[(size_t)r0 * FH + j] = l;
                split1(u1, h, l);
                UH[(size_t)(r0 + 8) * FH + j] = h;
                UL[(size_t)(r0 + 8) * FH + j] = l;
            } else {
                float b0 = bias[c0], b1 = bias[c0 + 1];
                float2 o0 = make_float2(acc[mi][ni][0] + b0, acc[mi][ni][1] + b1);
                float2 o1 = make_float2(acc[mi][ni][2] + b0, acc[mi][ni][3] + b1);
                if (EPI == EPI_RES) {
                    float2 rv0 = *(const float2*)(Rsd + (size_t)r0 * N + c0);
                    float2 rv1 = *(const float2*)(Rsd + (size_t)(r0 + 8) * N + c0);
                    o0.x += rv0.x; o0.y += rv0.y;
                    o1.x += rv1.x; o1.y += rv1.y;
                }
                *(float2*)(C + (size_t)r0 * N + c0)       = o0;
                *(float2*)(C + (size_t)(r0 + 8) * N + c0) = o1;
            }
        }
    }
}

// ---------------- sparse attention (one block per (batch, head); CSR mask) ----------------
// Masked entries contribute exactly 0.0f in the reference (expf underflow), and
// x + 0.0f == x, so skipping them in ascending-j order is bit-identical.
__global__ void attn_kernel(const float* __restrict__ QKV,
                            const int* __restrict__ cnt, const int* __restrict__ rs,
                            const unsigned char* __restrict__ fi,
                            const unsigned char* __restrict__ fj,
                            const int* __restrict__ Tp,
                            uint16_t* __restrict__ OH, uint16_t* __restrict__ OL)
{
    int bh = blockIdx.x;
    int h  = bh % NH;
    int b  = bh / NH;
    int t  = threadIdx.x;   // 256

    __shared__ float qs[S][DH + 1];
    __shared__ float ks[S][DH + 1];
    __shared__ float vs[S][DH + 1];
    __shared__ float fp[S * S];
    __shared__ unsigned char sfi[S * S], sfj[S * S];
    __shared__ int scnt[S], srs[S];

    const int T = *Tp;

    const size_t rbase = (size_t)(b * S) * NQKV + h * DH;
    for (int i = t; i < S * DH; i += 256) {
        int s = i / DH, d = i % DH;
        size_t p = rbase + (size_t)s * NQKV + d;
        qs[s][d] = QKV[p];
        ks[s][d] = QKV[p + D];
        vs[s][d] = QKV[p + 2 * D];
    }
    for (int p = t; p < T; p += 256) { sfi[p] = fi[p]; sfj[p] = fj[p]; }
    if (t < S) { scnt[t] = cnt[t]; srs[t] = rs[t]; }
    __syncthreads();

    const float scale = 0.125f;  // 1/sqrt(64)
    for (int p = t; p < T; p += 256) {
        int i = sfi[p], j = sfj[p];
        float s = 0.0f;
#pragma unroll 16
        for (int d = 0; d < DH; ++d) s += qs[i][d] * ks[j][d];
        fp[p] = s * scale;
    }
    __syncthreads();

    if (t < S) {
        int r0 = srs[t], c = scnt[t];
        float mx = -1e30f;
        for (int e = 0; e < c; ++e) mx = fmaxf(mx, fp[r0 + e]);
        float sum = 0.0f;
        for (int e = 0; e < c; ++e) { float ee = __expf(fp[r0 + e] - mx); fp[r0 + e] = ee; sum += ee; }
        float inv = 1.0f / sum;
        for (int e = 0; e < c; ++e) fp[r0 + e] *= inv;
    }
    __syncthreads();

    const size_t obase = (size_t)(b * S) * D + h * DH;
    for (int p = t; p < S * (DH / 2); p += 256) {
        int i  = p / (DH / 2);
        int dd = (p % (DH / 2)) * 2;
        int r0 = srs[i], c = scnt[i];
        float o0 = 0.0f, o1 = 0.0f;
        for (int e = 0; e < c; ++e) {
            int j = sfj[r0 + e];
            float a = fp[r0 + e];
            o0 += a * vs[j][dd];
            o1 += a * vs[j][dd + 1];
        }
        uint32_t hi, lo;
        split2(o0, o1, hi, lo);
        size_t off = obase + (size_t)i * D + dd;
        *(uint32_t*)(OH + off) = hi;
        *(uint32_t*)(OL + off) = lo;
    }
}

// ---------------- head: LN(cls) -> relu -> dot Wh + bh ----------------
__global__ void head_kernel(const float* __restrict__ X,
                            const float* __restrict__ hw, const float* __restrict__ hb,
                            const float* __restrict__ Wh, const float* __restrict__ bh,
                            float* __restrict__ out)
{
    int b = blockIdx.x;
    int t = threadIdx.x;   // 128
    const float* xr = X + ((size_t)b * S + (S - 1)) * D;
    float4 v = *(const float4*)(xr + t * 4);
    float s  = v.x + v.y + v.z + v.w;
    float sq = v.x * v.x + v.y * v.y + v.z * v.z + v.w * v.w;
#pragma unroll
    for (int o = 16; o > 0; o >>= 1) {
        s  += __shfl_xor_sync(0xffffffffu, s, o);
        sq += __shfl_xor_sync(0xffffffffu, sq, o);
    }
    __shared__ float ss[4], sqs[4], ds[4];
    if ((t & 31) == 0) { ss[t >> 5] = s; sqs[t >> 5] = sq; }
    __syncthreads();
    s  = ss[0] + ss[1] + ss[2] + ss[3];
    sq = sqs[0] + sqs[1] + sqs[2] + sqs[3];
    float mean = s * (1.0f / D);
    float var  = sq * (1.0f / D) - mean * mean;
    float r = rsqrtf(var + 1e-5f);
    float4 wv = *(const float4*)(hw + t * 4);
    float4 bv = *(const float4*)(hb + t * 4);
    float4 wh = *(const float4*)(Wh + t * 4);   // DOUT == 1
    float dot = 0.0f;
    dot += fmaxf((v.x - mean) * r * wv.x + bv.x, 0.0f) * wh.x;
    dot += fmaxf((v.y - mean) * r * wv.y + bv.y, 0.0f) * wh.y;
    dot += fmaxf((v.z - mean) * r * wv.z + bv.z, 0.0f) * wh.z;
    dot += fmaxf((v.w - mean) * r * wv.w + bv.w, 0.0f) * wh.w;
#pragma unroll
    for (int o = 16; o > 0; o >>= 1) dot += __shfl_xor_sync(0xffffffffu, dot, o);
    if ((t & 31) == 0) ds[t >> 5] = dot;
    __syncthreads();
    if (t == 0) out[b] = ds[0] + ds[1] + ds[2] + ds[3] + bh[0];
}

// ---------------- launcher ----------------
extern "C" void kernel_launch(void* const* d_in, const int* in_sizes, int n_in,
                              void* d_out, int out_size)
{
    (void)in_sizes; (void)n_in; (void)out_size;
    const float* x_num    = (const float*)d_in[0];
    const int*   x_cat    = (const int*)d_in[1];
    const float* w_num    = (const float*)d_in[2];
    const float* b_num    = (const float*)d_in[3];
    const float* emb_cat  = (const float*)d_in[4];
    const float* b_cat    = (const float*)d_in[5];
    const float* cls      = (const float*)d_in[6];
    const float* ln1_w    = (const float*)d_in[7];
    const float* ln1_b    = (const float*)d_in[8];
    const float* Wq       = (const float*)d_in[9];
    const float* bq       = (const float*)d_in[10];
    const float* Wk       = (const float*)d_in[11];
    const float* bk       = (const float*)d_in[12];
    const float* Wv       = (const float*)d_in[13];
    const float* bv       = (const float*)d_in[14];
    const float* Wo       = (const float*)d_in[15];
    const float* bo       = (const float*)d_in[16];
    const float* ln2_w    = (const float*)d_in[17];
    const float* ln2_b    = (const float*)d_in[18];
    const float* Wf1      = (const float*)d_in[19];
    const float* bf1      = (const float*)d_in[20];
    const float* Wf2      = (const float*)d_in[21];
    const float* bf2      = (const float*)d_in[22];
    const unsigned char* mask_raw = (const unsigned char*)d_in[23];
    const int*   cat_offsets  = (const int*)d_in[24];
    const float* hln_w    = (const float*)d_in[25];
    const float* hln_b    = (const float*)d_in[26];
    const float* Wh       = (const float*)d_in[27];
    const float* bh       = (const float*)d_in[28];
    float* out = (float*)d_out;

    float *X, *QKV, *BQKV;
    uint16_t *HnH, *HnL, *OH, *OL, *UH, *UL, *WHp, *WLp;
    int *Cnt, *Rs, *Tarr;
    unsigned char *Fi, *Fj;
    cudaGetSymbolAddress((void**)&X,    g_X);
    cudaGetSymbolAddress((void**)&QKV,  g_QKV);
    cudaGetSymbolAddress((void**)&BQKV, g_bqkv);
    cudaGetSymbolAddress((void**)&HnH,  g_HnH);
    cudaGetSymbolAddress((void**)&HnL,  g_HnL);
    cudaGetSymbolAddress((void**)&OH,   g_OH);
    cudaGetSymbolAddress((void**)&OL,   g_OL);
    cudaGetSymbolAddress((void**)&UH,   g_UH);
    cudaGetSymbolAddress((void**)&UL,   g_UL);
    cudaGetSymbolAddress((void**)&WHp,  g_WH);
    cudaGetSymbolAddress((void**)&WLp,  g_WL);
    cudaGetSymbolAddress((void**)&Cnt,  g_cnt);
    cudaGetSymbolAddress((void**)&Rs,   g_rs);
    cudaGetSymbolAddress((void**)&Fi,   g_fi);
    cudaGetSymbolAddress((void**)&Fj,   g_fj);
    cudaGetSymbolAddress((void**)&Tarr, g_T);

    cudaFuncSetAttribute(gemm_kernel<EPI_PLAIN>,
                         cudaFuncAttributeMaxDynamicSharedMemorySize, (int)GEMM_SMEM);
    cudaFuncSetAttribute(gemm_kernel<EPI_RES>,
                         cudaFuncAttributeMaxDynamicSharedMemorySize, (int)GEMM_SMEM);
    cudaFuncSetAttribute(gemm_kernel<EPI_REGLU>,
                         cudaFuncAttributeMaxDynamicSharedMemorySize, (int)GEMM_SMEM);

    mask_convert_kernel<<<(L * S * S + 255) / 256, 256>>>(mask_raw);
    csr_build_kernel<<<1, 32>>>();
    biaspack_kernel<<<(L * NQKV + 255) / 256, 256>>>(bq, bk, bv);
    tokenize_kernel<<<(M * (D / 4) + 255) / 256, 256>>>(
        x_num, x_cat, w_num, b_num, emb_cat, b_cat, cls, cat_offsets);
    {
        size_t total = L * W_LSTR / 4;
        wsplit_mega_kernel<<<(unsigned)((total + 255) / 256), 256>>>(
            Wq, Wk, Wv, Wo, Wf1, Wf2);
    }

    const dim3 gQKV(M / 128, NQKV / 128);       // N = 1536
    const dim3 g512(M / 128, D / 128);          // N = 512
    const dim3 g2048(M / 128, (2 * FH) / 128);  // N = 2048 (interleaved a/g)

    for (int l = 0; l < L; ++l) {
        size_t lo = (size_t)l * W_LSTR;
        ln_split_kernel<<<M / 8, 256>>>(X, HnH, HnL, ln1_w + (size_t)l * D, ln1_b + (size_t)l * D);

        gemm_kernel<EPI_PLAIN><<<gQKV, 256, GEMM_SMEM>>>(HnH, HnL, WHp + lo, WLp + lo,
            BQKV + l * NQKV, nullptr, QKV, nullptr, nullptr, D, NQKV);

        attn_kernel<<<B * NH, 256>>>(QKV, Cnt + l * S, Rs + l * S,
            Fi + l * S * S, Fj + l * S * S, Tarr + l, OH, OL);

        gemm_kernel<EPI_RES><<<g512, 256, GEMM_SMEM>>>(OH, OL, WHp + lo + OFF_O, WLp + lo + OFF_O,
            bo + (size_t)l * D, X, X, nullptr, nullptr, D, D);

        ln_split_kernel<<<M / 8, 256>>>(X, HnH, HnL, ln2_w + (size_t)l * D, ln2_b + (size_t)l * D);

        gemm_kernel<EPI_REGLU><<<g2048, 256, GEMM_SMEM>>>(HnH, HnL, WHp + lo + OFF_F1, WLp + lo + OFF_F1,
            bf1 + (size_t)l * 2 * FH, nullptr, nullptr, UH, UL, D, 2 * FH);

        gemm_kernel<EPI_RES><<<g512, 256, GEMM_SMEM>>>(UH, UL, WHp + lo + OFF_F2, WLp + lo + OFF_F2,
            bf2 + (size_t)l * D, X, X, nullptr, nullptr, FH, D);
    }

    head_kernel<<<B, 128>>>(X, hln_w, hln_b, Wh, bh, out);
}